// round 11
// baseline (speedup 1.0000x reference)
#include <cuda_runtime.h>
#include <math.h>
#include <stdint.h>

// Problem constants
#define BB 4
#define TT 10
#define SS 6
#define AA 6
#define HID 512
#define LL 6
#define IMGD 128
#define NPIX 16384          // 128*128
#define NIMG_CAM 40         // B*T per camera
#define NIMG 80

// fp32 layer-1 patch layout (32x32 tile)
#define PROW 36
#define PCH  (34 * PROW)

// tf32 patch layout (32x16 tile): halo 18 rows x 34 cols
#define PCHH (18 * PROW)         // 648 floats per ci  (648 % 32 == 8)
#define PATCH_FLOATS (8 * PCHH)  // 5184 per buffer
#define WS_FLOATS    1152        // 9 taps * 16 ko * 8 ci (pair-interleaved)

// ---------------------------------------------------------------------------
// Scratch (static __device__ globals: allocation-free per harness rules)
// ---------------------------------------------------------------------------
__device__ float g_bufA[(size_t)NIMG * 128 * NPIX];   // max 128 ch
__device__ float g_bufB[(size_t)NIMG * 64 * NPIX];    // max 64 ch
__device__ float g_feat[NIMG_CAM * 64];               // (b*T+t, 64)
__device__ float g_h[2 * LL * BB * HID];              // double-buffered h
__device__ float g_c[LL * BB * HID];

// ---------------------------------------------------------------------------
// f32x2 packed-FMA helpers (layer-1 fp32 conv)
// ---------------------------------------------------------------------------
__device__ __forceinline__ unsigned long long pack2(float a, float b) {
    unsigned long long r;
    asm("mov.b64 %0, {%1, %2};" : "=l"(r) : "r"(__float_as_uint(a)), "r"(__float_as_uint(b)));
    return r;
}
__device__ __forceinline__ void unpack2(unsigned long long v, float& a, float& b) {
    unsigned int lo, hi;
    asm("mov.b64 {%0, %1}, %2;" : "=r"(lo), "=r"(hi) : "l"(v));
    a = __uint_as_float(lo); b = __uint_as_float(hi);
}
__device__ __forceinline__ void fma2(unsigned long long& d, unsigned long long a, unsigned long long b) {
    asm("fma.rn.f32x2 %0, %1, %2, %0;" : "+l"(d) : "l"(a), "l"(b));
}

// ---------------------------------------------------------------------------
// cp.async helpers
// ---------------------------------------------------------------------------
__device__ __forceinline__ void cp_async4(uint32_t smem_addr, const void* gptr, int sz) {
    asm volatile("cp.async.ca.shared.global [%0], [%1], 4, %2;\n"
                 :: "r"(smem_addr), "l"(gptr), "r"(sz));
}
__device__ __forceinline__ void cp_commit() { asm volatile("cp.async.commit_group;"); }
template<int N>
__device__ __forceinline__ void cp_wait() { asm volatile("cp.async.wait_group %0;" :: "n"(N)); }

// ---------------------------------------------------------------------------
// tf32 mma m16n8k8 (row.col), fp32 accumulate
// ---------------------------------------------------------------------------
__device__ __forceinline__ void mma_tf32(float* d, const float* a, const float* b) {
    asm volatile(
        "mma.sync.aligned.m16n8k8.row.col.f32.tf32.tf32.f32 "
        "{%0,%1,%2,%3}, {%4,%5,%6,%7}, {%8,%9}, {%0,%1,%2,%3};"
        : "+f"(d[0]), "+f"(d[1]), "+f"(d[2]), "+f"(d[3])
        : "r"(__float_as_uint(a[0])), "r"(__float_as_uint(a[1])),
          "r"(__float_as_uint(a[2])), "r"(__float_as_uint(a[3])),
          "r"(__float_as_uint(b[0])), "r"(__float_as_uint(b[1])));
}

// ---------------------------------------------------------------------------
// tf32 staging (32x16 tile):
//  weights -> [k][ko][cq=ci%4][hi=ci/4]   (pair-interleaved)
//  patch   -> [ci][py(0..17)][px] contiguous rows, incremental addressing
// ---------------------------------------------------------------------------
template<int CIN>
__device__ __forceinline__ void stage_chunk_tf32(
    const float* __restrict__ ib, const float* __restrict__ wt,
    int g, int bx, int by, int c0,
    uint32_t ws_s, uint32_t patch_s, int tid)
{
    constexpr int CB = 8;
    for (int idx = tid; idx < CB * 144; idx += 256) {
        int ci = idx / 144;
        int rem = idx - ci * 144;
        int k = rem >> 4;
        int ko = rem & 15;
        const float* src = wt + ((size_t)(g * 16 + ko) * CIN + (c0 + ci)) * 9 + k;
        uint32_t pos = (uint32_t)((((k * 16 + ko) * 4 + (ci & 3)) << 1) + (ci >> 2));
        cp_async4(ws_s + pos * 4, src, 4);
    }
    const int lane32 = tid & 31;
    int py = tid >> 5;              // 0..7, advance by 8
    int ci = 0;
    const int gx = bx * 32 - 1 + lane32;
    const bool okx = ((unsigned)gx < 128u);
    const bool okx2 = ((unsigned)(gx + 32) < 128u) && (lane32 < 2);
#pragma unroll 4
    for (int r = tid >> 5; r < CB * 18; r += 8) {
        int gy = by * 16 + py - 1;
        bool oky = ((unsigned)gy < 128u);
        const float* srow = ib + (size_t)(c0 + ci) * NPIX + gy * IMGD;
        uint32_t drow = patch_s + (uint32_t)((ci * PCHH + py * PROW) * 4);
        bool ok = oky && okx;
        cp_async4(drow + lane32 * 4, srow + (ok ? gx : 0), ok ? 4 : 0);
        if (lane32 < 2) {
            bool ok2 = oky && okx2;
            cp_async4(drow + (32 + lane32) * 4, srow + (ok2 ? (gx + 32) : 0), ok2 ? 4 : 0);
        }
        py += 8;
        if (py >= 18) { py -= 18; ci++; }
    }
}

// ---------------------------------------------------------------------------
// tf32 tensor-core 3x3 SAME conv + bias + relu.  Dual-camera.
// Block: 32x16 pixel tile x 16 ko, 256 threads (8 warps), 3 CTAs/SM.
// Warp: 4-row band x 16 x-pixels x 16 ko; A reused across ky (sb+ky=row).
// ---------------------------------------------------------------------------
template<int CIN>
__global__ void __launch_bounds__(256, 3) conv3x3_tf32_kernel(
    const float* __restrict__ in,
    const float* __restrict__ wt0, const float* __restrict__ wt1,
    const float* __restrict__ bias0, const float* __restrict__ bias1,
    float* __restrict__ out, int groups)
{
    constexpr int CB = 8;
    constexpr int NCHUNK = CIN / CB;

    extern __shared__ __align__(16) float smem[];
    float* ws_base = smem;                         // 2 * WS_FLOATS
    float* patch_base = smem + 2 * WS_FLOATS;      // 2 * PATCH_FLOATS
    uint32_t sbase = (uint32_t)__cvta_generic_to_shared(smem);
    const uint32_t ws_off[2] = { sbase, sbase + (uint32_t)(WS_FLOATS * 4) };
    const uint32_t pa_off[2] = { sbase + (uint32_t)(2 * WS_FLOATS * 4),
                                 sbase + (uint32_t)((2 * WS_FLOATS + PATCH_FLOATS) * 4) };

    const int img = blockIdx.z / groups;
    const int grp = blockIdx.z % groups;
    const float* wt   = (img < NIMG_CAM) ? wt0 : wt1;
    const float* bias = (img < NIMG_CAM) ? bias0 : bias1;

    const int tid = threadIdx.x;
    const int w    = tid >> 5;
    const int lane = tid & 31;
    const int lg   = lane >> 2;         // 0..7
    const int tig  = lane & 3;          // 0..3
    const int wy   = w >> 1;            // band 0..3 (4 rows each)
    const int x0   = (w & 1) * 16;
    const int bx = (int)blockIdx.x;
    const int by = (int)blockIdx.y;

    const float* ib = in + (size_t)img * CIN * NPIX;

    float d[4][2][4];
#pragma unroll
    for (int sb = 0; sb < 4; sb++)
#pragma unroll
        for (int h = 0; h < 2; h++)
#pragma unroll
            for (int i = 0; i < 4; i++) d[sb][h][i] = 0.f;

    stage_chunk_tf32<CIN>(ib, wt, grp, bx, by, 0, ws_off[0], pa_off[0], tid);
    cp_commit();
    if (NCHUNK > 1) {
        stage_chunk_tf32<CIN>(ib, wt, grp, bx, by, CB, ws_off[1], pa_off[1], tid);
        cp_commit();
    }

    for (int ch = 0; ch < NCHUNK; ch++) {
        const int cur = ch & 1;
        if (ch + 1 < NCHUNK) cp_wait<1>(); else cp_wait<0>();
        __syncthreads();

        const float2* WB = (const float2*)(ws_base + cur * WS_FLOATS) + tig;
        const float* PA = patch_base + cur * PATCH_FLOATS
                        + tig * PCHH + (wy * 4) * PROW + x0 + lg;

#pragma unroll
        for (int kx = 0; kx < 3; kx++) {
            float a[6][4];
#pragma unroll
            for (int r = 0; r < 6; r++) {
                const float* ap = PA + r * PROW + kx;
                a[r][0] = ap[0];
                a[r][1] = ap[8];
                a[r][2] = ap[4 * PCHH];
                a[r][3] = ap[4 * PCHH + 8];
            }
#pragma unroll
            for (int ky = 0; ky < 3; ky++) {
                const int k = ky * 3 + kx;
                float2 B0 = WB[(k * 16 + lg) * 4];       // ko = lg
                float2 B1 = WB[(k * 16 + 8 + lg) * 4];   // ko = lg + 8
                float b0[2] = { B0.x, B0.y };
                float b1[2] = { B1.x, B1.y };
#pragma unroll
                for (int sb = 0; sb < 4; sb++) {
                    mma_tf32(d[sb][0], a[sb + ky], b0);
                    mma_tf32(d[sb][1], a[sb + ky], b1);
                }
            }
        }

        if (ch + 2 < NCHUNK) {
            __syncthreads();
            stage_chunk_tf32<CIN>(ib, wt, grp, bx, by, (ch + 2) * CB,
                                  ws_off[cur], pa_off[cur], tid);
            cp_commit();
        }
    }

    // epilogue: bias + relu + scalar stores
    float* ob = out + ((size_t)img * (groups * 16) + grp * 16) * NPIX;
    const int gxa = bx * 32 + x0 + lg;
    const int gxb = gxa + 8;
#pragma unroll
    for (int h = 0; h < 2; h++) {
        const int ko0 = h * 8 + 2 * tig;
        const float bi0 = bias[grp * 16 + ko0];
        const float bi1 = bias[grp * 16 + ko0 + 1];
        float* o0 = ob + (size_t)ko0 * NPIX;
        float* o1 = ob + (size_t)(ko0 + 1) * NPIX;
#pragma unroll
        for (int sb = 0; sb < 4; sb++) {
            const int gy = by * 16 + wy * 4 + sb;
            o0[gy * IMGD + gxa] = fmaxf(d[sb][h][0] + bi0, 0.f);
            o1[gy * IMGD + gxa] = fmaxf(d[sb][h][1] + bi1, 0.f);
            o0[gy * IMGD + gxb] = fmaxf(d[sb][h][2] + bi0, 0.f);
            o1[gy * IMGD + gxb] = fmaxf(d[sb][h][3] + bi1, 0.f);
        }
    }
}

// ---------------------------------------------------------------------------
// Layer-1 fp32 conv staging (scalar layout, CIN=3, 32x32 tile)
// ---------------------------------------------------------------------------
__device__ __forceinline__ void stage_l1(
    const float* __restrict__ ib, const float* __restrict__ wt,
    int g, int bx, int by, uint32_t ws_s, uint32_t patch_s, int tid)
{
    for (int idx = tid; idx < 3 * 144; idx += 256) {
        int ci = idx / 144;
        int rem = idx - ci * 144;
        int k = rem >> 4;
        int ko = rem & 15;
        const float* src = wt + ((size_t)(g * 16 + ko) * 3 + ci) * 9 + k;
        cp_async4(ws_s + idx * 4, src, 4);
    }
    const int lane32 = tid & 31;
    int py = tid >> 5;
    int ci = 0;
    const int gx = bx * 32 - 1 + lane32;
    const bool okx = ((unsigned)gx < 128u);
    for (int r = tid >> 5; r < 3 * 34; r += 8) {
        int gy = by * 32 + py - 1;
        bool oky = ((unsigned)gy < 128u);
        const float* srow = ib + (size_t)ci * NPIX + gy * IMGD;
        uint32_t drow = patch_s + (uint32_t)((ci * PCH + py * PROW) * 4);
        bool ok = oky && okx;
        cp_async4(drow + lane32 * 4, srow + (ok ? gx : 0), ok ? 4 : 0);
        if (lane32 < 2) {
            bool ok2 = oky && ((unsigned)(gx + 32) < 128u);
            cp_async4(drow + (32 + lane32) * 4, srow + (ok2 ? (gx + 32) : 0), ok2 ? 4 : 0);
        }
        py += 8;
        if (py >= 34) { py -= 34; ci++; }
    }
}

// ---------------------------------------------------------------------------
// Layer-1 fp32 conv (CIN=3), dual-camera, 32x32 tile.
// ---------------------------------------------------------------------------
__global__ void __launch_bounds__(256, 2) conv3x3_l1_kernel(
    const float* __restrict__ in0, const float* __restrict__ in1,
    const float* __restrict__ wt0, const float* __restrict__ wt1,
    const float* __restrict__ bias0, const float* __restrict__ bias1,
    float* __restrict__ out, int groups)
{
    extern __shared__ __align__(16) float smem[];
    float* ws_base = smem;
    float* patch_base = smem + 3 * 144;
    uint32_t sbase = (uint32_t)__cvta_generic_to_shared(smem);
    const uint32_t ws_s = sbase;
    const uint32_t pa_s = sbase + (uint32_t)(3 * 144 * 4);

    const int img = blockIdx.z / groups;
    const int g   = blockIdx.z % groups;
    const float* wt   = (img < NIMG_CAM) ? wt0 : wt1;
    const float* bias = (img < NIMG_CAM) ? bias0 : bias1;
    const int limg = (img < NIMG_CAM) ? img : (img - NIMG_CAM);
    const float* ib = ((img < NIMG_CAM) ? in0 : in1) + (size_t)limg * 3 * NPIX;

    const int tid = threadIdx.x;
    const int tx  = tid & 15;
    const int ty  = tid >> 4;
    const int bx  = (int)blockIdx.x;
    const int by  = (int)blockIdx.y;
    const int ox0 = bx * 32 + 2 * tx;
    const int oy0 = by * 32 + 2 * ty;

    unsigned long long acc[4][8];
    const unsigned long long z2 = pack2(0.f, 0.f);
#pragma unroll
    for (int p_ = 0; p_ < 4; p_++)
#pragma unroll
        for (int i = 0; i < 8; i++) acc[p_][i] = z2;

    stage_l1(ib, wt, g, bx, by, ws_s, pa_s, tid);
    cp_commit();
    cp_wait<0>();
    __syncthreads();

#pragma unroll
    for (int ci = 0; ci < 3; ci++) {
        float p[4][4];
        const float* pb = patch_base + ci * PCH + (2 * ty) * PROW + 2 * tx;
#pragma unroll
        for (int r = 0; r < 4; r++) {
            float2 a = *(const float2*)(pb + r * PROW);
            float2 b = *(const float2*)(pb + r * PROW + 2);
            p[r][0] = a.x; p[r][1] = a.y; p[r][2] = b.x; p[r][3] = b.y;
        }
        const float* wk = ws_base + ci * 144;
#pragma unroll
        for (int k = 0; k < 9; k++) {
            const int ky = k / 3, kx = k - 3 * (k / 3);
            const ulonglong2* wp = (const ulonglong2*)(wk + k * 16);
            ulonglong2 w01 = wp[0];
            ulonglong2 w23 = wp[1];
            ulonglong2 w45 = wp[2];
            ulonglong2 w67 = wp[3];
#pragma unroll
            for (int p_ = 0; p_ < 4; p_++) {
                float v = p[(p_ >> 1) + ky][(p_ & 1) + kx];
                unsigned long long bb = pack2(v, v);
                fma2(acc[p_][0], w01.x, bb);
                fma2(acc[p_][1], w01.y, bb);
                fma2(acc[p_][2], w23.x, bb);
                fma2(acc[p_][3], w23.y, bb);
                fma2(acc[p_][4], w45.x, bb);
                fma2(acc[p_][5], w45.y, bb);
                fma2(acc[p_][6], w67.x, bb);
                fma2(acc[p_][7], w67.y, bb);
            }
        }
    }

    float* ob = out + ((size_t)img * (groups * 16) + g * 16) * NPIX;
#pragma unroll
    for (int i = 0; i < 8; i++) {
        float b0 = bias[g * 16 + 2 * i];
        float b1 = bias[g * 16 + 2 * i + 1];
#pragma unroll
        for (int pr = 0; pr < 2; pr++) {
            float a0l, a1l, a0r, a1r;
            unpack2(acc[pr * 2 + 0][i], a0l, a1l);
            unpack2(acc[pr * 2 + 1][i], a0r, a1r);
            int row = oy0 + pr;
            float2 v0 = make_float2(fmaxf(a0l + b0, 0.f), fmaxf(a0r + b0, 0.f));
            float2 v1 = make_float2(fmaxf(a1l + b1, 0.f), fmaxf(a1r + b1, 0.f));
            *(float2*)(ob + (size_t)(2 * i) * NPIX + row * IMGD + ox0) = v0;
            *(float2*)(ob + (size_t)(2 * i + 1) * NPIX + row * IMGD + ox0) = v1;
        }
    }
}

// ---------------------------------------------------------------------------
// Spatial softmax (conv16 laid out img-major: ((img*16)+ch)*NPIX)
// ---------------------------------------------------------------------------
__global__ void __launch_bounds__(256) sspmax_kernel(
    const float* __restrict__ conv16, float* __restrict__ feat)
{
    __shared__ float red[8];
    __shared__ float r2[3][8];

    const int id = blockIdx.x;
    const int img = id >> 4;
    const int ch = id & 15;
    const int cam = (img >= NIMG_CAM) ? 1 : 0;
    const int bt = img - cam * NIMG_CAM;
    const float* p = conv16 + ((size_t)img * 16 + ch) * NPIX;
    const int tid = threadIdx.x;

    float m = -1e30f;
    for (int k = tid; k < NPIX; k += 256) m = fmaxf(m, p[k]);
    for (int o = 16; o; o >>= 1) m = fmaxf(m, __shfl_xor_sync(~0u, m, o));
    if ((tid & 31) == 0) red[tid >> 5] = m;
    __syncthreads();
    if (tid < 8) {
        float v = red[tid];
        for (int o = 4; o; o >>= 1) v = fmaxf(v, __shfl_xor_sync(0xffu, v, o));
        if (tid == 0) red[0] = v;
    }
    __syncthreads();
    m = red[0];

    float se = 0.f, sx = 0.f, sy = 0.f;
    const float step = 2.f / 127.f;
    for (int k = tid; k < NPIX; k += 256) {
        float e = expf(p[k] - m);
        float px = -1.f + (float)(k & 127) * step;
        float py = -1.f + (float)(k >> 7) * step;
        se += e; sx += e * px; sy += e * py;
    }
    for (int o = 16; o; o >>= 1) {
        se += __shfl_xor_sync(~0u, se, o);
        sx += __shfl_xor_sync(~0u, sx, o);
        sy += __shfl_xor_sync(~0u, sy, o);
    }
    if ((tid & 31) == 0) { r2[0][tid >> 5] = se; r2[1][tid >> 5] = sx; r2[2][tid >> 5] = sy; }
    __syncthreads();
    if (tid == 0) {
        float a = 0.f, bx = 0.f, by = 0.f;
        for (int w = 0; w < 8; w++) { a += r2[0][w]; bx += r2[1][w]; by += r2[2][w]; }
        feat[bt * 64 + cam * 32 + 2 * ch + 0] = bx / a;
        feat[bt * 64 + cam * 32 + 2 * ch + 1] = by / a;
    }
}

// ---------------------------------------------------------------------------
// LSTM cell
// ---------------------------------------------------------------------------
__device__ __forceinline__ float sigm(float x) { return 1.f / (1.f + expf(-x)); }

__global__ void __launch_bounds__(256) lstm_cell_kernel(
    const float* __restrict__ xa, int alen, int xa_stride,
    const float* __restrict__ im,
    const float* __restrict__ wih, const float* __restrict__ whh,
    const float* __restrict__ bih, const float* __restrict__ bhh,
    const float* __restrict__ hprev, float* __restrict__ hnew,
    float* __restrict__ c)
{
    __shared__ float xs[BB][576];
    __shared__ float hs[BB][HID];
    __shared__ float part[8][BB];
    __shared__ float gs[16];

    const int inlen = alen + 64;
    const int tid = threadIdx.x;

    for (int idx = tid; idx < BB * inlen; idx += 256) {
        int b = idx / inlen;
        int k = idx - b * inlen;
        xs[b][k] = (k < alen) ? xa[b * xa_stride + k] : im[b * (TT * 64) + (k - alen)];
    }
    for (int idx = tid; idx < BB * HID; idx += 256)
        hs[idx >> 9][idx & 511] = hprev[idx];
    __syncthreads();

    const int j = blockIdx.x;
    const int warp = tid >> 5;
    const int lane = tid & 31;
    const int g = warp >> 1;
    const int half = warp & 1;
    const int row = g * HID + j;
    const int k0 = half * 32 + lane;

    float s0 = 0.f, s1 = 0.f, s2 = 0.f, s3 = 0.f;
    const float* wr = wih + (size_t)row * inlen;
#pragma unroll 4
    for (int k = k0; k < inlen; k += 64) {
        float w = wr[k];
        s0 += w * xs[0][k]; s1 += w * xs[1][k];
        s2 += w * xs[2][k]; s3 += w * xs[3][k];
    }
    const float* hr = whh + (size_t)row * HID;
#pragma unroll 4
    for (int k = k0; k < HID; k += 64) {
        float w = hr[k];
        s0 += w * hs[0][k]; s1 += w * hs[1][k];
        s2 += w * hs[2][k]; s3 += w * hs[3][k];
    }
    for (int o = 16; o; o >>= 1) {
        s0 += __shfl_xor_sync(~0u, s0, o);
        s1 += __shfl_xor_sync(~0u, s1, o);
        s2 += __shfl_xor_sync(~0u, s2, o);
        s3 += __shfl_xor_sync(~0u, s3, o);
    }
    if (lane == 0) {
        part[warp][0] = s0; part[warp][1] = s1;
        part[warp][2] = s2; part[warp][3] = s3;
    }
    __syncthreads();

    if (tid < 16) {
        int gg = tid >> 2, b = tid & 3;
        float s = part[gg * 2][b] + part[gg * 2 + 1][b]
                + bih[gg * HID + j] + bhh[gg * HID + j];
        gs[b * 4 + gg] = s;
    }
    __syncthreads();

    if (tid < BB) {
        const int b = tid;
        float gi = gs[b * 4 + 0];
        float gf = gs[b * 4 + 1];
        float gg = gs[b * 4 + 2];
        float go = gs[b * 4 + 3];
        float cold = c[b * HID + j];
        float cn = sigm(gf) * cold + sigm(gi) * tanhf(gg);
        float hn = sigm(go) * tanhf(cn);
        c[b * HID + j] = cn;
        hnew[b * HID + j] = hn;
    }
}

// ---------------------------------------------------------------------------
// Output head
// ---------------------------------------------------------------------------
__global__ void __launch_bounds__(128) out_kernel(
    const float* __restrict__ h, const float* __restrict__ im,
    const float* __restrict__ ow, const float* __restrict__ ob,
    float* __restrict__ outp)
{
    const int b = blockIdx.x / AA;
    const int a = blockIdx.x % AA;
    const float* w = ow + a * (HID + 64);
    float s = 0.f;
    for (int k = threadIdx.x; k < HID; k += 128) s += w[k] * h[b * HID + k];
    for (int k = threadIdx.x; k < 64; k += 128) s += w[HID + k] * im[b * (TT * 64) + k];
    __shared__ float red[4];
    for (int o = 16; o; o >>= 1) s += __shfl_xor_sync(~0u, s, o);
    if ((threadIdx.x & 31) == 0) red[threadIdx.x >> 5] = s;
    __syncthreads();
    if (threadIdx.x == 0)
        outp[b * (TT * AA) + a] = red[0] + red[1] + red[2] + red[3] + ob[a];
}

__global__ void zero_state_kernel()
{
    int i = blockIdx.x * blockDim.x + threadIdx.x;
    if (i < 2 * LL * BB * HID) g_h[i] = 0.f;
    if (i < LL * BB * HID) g_c[i] = 0.f;
}

// ---------------------------------------------------------------------------
// Launch
// ---------------------------------------------------------------------------
extern "C" void kernel_launch(void* const* d_in, const int* in_sizes, int n_in,
                              void* d_out, int out_size)
{
    (void)in_sizes; (void)n_in; (void)out_size;

    const float* img_m  = (const float*)d_in[0];
    const float* img_s  = (const float*)d_in[1];
    const float* states = (const float*)d_in[2];
    const float* wih0 = (const float*)d_in[19];
    const float* whh0 = (const float*)d_in[20];
    const float* bih0 = (const float*)d_in[21];
    const float* bhh0 = (const float*)d_in[22];
    const float* wih_r = (const float*)d_in[23];
    const float* whh_r = (const float*)d_in[24];
    const float* bih_r = (const float*)d_in[25];
    const float* bhh_r = (const float*)d_in[26];
    const float* out_w = (const float*)d_in[27];
    const float* out_b = (const float*)d_in[28];
    float* outp = (float*)d_out;

    float* bufA; cudaGetSymbolAddress((void**)&bufA, g_bufA);
    float* bufB; cudaGetSymbolAddress((void**)&bufB, g_bufB);
    float* feat; cudaGetSymbolAddress((void**)&feat, g_feat);
    float* hbuf; cudaGetSymbolAddress((void**)&hbuf, g_h);
    float* cbuf; cudaGetSymbolAddress((void**)&cbuf, g_c);

    const int smemL1 = (3 * 144 + 3 * PCH) * 4;                 // 16416
    const int smemTF = 2 * (WS_FLOATS + PATCH_FLOATS) * 4;      // 50688
    cudaFuncSetAttribute(conv3x3_l1_kernel,        cudaFuncAttributeMaxDynamicSharedMemorySize, smemL1);
    cudaFuncSetAttribute(conv3x3_tf32_kernel<32>,  cudaFuncAttributeMaxDynamicSharedMemorySize, smemTF);
    cudaFuncSetAttribute(conv3x3_tf32_kernel<64>,  cudaFuncAttributeMaxDynamicSharedMemorySize, smemTF);
    cudaFuncSetAttribute(conv3x3_tf32_kernel<128>, cudaFuncAttributeMaxDynamicSharedMemorySize, smemTF);

    zero_state_kernel<<<96, 256>>>();

    const float* mw[4] = { (const float*)d_in[3], (const float*)d_in[5],
                           (const float*)d_in[7], (const float*)d_in[9] };
    const float* mb[4] = { (const float*)d_in[4], (const float*)d_in[6],
                           (const float*)d_in[8], (const float*)d_in[10] };
    const float* sw[4] = { (const float*)d_in[11], (const float*)d_in[13],
                           (const float*)d_in[15], (const float*)d_in[17] };
    const float* sb[4] = { (const float*)d_in[12], (const float*)d_in[14],
                           (const float*)d_in[16], (const float*)d_in[18] };

    // Buffer plan: L1 -> a32 (bufA), L2 -> b64 (bufB), L3 -> a128 (bufA), L4 -> b16 (bufB)
    float* a32  = bufA;
    float* b64  = bufB;
    float* a128 = bufA;
    float* b16  = bufB;

    conv3x3_l1_kernel<<<dim3(4, 4, NIMG * 2), 256, smemL1>>>(
        img_m, img_s, mw[0], sw[0], mb[0], sb[0], a32, 2);
    conv3x3_tf32_kernel<32><<<dim3(4, 8, NIMG * 4), 256, smemTF>>>(
        a32, mw[1], sw[1], mb[1], sb[1], b64, 4);
    conv3x3_tf32_kernel<64><<<dim3(4, 8, NIMG * 8), 256, smemTF>>>(
        b64, mw[2], sw[2], mb[2], sb[2], a128, 8);
    conv3x3_tf32_kernel<128><<<dim3(4, 8, NIMG * 1), 256, smemTF>>>(
        a128, mw[3], sw[3], mb[3], sb[3], b16, 1);

    sspmax_kernel<<<NIMG * 16, 256>>>(b16, feat);

    const int half = LL * BB * HID;
    for (int t = 0; t < TT; t++) {
        float* hprev = hbuf + (t & 1) * half;
        float* hcur  = hbuf + (1 - (t & 1)) * half;
        const float* im_t = feat + t * 64;

        lstm_cell_kernel<<<HID, 256>>>(
            states + t * SS, SS, TT * SS, im_t,
            wih0, whh0, bih0, bhh0,
            hprev + 0, hcur + 0, cbuf + 0);

        for (int l = 1; l < LL; l++) {
            lstm_cell_kernel<<<HID, 256>>>(
                hcur + (size_t)(l - 1) * BB * HID, HID, HID, im_t,
                wih_r + (size_t)(l - 1) * 4 * HID * (HID + 64),
                whh_r + (size_t)(l - 1) * 4 * HID * HID,
                bih_r + (size_t)(l - 1) * 4 * HID,
                bhh_r + (size_t)(l - 1) * 4 * HID,
                hprev + (size_t)l * BB * HID,
                hcur + (size_t)l * BB * HID,
                cbuf + (size_t)l * BB * HID);
        }

        out_kernel<<<BB * AA, 128>>>(
            hcur + (size_t)(LL - 1) * BB * HID, im_t, out_w, out_b, outp + t * AA);
    }
}

// round 12
// speedup vs baseline: 1.9766x; 1.9766x over previous
#include <cuda_runtime.h>
#include <cuda_bf16.h>
#include <math.h>
#include <stdint.h>

// Problem constants
#define BB 4
#define TT 10
#define SS 6
#define AA 6
#define HID 512
#define LL 6
#define IMGD 128
#define NPIX 16384          // 128*128
#define NIMG_CAM 40         // B*T per camera
#define NIMG 80

// patch layouts
#define PROW 36             // padded row stride (elements)
#define PCH  (34 * PROW)    // per-channel(-pair) patch elements (1224)
#define PATCH_U32 (8 * PCH)      // 9792 u32 per buffer (8 cq pairs)
#define WS_U32    1152           // 9 taps * 16 ko * 8 cq (bf16x2 each)

// per-camera bf16 weight block offsets (u32 pairs)
#define WOFF_L2 0
#define WSZ_L2  9216             // 4 grp * 2 chunk * 1152
#define WOFF_L3 9216
#define WSZ_L3  36864            // 8 grp * 4 chunk * 1152
#define WOFF_L4 46080
#define WSZ_L4  9216             // 1 grp * 8 chunk * 1152
#define WCAM    55296

// ---------------------------------------------------------------------------
// Scratch (static __device__ globals)
// ---------------------------------------------------------------------------
__device__ __align__(16) unsigned g_actA[(size_t)NIMG * 64 * NPIX];  // bf16x2 pairs (max 64/img)
__device__ __align__(16) unsigned g_actB[(size_t)NIMG * 32 * NPIX];  // bf16x2 pairs (max 32/img)
__device__ __align__(16) float    g_conv16[(size_t)NIMG * 16 * NPIX];
__device__ __align__(16) unsigned g_wb[2 * WCAM];                    // bf16x2 weights, both cams
__device__ float g_feat[NIMG_CAM * 64];
__device__ float g_h[2 * LL * BB * HID];
__device__ float g_c[LL * BB * HID];

// ---------------------------------------------------------------------------
// helpers
// ---------------------------------------------------------------------------
__device__ __forceinline__ unsigned long long pack2(float a, float b) {
    unsigned long long r;
    asm("mov.b64 %0, {%1, %2};" : "=l"(r) : "r"(__float_as_uint(a)), "r"(__float_as_uint(b)));
    return r;
}
__device__ __forceinline__ void unpack2(unsigned long long v, float& a, float& b) {
    unsigned int lo, hi;
    asm("mov.b64 {%0, %1}, %2;" : "=r"(lo), "=r"(hi) : "l"(v));
    a = __uint_as_float(lo); b = __uint_as_float(hi);
}
__device__ __forceinline__ void fma2(unsigned long long& d, unsigned long long a, unsigned long long b) {
    asm("fma.rn.f32x2 %0, %1, %2, %0;" : "+l"(d) : "l"(a), "l"(b));
}
__device__ __forceinline__ unsigned pack_bf2(float lo, float hi) {
    __nv_bfloat162 v = __floats2bfloat162_rn(lo, hi);   // x(low)=lo, y(high)=hi
    return *(unsigned*)&v;
}

__device__ __forceinline__ void cp_async4(uint32_t smem_addr, const void* gptr, int sz) {
    asm volatile("cp.async.ca.shared.global [%0], [%1], 4, %2;\n"
                 :: "r"(smem_addr), "l"(gptr), "r"(sz));
}
__device__ __forceinline__ void cp_async16(uint32_t smem_addr, const void* gptr) {
    asm volatile("cp.async.cg.shared.global [%0], [%1], 16;\n"
                 :: "r"(smem_addr), "l"(gptr));
}
__device__ __forceinline__ void cp_commit() { asm volatile("cp.async.commit_group;"); }
template<int N>
__device__ __forceinline__ void cp_wait() { asm volatile("cp.async.wait_group %0;" :: "n"(N)); }

// bf16 mma m16n8k16 (row.col), fp32 accumulate
__device__ __forceinline__ void mma_bf16(float* d, const unsigned* a, unsigned b0, unsigned b1) {
    asm volatile(
        "mma.sync.aligned.m16n8k16.row.col.f32.bf16.bf16.f32 "
        "{%0,%1,%2,%3}, {%4,%5,%6,%7}, {%8,%9}, {%0,%1,%2,%3};"
        : "+f"(d[0]), "+f"(d[1]), "+f"(d[2]), "+f"(d[3])
        : "r"(a[0]), "r"(a[1]), "r"(a[2]), "r"(a[3]), "r"(b0), "r"(b1));
}

// ---------------------------------------------------------------------------
// Weight prep: fp32 [KO][CIN][3][3] -> bf16x2 blocks
// dst[((grp*nch + chunk)*9 + k)*16*8 + ko_l*8 + cq] = (ci0, ci0+1)
// ---------------------------------------------------------------------------
__global__ void prep_w_kernel(const float* __restrict__ wt, unsigned* __restrict__ dst,
                              int CIN, int npairs)
{
    int idx = blockIdx.x * 256 + threadIdx.x;
    if (idx >= npairs) return;
    int p = idx;
    int cq = p & 7;  p >>= 3;
    int ko_l = p & 15; p >>= 4;
    int k = p % 9;   p /= 9;
    int nch = CIN >> 4;
    int chunk = p % nch;
    int grp = p / nch;
    int ci0 = chunk * 16 + cq * 2;
    int ko = grp * 16 + ko_l;
    float lo = wt[((size_t)ko * CIN + ci0) * 9 + k];
    float hi = wt[((size_t)ko * CIN + ci0 + 1) * 9 + k];
    dst[idx] = pack_bf2(lo, hi);
}

// ---------------------------------------------------------------------------
// bf16 conv staging: weights contiguous; patch rows (u32 bf16x2 elements)
// ---------------------------------------------------------------------------
__device__ __forceinline__ void stage_chunk_bf16(
    const unsigned* __restrict__ inb, int inp_pairs, const unsigned* __restrict__ wb,
    int nchunk, int grp, int bx, int by, int ch,
    uint32_t ws_s, uint32_t patch_s, int tid)
{
    // weights: contiguous 1152 u32 = 288 x 16B
    const unsigned* wsrc = wb + (size_t)(grp * nchunk + ch) * WS_U32;
    for (int idx = tid; idx < 288; idx += 256)
        cp_async16(ws_s + idx * 16, wsrc + idx * 4);

    // patch: 8 cq-pairs x 34 halo rows x 34 cols (u32 each)
    const int lane32 = tid & 31;
    int py = tid >> 5;
    int cq = 0;
    const int gx = bx * 32 - 1 + lane32;
    const bool okx = ((unsigned)gx < 128u);
    const bool okx2 = ((unsigned)(gx + 32) < 128u) && (lane32 < 2);
    const int c0q = ch * 8;
#pragma unroll 4
    for (int r = tid >> 5; r < 8 * 34; r += 8) {
        int gy = by * 32 + py - 1;
        bool oky = ((unsigned)gy < 128u);
        const unsigned* srow = inb + (size_t)(c0q + cq) * NPIX + gy * IMGD;
        uint32_t drow = patch_s + (uint32_t)((cq * PCH + py * PROW) * 4);
        bool ok = oky && okx;
        cp_async4(drow + lane32 * 4, srow + (ok ? gx : 0), ok ? 4 : 0);
        if (lane32 < 2) {
            bool ok2 = oky && okx2;
            cp_async4(drow + (32 + lane32) * 4, srow + (ok2 ? (gx + 32) : 0), ok2 ? 4 : 0);
        }
        py += 8;
        if (py >= 34) { py -= 34; cq++; }
    }
    (void)inp_pairs;
}

// ---------------------------------------------------------------------------
// bf16 tensor-core 3x3 SAME conv + bias + relu.  Dual-camera.
// Block: 32x32 pixel tile x 16 ko, 256 threads (8 warps).
// Warp: 8-row band x 16 x-pixels x 16 ko.  K=16 ci per MMA (chunk = 16 ci).
// OBF: true -> bf16x2 pair output; false -> fp32 output.
// ---------------------------------------------------------------------------
template<int CIN, bool OBF>
__global__ void __launch_bounds__(256, 2) conv3x3_bf16_kernel(
    const unsigned* __restrict__ in, int inp_pairs,
    const unsigned* __restrict__ wb0, const unsigned* __restrict__ wb1,
    const float* __restrict__ bias0, const float* __restrict__ bias1,
    unsigned* __restrict__ outu, float* __restrict__ outf,
    int out_pairs, int groups)
{
    constexpr int NCHUNK = CIN / 16;

    extern __shared__ __align__(16) float smem[];
    unsigned* ws_base = (unsigned*)smem;                      // 2 * WS_U32
    unsigned* patch_base = (unsigned*)smem + 2 * WS_U32;      // 2 * PATCH_U32
    uint32_t sbase = (uint32_t)__cvta_generic_to_shared(smem);
    const uint32_t ws_off[2] = { sbase, sbase + (uint32_t)(WS_U32 * 4) };
    const uint32_t pa_off[2] = { sbase + (uint32_t)(2 * WS_U32 * 4),
                                 sbase + (uint32_t)((2 * WS_U32 + PATCH_U32) * 4) };

    const int img = blockIdx.z / groups;
    const int grp = blockIdx.z % groups;
    const unsigned* wb = (img < NIMG_CAM) ? wb0 : wb1;
    const float* bias  = (img < NIMG_CAM) ? bias0 : bias1;

    const int tid = threadIdx.x;
    const int w    = tid >> 5;
    const int lane = tid & 31;
    const int lg   = lane >> 2;         // 0..7
    const int tig  = lane & 3;          // 0..3
    const int wy   = w >> 1;            // band 0..3
    const int x0   = (w & 1) * 16;
    const int bx = (int)blockIdx.x;
    const int by = (int)blockIdx.y;

    const unsigned* ib = in + (size_t)img * inp_pairs * NPIX;

    float d[8][2][4];
#pragma unroll
    for (int sb = 0; sb < 8; sb++)
#pragma unroll
        for (int h = 0; h < 2; h++)
#pragma unroll
            for (int i = 0; i < 4; i++) d[sb][h][i] = 0.f;

    stage_chunk_bf16(ib, inp_pairs, wb, NCHUNK, grp, bx, by, 0, ws_off[0], pa_off[0], tid);
    cp_commit();
    if (NCHUNK > 1) {
        stage_chunk_bf16(ib, inp_pairs, wb, NCHUNK, grp, bx, by, 1, ws_off[1], pa_off[1], tid);
        cp_commit();
    }

    for (int ch = 0; ch < NCHUNK; ch++) {
        const int cur = ch & 1;
        if (ch + 1 < NCHUNK) cp_wait<1>(); else cp_wait<0>();
        __syncthreads();

        const unsigned* W = ws_base + cur * WS_U32;
        const unsigned* PA = patch_base + cur * PATCH_U32
                           + tig * PCH + (wy * 8) * PROW + x0 + lg;

#pragma unroll
        for (int kx = 0; kx < 3; kx++) {
            unsigned a[10][4];
#pragma unroll
            for (int r = 0; r < 10; r++) {
                const unsigned* ap = PA + r * PROW + kx;
                a[r][0] = ap[0];            // x,   cq=tig
                a[r][1] = ap[8];            // x+8, cq=tig
                a[r][2] = ap[4 * PCH];      // x,   cq=tig+4
                a[r][3] = ap[4 * PCH + 8];  // x+8, cq=tig+4
            }
#pragma unroll
            for (int ky = 0; ky < 3; ky++) {
                const int k = ky * 3 + kx;
                const unsigned* wk = W + k * 128;
                unsigned b00 = wk[lg * 8 + tig];            // ko=lg,   cq=tig
                unsigned b01 = wk[lg * 8 + tig + 4];        //          cq=tig+4
                unsigned b10 = wk[(8 + lg) * 8 + tig];      // ko=lg+8
                unsigned b11 = wk[(8 + lg) * 8 + tig + 4];
#pragma unroll
                for (int sb = 0; sb < 8; sb++) {
                    mma_bf16(d[sb][0], a[sb + ky], b00, b01);
                    mma_bf16(d[sb][1], a[sb + ky], b10, b11);
                }
            }
        }

        if (ch + 2 < NCHUNK) {
            __syncthreads();
            stage_chunk_bf16(ib, inp_pairs, wb, NCHUNK, grp, bx, by, ch + 2,
                             ws_off[cur], pa_off[cur], tid);
            cp_commit();
        }
    }

    // epilogue: bias + relu
    const int gxa = bx * 32 + x0 + lg;
    const int gxb = gxa + 8;
    if (OBF) {
        unsigned* ob = outu + (size_t)img * out_pairs * NPIX;
#pragma unroll
        for (int h = 0; h < 2; h++) {
            const int ko0 = h * 8 + 2 * tig;             // local ko of c0
            const float bi0 = bias[grp * 16 + ko0];
            const float bi1 = bias[grp * 16 + ko0 + 1];
            const int q = grp * 8 + h * 4 + tig;         // global pair index
            unsigned* oq = ob + (size_t)q * NPIX;
#pragma unroll
            for (int sb = 0; sb < 8; sb++) {
                const int gy = by * 32 + wy * 8 + sb;
                oq[gy * IMGD + gxa] = pack_bf2(fmaxf(d[sb][h][0] + bi0, 0.f),
                                               fmaxf(d[sb][h][1] + bi1, 0.f));
                oq[gy * IMGD + gxb] = pack_bf2(fmaxf(d[sb][h][2] + bi0, 0.f),
                                               fmaxf(d[sb][h][3] + bi1, 0.f));
            }
        }
    } else {
        float* ob = outf + (size_t)img * (groups * 16) * NPIX + (size_t)grp * 16 * NPIX;
#pragma unroll
        for (int h = 0; h < 2; h++) {
            const int ko0 = h * 8 + 2 * tig;
            const float bi0 = bias[grp * 16 + ko0];
            const float bi1 = bias[grp * 16 + ko0 + 1];
            float* o0 = ob + (size_t)ko0 * NPIX;
            float* o1 = ob + (size_t)(ko0 + 1) * NPIX;
#pragma unroll
            for (int sb = 0; sb < 8; sb++) {
                const int gy = by * 32 + wy * 8 + sb;
                o0[gy * IMGD + gxa] = fmaxf(d[sb][h][0] + bi0, 0.f);
                o1[gy * IMGD + gxa] = fmaxf(d[sb][h][1] + bi1, 0.f);
                o0[gy * IMGD + gxb] = fmaxf(d[sb][h][2] + bi0, 0.f);
                o1[gy * IMGD + gxb] = fmaxf(d[sb][h][3] + bi1, 0.f);
            }
        }
    }
}

// ---------------------------------------------------------------------------
// Layer-1 fp32 conv staging (fp32 elements)
// ---------------------------------------------------------------------------
__device__ __forceinline__ void stage_l1(
    const float* __restrict__ ib, const float* __restrict__ wt,
    int g, int bx, int by, uint32_t ws_s, uint32_t patch_s, int tid)
{
    for (int idx = tid; idx < 3 * 144; idx += 256) {
        int ci = idx / 144;
        int rem = idx - ci * 144;
        int k = rem >> 4;
        int ko = rem & 15;
        const float* src = wt + ((size_t)(g * 16 + ko) * 3 + ci) * 9 + k;
        cp_async4(ws_s + idx * 4, src, 4);
    }
    const int lane32 = tid & 31;
    int py = tid >> 5;
    int ci = 0;
    const int gx = bx * 32 - 1 + lane32;
    const bool okx = ((unsigned)gx < 128u);
    for (int r = tid >> 5; r < 3 * 34; r += 8) {
        int gy = by * 32 + py - 1;
        bool oky = ((unsigned)gy < 128u);
        const float* srow = ib + (size_t)ci * NPIX + gy * IMGD;
        uint32_t drow = patch_s + (uint32_t)((ci * PCH + py * PROW) * 4);
        bool ok = oky && okx;
        cp_async4(drow + lane32 * 4, srow + (ok ? gx : 0), ok ? 4 : 0);
        if (lane32 < 2) {
            bool ok2 = oky && ((unsigned)(gx + 32) < 128u);
            cp_async4(drow + (32 + lane32) * 4, srow + (ok2 ? (gx + 32) : 0), ok2 ? 4 : 0);
        }
        py += 8;
        if (py >= 34) { py -= 34; ci++; }
    }
}

// ---------------------------------------------------------------------------
// Layer-1 fp32 conv (CIN=3), dual-camera, bf16x2 pair output (16 pairs/img).
// ---------------------------------------------------------------------------
__global__ void __launch_bounds__(256, 2) conv3x3_l1_kernel(
    const float* __restrict__ in0, const float* __restrict__ in1,
    const float* __restrict__ wt0, const float* __restrict__ wt1,
    const float* __restrict__ bias0, const float* __restrict__ bias1,
    unsigned* __restrict__ outu, int groups)
{
    extern __shared__ __align__(16) float smem[];
    float* ws_base = smem;
    float* patch_base = smem + 3 * 144;
    uint32_t sbase = (uint32_t)__cvta_generic_to_shared(smem);
    const uint32_t ws_s = sbase;
    const uint32_t pa_s = sbase + (uint32_t)(3 * 144 * 4);

    const int img = blockIdx.z / groups;
    const int g   = blockIdx.z % groups;
    const float* wt   = (img < NIMG_CAM) ? wt0 : wt1;
    const float* bias = (img < NIMG_CAM) ? bias0 : bias1;
    const int limg = (img < NIMG_CAM) ? img : (img - NIMG_CAM);
    const float* ib = ((img < NIMG_CAM) ? in0 : in1) + (size_t)limg * 3 * NPIX;

    const int tid = threadIdx.x;
    const int tx  = tid & 15;
    const int ty  = tid >> 4;
    const int bx  = (int)blockIdx.x;
    const int by  = (int)blockIdx.y;
    const int ox0 = bx * 32 + 2 * tx;
    const int oy0 = by * 32 + 2 * ty;

    unsigned long long acc[4][8];
    const unsigned long long z2 = pack2(0.f, 0.f);
#pragma unroll
    for (int p_ = 0; p_ < 4; p_++)
#pragma unroll
        for (int i = 0; i < 8; i++) acc[p_][i] = z2;

    stage_l1(ib, wt, g, bx, by, ws_s, pa_s, tid);
    cp_commit();
    cp_wait<0>();
    __syncthreads();

#pragma unroll
    for (int ci = 0; ci < 3; ci++) {
        float p[4][4];
        const float* pb = patch_base + ci * PCH + (2 * ty) * PROW + 2 * tx;
#pragma unroll
        for (int r = 0; r < 4; r++) {
            float2 a = *(const float2*)(pb + r * PROW);
            float2 b = *(const float2*)(pb + r * PROW + 2);
            p[r][0] = a.x; p[r][1] = a.y; p[r][2] = b.x; p[r][3] = b.y;
        }
        const float* wk = ws_base + ci * 144;
#pragma unroll
        for (int k = 0; k < 9; k++) {
            const int ky = k / 3, kx = k - 3 * (k / 3);
            const ulonglong2* wp = (const ulonglong2*)(wk + k * 16);
            ulonglong2 w01 = wp[0];
            ulonglong2 w23 = wp[1];
            ulonglong2 w45 = wp[2];
            ulonglong2 w67 = wp[3];
#pragma unroll
            for (int p_ = 0; p_ < 4; p_++) {
                float v = p[(p_ >> 1) + ky][(p_ & 1) + kx];
                unsigned long long bb = pack2(v, v);
                fma2(acc[p_][0], w01.x, bb);
                fma2(acc[p_][1], w01.y, bb);
                fma2(acc[p_][2], w23.x, bb);
                fma2(acc[p_][3], w23.y, bb);
                fma2(acc[p_][4], w45.x, bb);
                fma2(acc[p_][5], w45.y, bb);
                fma2(acc[p_][6], w67.x, bb);
                fma2(acc[p_][7], w67.y, bb);
            }
        }
    }

    // epilogue: bias + relu + bf16x2 pair stores (pair q = g*8 + i)
    unsigned* ob = outu + (size_t)img * 16 * NPIX;
#pragma unroll
    for (int i = 0; i < 8; i++) {
        float b0 = bias[g * 16 + 2 * i];
        float b1 = bias[g * 16 + 2 * i + 1];
        unsigned* oq = ob + (size_t)(g * 8 + i) * NPIX;
#pragma unroll
        for (int pr = 0; pr < 2; pr++) {
            float a0l, a1l, a0r, a1r;
            unpack2(acc[pr * 2 + 0][i], a0l, a1l);
            unpack2(acc[pr * 2 + 1][i], a0r, a1r);
            int row = oy0 + pr;
            oq[row * IMGD + ox0]     = pack_bf2(fmaxf(a0l + b0, 0.f), fmaxf(a1l + b1, 0.f));
            oq[row * IMGD + ox0 + 1] = pack_bf2(fmaxf(a0r + b0, 0.f), fmaxf(a1r + b1, 0.f));
        }
    }
}

// ---------------------------------------------------------------------------
// Spatial softmax (conv16 fp32, img-major)
// ---------------------------------------------------------------------------
__global__ void __launch_bounds__(256) sspmax_kernel(
    const float* __restrict__ conv16, float* __restrict__ feat)
{
    __shared__ float red[8];
    __shared__ float r2[3][8];

    const int id = blockIdx.x;
    const int img = id >> 4;
    const int ch = id & 15;
    const int cam = (img >= NIMG_CAM) ? 1 : 0;
    const int bt = img - cam * NIMG_CAM;
    const float* p = conv16 + ((size_t)img * 16 + ch) * NPIX;
    const int tid = threadIdx.x;

    float m = -1e30f;
    for (int k = tid; k < NPIX; k += 256) m = fmaxf(m, p[k]);
    for (int o = 16; o; o >>= 1) m = fmaxf(m, __shfl_xor_sync(~0u, m, o));
    if ((tid & 31) == 0) red[tid >> 5] = m;
    __syncthreads();
    if (tid < 8) {
        float v = red[tid];
        for (int o = 4; o; o >>= 1) v = fmaxf(v, __shfl_xor_sync(0xffu, v, o));
        if (tid == 0) red[0] = v;
    }
    __syncthreads();
    m = red[0];

    float se = 0.f, sx = 0.f, sy = 0.f;
    const float step = 2.f / 127.f;
    for (int k = tid; k < NPIX; k += 256) {
        float e = expf(p[k] - m);
        float px = -1.f + (float)(k & 127) * step;
        float py = -1.f + (float)(k >> 7) * step;
        se += e; sx += e * px; sy += e * py;
    }
    for (int o = 16; o; o >>= 1) {
        se += __shfl_xor_sync(~0u, se, o);
        sx += __shfl_xor_sync(~0u, sx, o);
        sy += __shfl_xor_sync(~0u, sy, o);
    }
    if ((tid & 31) == 0) { r2[0][tid >> 5] = se; r2[1][tid >> 5] = sx; r2[2][tid >> 5] = sy; }
    __syncthreads();
    if (tid == 0) {
        float a = 0.f, bx = 0.f, by = 0.f;
        for (int w = 0; w < 8; w++) { a += r2[0][w]; bx += r2[1][w]; by += r2[2][w]; }
        feat[bt * 64 + cam * 32 + 2 * ch + 0] = bx / a;
        feat[bt * 64 + cam * 32 + 2 * ch + 1] = by / a;
    }
}

// ---------------------------------------------------------------------------
// LSTM cell (unchanged from R8)
// ---------------------------------------------------------------------------
__device__ __forceinline__ float sigm(float x) { return 1.f / (1.f + expf(-x)); }

__global__ void __launch_bounds__(256) lstm_cell_kernel(
    const float* __restrict__ xa, int alen, int xa_stride,
    const float* __restrict__ im,
    const float* __restrict__ wih, const float* __restrict__ whh,
    const float* __restrict__ bih, const float* __restrict__ bhh,
    const float* __restrict__ hprev, float* __restrict__ hnew,
    float* __restrict__ c)
{
    __shared__ float xs[BB][576];
    __shared__ float hs[BB][HID];
    __shared__ float part[8][BB];
    __shared__ float gs[16];

    const int inlen = alen + 64;
    const int tid = threadIdx.x;

    for (int idx = tid; idx < BB * inlen; idx += 256) {
        int b = idx / inlen;
        int k = idx - b * inlen;
        xs[b][k] = (k < alen) ? xa[b * xa_stride + k] : im[b * (TT * 64) + (k - alen)];
    }
    for (int idx = tid; idx < BB * HID; idx += 256)
        hs[idx >> 9][idx & 511] = hprev[idx];
    __syncthreads();

    const int j = blockIdx.x;
    const int warp = tid >> 5;
    const int lane = tid & 31;
    const int g = warp >> 1;
    const int half = warp & 1;
    const int row = g * HID + j;
    const int k0 = half * 32 + lane;

    float s0 = 0.f, s1 = 0.f, s2 = 0.f, s3 = 0.f;
    const float* wr = wih + (size_t)row * inlen;
#pragma unroll 4
    for (int k = k0; k < inlen; k += 64) {
        float w = wr[k];
        s0 += w * xs[0][k]; s1 += w * xs[1][k];
        s2 += w * xs[2][k]; s3 += w * xs[3][k];
    }
    const float* hr = whh + (size_t)row * HID;
#pragma unroll 4
    for (int k = k0; k < HID; k += 64) {
        float w = hr[k];
        s0 += w * hs[0][k]; s1 += w * hs[1][k];
        s2 += w * hs[2][k]; s3 += w * hs[3][k];
    }
    for (int o = 16; o; o >>= 1) {
        s0 += __shfl_xor_sync(~0u, s0, o);
        s1 += __shfl_xor_sync(~0u, s1, o);
        s2 += __shfl_xor_sync(~0u, s2, o);
        s3 += __shfl_xor_sync(~0u, s3, o);
    }
    if (lane == 0) {
        part[warp][0] = s0; part[warp][1] = s1;
        part[warp][2] = s2; part[warp][3] = s3;
    }
    __syncthreads();

    if (tid < 16) {
        int gg = tid >> 2, b = tid & 3;
        float s = part[gg * 2][b] + part[gg * 2 + 1][b]
                + bih[gg * HID + j] + bhh[gg * HID + j];
        gs[b * 4 + gg] = s;
    }
    __syncthreads();

    if (tid < BB) {
        const int b = tid;
        float gi = gs[b * 4 + 0];
        float gf = gs[b * 4 + 1];
        float gg = gs[b * 4 + 2];
        float go = gs[b * 4 + 3];
        float cold = c[b * HID + j];
        float cn = sigm(gf) * cold + sigm(gi) * tanhf(gg);
        float hn = sigm(go) * tanhf(cn);
        c[b * HID + j] = cn;
        hnew[b * HID + j] = hn;
    }
}

// ---------------------------------------------------------------------------
// Output head
// ---------------------------------------------------------------------------
__global__ void __launch_bounds__(128) out_kernel(
    const float* __restrict__ h, const float* __restrict__ im,
    const float* __restrict__ ow, const float* __restrict__ ob,
    float* __restrict__ outp)
{
    const int b = blockIdx.x / AA;
    const int a = blockIdx.x % AA;
    const float* w = ow + a * (HID + 64);
    float s = 0.f;
    for (int k = threadIdx.x; k < HID; k += 128) s += w[k] * h[b * HID + k];
    for (int k = threadIdx.x; k < 64; k += 128) s += w[HID + k] * im[b * (TT * 64) + k];
    __shared__ float red[4];
    for (int o = 16; o; o >>= 1) s += __shfl_xor_sync(~0u, s, o);
    if ((threadIdx.x & 31) == 0) red[threadIdx.x >> 5] = s;
    __syncthreads();
    if (threadIdx.x == 0)
        outp[b * (TT * AA) + a] = red[0] + red[1] + red[2] + red[3] + ob[a];
}

__global__ void zero_state_kernel()
{
    int i = blockIdx.x * blockDim.x + threadIdx.x;
    if (i < 2 * LL * BB * HID) g_h[i] = 0.f;
    if (i < LL * BB * HID) g_c[i] = 0.f;
}

// ---------------------------------------------------------------------------
// Launch
// ---------------------------------------------------------------------------
extern "C" void kernel_launch(void* const* d_in, const int* in_sizes, int n_in,
                              void* d_out, int out_size)
{
    (void)in_sizes; (void)n_in; (void)out_size;

    const float* img_m  = (const float*)d_in[0];
    const float* img_s  = (const float*)d_in[1];
    const float* states = (const float*)d_in[2];
    const float* wih0 = (const float*)d_in[19];
    const float* whh0 = (const float*)d_in[20];
    const float* bih0 = (const float*)d_in[21];
    const float* bhh0 = (const float*)d_in[22];
    const float* wih_r = (const float*)d_in[23];
    const float* whh_r = (const float*)d_in[24];
    const float* bih_r = (const float*)d_in[25];
    const float* bhh_r = (const float*)d_in[26];
    const float* out_w = (const float*)d_in[27];
    const float* out_b = (const float*)d_in[28];
    float* outp = (float*)d_out;

    unsigned* actA; cudaGetSymbolAddress((void**)&actA, g_actA);
    unsigned* actB; cudaGetSymbolAddress((void**)&actB, g_actB);
    float* conv16;  cudaGetSymbolAddress((void**)&conv16, g_conv16);
    unsigned* wbuf; cudaGetSymbolAddress((void**)&wbuf, g_wb);
    float* feat;    cudaGetSymbolAddress((void**)&feat, g_feat);
    float* hbuf;    cudaGetSymbolAddress((void**)&hbuf, g_h);
    float* cbuf;    cudaGetSymbolAddress((void**)&cbuf, g_c);

    const int smemL1 = (3 * 144 + 3 * PCH) * 4;            // 16416
    const int smemBF = 2 * (WS_U32 + PATCH_U32) * 4;       // 87552
    cudaFuncSetAttribute(conv3x3_l1_kernel, cudaFuncAttributeMaxDynamicSharedMemorySize, smemL1);
    cudaFuncSetAttribute(conv3x3_bf16_kernel<32, true>,   cudaFuncAttributeMaxDynamicSharedMemorySize, smemBF);
    cudaFuncSetAttribute(conv3x3_bf16_kernel<64, true>,   cudaFuncAttributeMaxDynamicSharedMemorySize, smemBF);
    cudaFuncSetAttribute(conv3x3_bf16_kernel<128, false>, cudaFuncAttributeMaxDynamicSharedMemorySize, smemBF);

    zero_state_kernel<<<96, 256>>>();

    const float* mw[4] = { (const float*)d_in[3], (const float*)d_in[5],
                           (const float*)d_in[7], (const float*)d_in[9] };
    const float* mb[4] = { (const float*)d_in[4], (const float*)d_in[6],
                           (const float*)d_in[8], (const float*)d_in[10] };
    const float* sw[4] = { (const float*)d_in[11], (const float*)d_in[13],
                           (const float*)d_in[15], (const float*)d_in[17] };
    const float* sb[4] = { (const float*)d_in[12], (const float*)d_in[14],
                           (const float*)d_in[16], (const float*)d_in[18] };

    // weight prep: layers 2..4, both cams -> bf16x2 tiled blocks
    prep_w_kernel<<<(WSZ_L2 + 255) / 256, 256>>>(mw[1], wbuf + WOFF_L2, 32, WSZ_L2);
    prep_w_kernel<<<(WSZ_L3 + 255) / 256, 256>>>(mw[2], wbuf + WOFF_L3, 64, WSZ_L3);
    prep_w_kernel<<<(WSZ_L4 + 255) / 256, 256>>>(mw[3], wbuf + WOFF_L4, 128, WSZ_L4);
    prep_w_kernel<<<(WSZ_L2 + 255) / 256, 256>>>(sw[1], wbuf + WCAM + WOFF_L2, 32, WSZ_L2);
    prep_w_kernel<<<(WSZ_L3 + 255) / 256, 256>>>(sw[2], wbuf + WCAM + WOFF_L3, 64, WSZ_L3);
    prep_w_kernel<<<(WSZ_L4 + 255) / 256, 256>>>(sw[3], wbuf + WCAM + WOFF_L4, 128, WSZ_L4);

    // conv chain: L1(fp32->bf16 pairs, actA:16) -> L2(actB:32) -> L3(actA:64) -> L4(conv16 fp32)
    conv3x3_l1_kernel<<<dim3(4, 4, NIMG * 2), 256, smemL1>>>(
        img_m, img_s, mw[0], sw[0], mb[0], sb[0], actA, 2);
    conv3x3_bf16_kernel<32, true><<<dim3(4, 4, NIMG * 4), 256, smemBF>>>(
        actA, 16, wbuf + WOFF_L2, wbuf + WCAM + WOFF_L2, mb[1], sb[1],
        actB, nullptr, 32, 4);
    conv3x3_bf16_kernel<64, true><<<dim3(4, 4, NIMG * 8), 256, smemBF>>>(
        actB, 32, wbuf + WOFF_L3, wbuf + WCAM + WOFF_L3, mb[2], sb[2],
        actA, nullptr, 64, 8);
    conv3x3_bf16_kernel<128, false><<<dim3(4, 4, NIMG * 1), 256, smemBF>>>(
        actA, 64, wbuf + WOFF_L4, wbuf + WCAM + WOFF_L4, mb[3], sb[3],
        nullptr, conv16, 16, 1);

    sspmax_kernel<<<NIMG * 16, 256>>>(conv16, feat);

    const int half = LL * BB * HID;
    for (int t = 0; t < TT; t++) {
        float* hprev = hbuf + (t & 1) * half;
        float* hcur  = hbuf + (1 - (t & 1)) * half;
        const float* im_t = feat + t * 64;

        lstm_cell_kernel<<<HID, 256>>>(
            states + t * SS, SS, TT * SS, im_t,
            wih0, whh0, bih0, bhh0,
            hprev + 0, hcur + 0, cbuf + 0);

        for (int l = 1; l < LL; l++) {
            lstm_cell_kernel<<<HID, 256>>>(
                hcur + (size_t)(l - 1) * BB * HID, HID, HID, im_t,
                wih_r + (size_t)(l - 1) * 4 * HID * (HID + 64),
                whh_r + (size_t)(l - 1) * 4 * HID * HID,
                bih_r + (size_t)(l - 1) * 4 * HID,
                bhh_r + (size_t)(l - 1) * 4 * HID,
                hprev + (size_t)l * BB * HID,
                hcur + (size_t)l * BB * HID,
                cbuf + (size_t)l * BB * HID);
        }

        out_kernel<<<BB * AA, 128>>>(
            hcur + (size_t)(LL - 1) * BB * HID, im_t, out_w, out_b, outp + t * AA);
    }
}

// round 13
// speedup vs baseline: 2.0731x; 1.0488x over previous
#include <cuda_runtime.h>
#include <cuda_bf16.h>
#include <math.h>
#include <stdint.h>

// Problem constants
#define BB 4
#define TT 10
#define SS 6
#define AA 6
#define HID 512
#define LL 6
#define IMGD 128
#define NPIX 16384
#define NIMG_CAM 40
#define NIMG 80

// patch layouts
#define PROW 36
#define PCH  (34 * PROW)
#define PATCH_U32 (8 * PCH)
#define WS_U32    1152

// per-camera bf16 weight block offsets (u32 pairs)
#define WOFF_L2 0
#define WSZ_L2  9216
#define WOFF_L3 9216
#define WSZ_L3  36864
#define WOFF_L4 46080
#define WSZ_L4  9216
#define WCAM    55296

#define NBLK 512            // persistent LSTM grid

// ---------------------------------------------------------------------------
// Scratch
// ---------------------------------------------------------------------------
__device__ __align__(16) unsigned g_actA[(size_t)NIMG * 64 * NPIX];
__device__ __align__(16) unsigned g_actB[(size_t)NIMG * 32 * NPIX];
__device__ __align__(16) float    g_conv16[(size_t)NIMG * 16 * NPIX];
__device__ __align__(16) unsigned g_wb[2 * WCAM];
__device__ float g_feat[NIMG_CAM * 64];
__device__ float g_h[LL * BB * HID];
__device__ float g_c[LL * BB * HID];
__device__ unsigned g_bar_in;
__device__ unsigned g_bar_out;

// ---------------------------------------------------------------------------
// helpers
// ---------------------------------------------------------------------------
__device__ __forceinline__ unsigned long long pack2(float a, float b) {
    unsigned long long r;
    asm("mov.b64 %0, {%1, %2};" : "=l"(r) : "r"(__float_as_uint(a)), "r"(__float_as_uint(b)));
    return r;
}
__device__ __forceinline__ void unpack2(unsigned long long v, float& a, float& b) {
    unsigned int lo, hi;
    asm("mov.b64 {%0, %1}, %2;" : "=r"(lo), "=r"(hi) : "l"(v));
    a = __uint_as_float(lo); b = __uint_as_float(hi);
}
__device__ __forceinline__ void fma2(unsigned long long& d, unsigned long long a, unsigned long long b) {
    asm("fma.rn.f32x2 %0, %1, %2, %0;" : "+l"(d) : "l"(a), "l"(b));
}
__device__ __forceinline__ unsigned pack_bf2(float lo, float hi) {
    __nv_bfloat162 v = __floats2bfloat162_rn(lo, hi);
    return *(unsigned*)&v;
}

__device__ __forceinline__ void cp_async4(uint32_t smem_addr, const void* gptr, int sz) {
    asm volatile("cp.async.ca.shared.global [%0], [%1], 4, %2;\n"
                 :: "r"(smem_addr), "l"(gptr), "r"(sz));
}
__device__ __forceinline__ void cp_async16(uint32_t smem_addr, const void* gptr) {
    asm volatile("cp.async.cg.shared.global [%0], [%1], 16;\n"
                 :: "r"(smem_addr), "l"(gptr));
}
__device__ __forceinline__ void cp_commit() { asm volatile("cp.async.commit_group;"); }
template<int N>
__device__ __forceinline__ void cp_wait() { asm volatile("cp.async.wait_group %0;" :: "n"(N)); }

__device__ __forceinline__ void mma_bf16(float* d, const unsigned* a, unsigned b0, unsigned b1) {
    asm volatile(
        "mma.sync.aligned.m16n8k16.row.col.f32.bf16.bf16.f32 "
        "{%0,%1,%2,%3}, {%4,%5,%6,%7}, {%8,%9}, {%0,%1,%2,%3};"
        : "+f"(d[0]), "+f"(d[1]), "+f"(d[2]), "+f"(d[3])
        : "r"(a[0]), "r"(a[1]), "r"(a[2]), "r"(a[3]), "r"(b0), "r"(b1));
}

// ---------------------------------------------------------------------------
// Combined weight prep (all 6 blocks, both cams) -> bf16x2 tiled
// ---------------------------------------------------------------------------
__device__ __forceinline__ void prep_one(const float* wt, unsigned* dst, int CIN, int local)
{
    int p = local;
    int cq = p & 7;  p >>= 3;
    int ko_l = p & 15; p >>= 4;
    int k = p % 9;   p /= 9;
    int nch = CIN >> 4;
    int chunk = p % nch;
    int grp = p / nch;
    int ci0 = chunk * 16 + cq * 2;
    int ko = grp * 16 + ko_l;
    float lo = wt[((size_t)ko * CIN + ci0) * 9 + k];
    float hi = wt[((size_t)ko * CIN + ci0 + 1) * 9 + k];
    dst[local] = pack_bf2(lo, hi);
}

__global__ void prep_all_kernel(const float* m2, const float* m3, const float* m4,
                                const float* s2, const float* s3, const float* s4,
                                unsigned* dst)
{
    int idx = blockIdx.x * 256 + threadIdx.x;
    if (idx >= 2 * WCAM) return;
    int i = idx;
    const float* wt; int CIN; int local; unsigned* out;
    if (i < WCAM) {
        out = dst;
        if (i < WOFF_L3)      { wt = m2; CIN = 32;  local = i; out += WOFF_L2; }
        else if (i < WOFF_L4) { wt = m3; CIN = 64;  local = i - WOFF_L3; out += WOFF_L3; }
        else                  { wt = m4; CIN = 128; local = i - WOFF_L4; out += WOFF_L4; }
    } else {
        i -= WCAM;
        out = dst + WCAM;
        if (i < WOFF_L3)      { wt = s2; CIN = 32;  local = i; out += WOFF_L2; }
        else if (i < WOFF_L4) { wt = s3; CIN = 64;  local = i - WOFF_L3; out += WOFF_L3; }
        else                  { wt = s4; CIN = 128; local = i - WOFF_L4; out += WOFF_L4; }
    }
    prep_one(wt, out, CIN, local);
}

// ---------------------------------------------------------------------------
// bf16 conv staging
// ---------------------------------------------------------------------------
__device__ __forceinline__ void stage_chunk_bf16(
    const unsigned* __restrict__ inb, const unsigned* __restrict__ wb,
    int nchunk, int grp, int bx, int by, int ch,
    uint32_t ws_s, uint32_t patch_s, int tid)
{
    const unsigned* wsrc = wb + (size_t)(grp * nchunk + ch) * WS_U32;
    for (int idx = tid; idx < 288; idx += 256)
        cp_async16(ws_s + idx * 16, wsrc + idx * 4);

    const int lane32 = tid & 31;
    int py = tid >> 5;
    int cq = 0;
    const int gx = bx * 32 - 1 + lane32;
    const bool okx = ((unsigned)gx < 128u);
    const bool okx2 = ((unsigned)(gx + 32) < 128u) && (lane32 < 2);
    const int c0q = ch * 8;
#pragma unroll 4
    for (int r = tid >> 5; r < 8 * 34; r += 8) {
        int gy = by * 32 + py - 1;
        bool oky = ((unsigned)gy < 128u);
        const unsigned* srow = inb + (size_t)(c0q + cq) * NPIX + gy * IMGD;
        uint32_t drow = patch_s + (uint32_t)((cq * PCH + py * PROW) * 4);
        bool ok = oky && okx;
        cp_async4(drow + lane32 * 4, srow + (ok ? gx : 0), ok ? 4 : 0);
        if (lane32 < 2) {
            bool ok2 = oky && okx2;
            cp_async4(drow + (32 + lane32) * 4, srow + (ok2 ? (gx + 32) : 0), ok2 ? 4 : 0);
        }
        py += 8;
        if (py >= 34) { py -= 34; cq++; }
    }
}

// ---------------------------------------------------------------------------
// bf16 tensor-core 3x3 conv + bias + relu (dual-camera)
// ---------------------------------------------------------------------------
template<int CIN, bool OBF>
__global__ void __launch_bounds__(256, 2) conv3x3_bf16_kernel(
    const unsigned* __restrict__ in, int inp_pairs,
    const unsigned* __restrict__ wb0, const unsigned* __restrict__ wb1,
    const float* __restrict__ bias0, const float* __restrict__ bias1,
    unsigned* __restrict__ outu, float* __restrict__ outf,
    int out_pairs, int groups)
{
    constexpr int NCHUNK = CIN / 16;

    extern __shared__ __align__(16) float smem[];
    unsigned* ws_base = (unsigned*)smem;
    unsigned* patch_base = (unsigned*)smem + 2 * WS_U32;
    uint32_t sbase = (uint32_t)__cvta_generic_to_shared(smem);
    const uint32_t ws_off[2] = { sbase, sbase + (uint32_t)(WS_U32 * 4) };
    const uint32_t pa_off[2] = { sbase + (uint32_t)(2 * WS_U32 * 4),
                                 sbase + (uint32_t)((2 * WS_U32 + PATCH_U32) * 4) };

    const int img = blockIdx.z / groups;
    const int grp = blockIdx.z % groups;
    const unsigned* wb = (img < NIMG_CAM) ? wb0 : wb1;
    const float* bias  = (img < NIMG_CAM) ? bias0 : bias1;

    const int tid = threadIdx.x;
    const int w    = tid >> 5;
    const int lane = tid & 31;
    const int lg   = lane >> 2;
    const int tig  = lane & 3;
    const int wy   = w >> 1;
    const int x0   = (w & 1) * 16;
    const int bx = (int)blockIdx.x;
    const int by = (int)blockIdx.y;

    const unsigned* ib = in + (size_t)img * inp_pairs * NPIX;

    float d[8][2][4];
#pragma unroll
    for (int sb = 0; sb < 8; sb++)
#pragma unroll
        for (int h = 0; h < 2; h++)
#pragma unroll
            for (int i = 0; i < 4; i++) d[sb][h][i] = 0.f;

    stage_chunk_bf16(ib, wb, NCHUNK, grp, bx, by, 0, ws_off[0], pa_off[0], tid);
    cp_commit();
    if (NCHUNK > 1) {
        stage_chunk_bf16(ib, wb, NCHUNK, grp, bx, by, 1, ws_off[1], pa_off[1], tid);
        cp_commit();
    }

    for (int ch = 0; ch < NCHUNK; ch++) {
        const int cur = ch & 1;
        if (ch + 1 < NCHUNK) cp_wait<1>(); else cp_wait<0>();
        __syncthreads();

        const unsigned* W = ws_base + cur * WS_U32;
        const unsigned* PA = patch_base + cur * PATCH_U32
                           + tig * PCH + (wy * 8) * PROW + x0 + lg;

#pragma unroll
        for (int kx = 0; kx < 3; kx++) {
            unsigned a[10][4];
#pragma unroll
            for (int r = 0; r < 10; r++) {
                const unsigned* ap = PA + r * PROW + kx;
                a[r][0] = ap[0];
                a[r][1] = ap[8];
                a[r][2] = ap[4 * PCH];
                a[r][3] = ap[4 * PCH + 8];
            }
#pragma unroll
            for (int ky = 0; ky < 3; ky++) {
                const int k = ky * 3 + kx;
                const unsigned* wk = W + k * 128;
                unsigned b00 = wk[lg * 8 + tig];
                unsigned b01 = wk[lg * 8 + tig + 4];
                unsigned b10 = wk[(8 + lg) * 8 + tig];
                unsigned b11 = wk[(8 + lg) * 8 + tig + 4];
#pragma unroll
                for (int sb = 0; sb < 8; sb++) {
                    mma_bf16(d[sb][0], a[sb + ky], b00, b01);
                    mma_bf16(d[sb][1], a[sb + ky], b10, b11);
                }
            }
        }

        if (ch + 2 < NCHUNK) {
            __syncthreads();
            stage_chunk_bf16(ib, wb, NCHUNK, grp, bx, by, ch + 2,
                             ws_off[cur], pa_off[cur], tid);
            cp_commit();
        }
    }

    const int gxa = bx * 32 + x0 + lg;
    const int gxb = gxa + 8;
    if (OBF) {
        unsigned* ob = outu + (size_t)img * out_pairs * NPIX;
#pragma unroll
        for (int h = 0; h < 2; h++) {
            const int ko0 = h * 8 + 2 * tig;
            const float bi0 = bias[grp * 16 + ko0];
            const float bi1 = bias[grp * 16 + ko0 + 1];
            const int q = grp * 8 + h * 4 + tig;
            unsigned* oq = ob + (size_t)q * NPIX;
#pragma unroll
            for (int sb = 0; sb < 8; sb++) {
                const int gy = by * 32 + wy * 8 + sb;
                oq[gy * IMGD + gxa] = pack_bf2(fmaxf(d[sb][h][0] + bi0, 0.f),
                                               fmaxf(d[sb][h][1] + bi1, 0.f));
                oq[gy * IMGD + gxb] = pack_bf2(fmaxf(d[sb][h][2] + bi0, 0.f),
                                               fmaxf(d[sb][h][3] + bi1, 0.f));
            }
        }
    } else {
        float* ob = outf + (size_t)img * (groups * 16) * NPIX + (size_t)grp * 16 * NPIX;
#pragma unroll
        for (int h = 0; h < 2; h++) {
            const int ko0 = h * 8 + 2 * tig;
            const float bi0 = bias[grp * 16 + ko0];
            const float bi1 = bias[grp * 16 + ko0 + 1];
            float* o0 = ob + (size_t)ko0 * NPIX;
            float* o1 = ob + (size_t)(ko0 + 1) * NPIX;
#pragma unroll
            for (int sb = 0; sb < 8; sb++) {
                const int gy = by * 32 + wy * 8 + sb;
                o0[gy * IMGD + gxa] = fmaxf(d[sb][h][0] + bi0, 0.f);
                o1[gy * IMGD + gxa] = fmaxf(d[sb][h][1] + bi1, 0.f);
                o0[gy * IMGD + gxb] = fmaxf(d[sb][h][2] + bi0, 0.f);
                o1[gy * IMGD + gxb] = fmaxf(d[sb][h][3] + bi1, 0.f);
            }
        }
    }
}

// ---------------------------------------------------------------------------
// Layer-1 fp32 conv staging + kernel (bf16x2 output)
// ---------------------------------------------------------------------------
__device__ __forceinline__ void stage_l1(
    const float* __restrict__ ib, const float* __restrict__ wt,
    int g, int bx, int by, uint32_t ws_s, uint32_t patch_s, int tid)
{
    for (int idx = tid; idx < 3 * 144; idx += 256) {
        int ci = idx / 144;
        int rem = idx - ci * 144;
        int k = rem >> 4;
        int ko = rem & 15;
        const float* src = wt + ((size_t)(g * 16 + ko) * 3 + ci) * 9 + k;
        cp_async4(ws_s + idx * 4, src, 4);
    }
    const int lane32 = tid & 31;
    int py = tid >> 5;
    int ci = 0;
    const int gx = bx * 32 - 1 + lane32;
    const bool okx = ((unsigned)gx < 128u);
    for (int r = tid >> 5; r < 3 * 34; r += 8) {
        int gy = by * 32 + py - 1;
        bool oky = ((unsigned)gy < 128u);
        const float* srow = ib + (size_t)ci * NPIX + gy * IMGD;
        uint32_t drow = patch_s + (uint32_t)((ci * PCH + py * PROW) * 4);
        bool ok = oky && okx;
        cp_async4(drow + lane32 * 4, srow + (ok ? gx : 0), ok ? 4 : 0);
        if (lane32 < 2) {
            bool ok2 = oky && ((unsigned)(gx + 32) < 128u);
            cp_async4(drow + (32 + lane32) * 4, srow + (ok2 ? (gx + 32) : 0), ok2 ? 4 : 0);
        }
        py += 8;
        if (py >= 34) { py -= 34; ci++; }
    }
}

__global__ void __launch_bounds__(256, 2) conv3x3_l1_kernel(
    const float* __restrict__ in0, const float* __restrict__ in1,
    const float* __restrict__ wt0, const float* __restrict__ wt1,
    const float* __restrict__ bias0, const float* __restrict__ bias1,
    unsigned* __restrict__ outu, int groups)
{
    extern __shared__ __align__(16) float smem[];
    float* ws_base = smem;
    float* patch_base = smem + 3 * 144;
    uint32_t sbase = (uint32_t)__cvta_generic_to_shared(smem);
    const uint32_t ws_s = sbase;
    const uint32_t pa_s = sbase + (uint32_t)(3 * 144 * 4);

    const int img = blockIdx.z / groups;
    const int g   = blockIdx.z % groups;
    const float* wt   = (img < NIMG_CAM) ? wt0 : wt1;
    const float* bias = (img < NIMG_CAM) ? bias0 : bias1;
    const int limg = (img < NIMG_CAM) ? img : (img - NIMG_CAM);
    const float* ib = ((img < NIMG_CAM) ? in0 : in1) + (size_t)limg * 3 * NPIX;

    const int tid = threadIdx.x;
    const int tx  = tid & 15;
    const int ty  = tid >> 4;
    const int bx  = (int)blockIdx.x;
    const int by  = (int)blockIdx.y;
    const int ox0 = bx * 32 + 2 * tx;
    const int oy0 = by * 32 + 2 * ty;

    unsigned long long acc[4][8];
    const unsigned long long z2 = pack2(0.f, 0.f);
#pragma unroll
    for (int p_ = 0; p_ < 4; p_++)
#pragma unroll
        for (int i = 0; i < 8; i++) acc[p_][i] = z2;

    stage_l1(ib, wt, g, bx, by, ws_s, pa_s, tid);
    cp_commit();
    cp_wait<0>();
    __syncthreads();

#pragma unroll
    for (int ci = 0; ci < 3; ci++) {
        float p[4][4];
        const float* pb = patch_base + ci * PCH + (2 * ty) * PROW + 2 * tx;
#pragma unroll
        for (int r = 0; r < 4; r++) {
            float2 a = *(const float2*)(pb + r * PROW);
            float2 b = *(const float2*)(pb + r * PROW + 2);
            p[r][0] = a.x; p[r][1] = a.y; p[r][2] = b.x; p[r][3] = b.y;
        }
        const float* wk = ws_base + ci * 144;
#pragma unroll
        for (int k = 0; k < 9; k++) {
            const int ky = k / 3, kx = k - 3 * (k / 3);
            const ulonglong2* wp = (const ulonglong2*)(wk + k * 16);
            ulonglong2 w01 = wp[0];
            ulonglong2 w23 = wp[1];
            ulonglong2 w45 = wp[2];
            ulonglong2 w67 = wp[3];
#pragma unroll
            for (int p_ = 0; p_ < 4; p_++) {
                float v = p[(p_ >> 1) + ky][(p_ & 1) + kx];
                unsigned long long bb = pack2(v, v);
                fma2(acc[p_][0], w01.x, bb);
                fma2(acc[p_][1], w01.y, bb);
                fma2(acc[p_][2], w23.x, bb);
                fma2(acc[p_][3], w23.y, bb);
                fma2(acc[p_][4], w45.x, bb);
                fma2(acc[p_][5], w45.y, bb);
                fma2(acc[p_][6], w67.x, bb);
                fma2(acc[p_][7], w67.y, bb);
            }
        }
    }

    unsigned* ob = outu + (size_t)img * 16 * NPIX;
#pragma unroll
    for (int i = 0; i < 8; i++) {
        float b0 = bias[g * 16 + 2 * i];
        float b1 = bias[g * 16 + 2 * i + 1];
        unsigned* oq = ob + (size_t)(g * 8 + i) * NPIX;
#pragma unroll
        for (int pr = 0; pr < 2; pr++) {
            float a0l, a1l, a0r, a1r;
            unpack2(acc[pr * 2 + 0][i], a0l, a1l);
            unpack2(acc[pr * 2 + 1][i], a0r, a1r);
            int row = oy0 + pr;
            oq[row * IMGD + ox0]     = pack_bf2(fmaxf(a0l + b0, 0.f), fmaxf(a1l + b1, 0.f));
            oq[row * IMGD + ox0 + 1] = pack_bf2(fmaxf(a0r + b0, 0.f), fmaxf(a1r + b1, 0.f));
        }
    }
}

// ---------------------------------------------------------------------------
// Spatial softmax
// ---------------------------------------------------------------------------
__global__ void __launch_bounds__(256) sspmax_kernel(
    const float* __restrict__ conv16, float* __restrict__ feat)
{
    __shared__ float red[8];
    __shared__ float r2[3][8];

    const int id = blockIdx.x;
    const int img = id >> 4;
    const int ch = id & 15;
    const int cam = (img >= NIMG_CAM) ? 1 : 0;
    const int bt = img - cam * NIMG_CAM;
    const float* p = conv16 + ((size_t)img * 16 + ch) * NPIX;
    const int tid = threadIdx.x;

    float m = -1e30f;
    for (int k = tid; k < NPIX; k += 256) m = fmaxf(m, p[k]);
    for (int o = 16; o; o >>= 1) m = fmaxf(m, __shfl_xor_sync(~0u, m, o));
    if ((tid & 31) == 0) red[tid >> 5] = m;
    __syncthreads();
    if (tid < 8) {
        float v = red[tid];
        for (int o = 4; o; o >>= 1) v = fmaxf(v, __shfl_xor_sync(0xffu, v, o));
        if (tid == 0) red[0] = v;
    }
    __syncthreads();
    m = red[0];

    float se = 0.f, sx = 0.f, sy = 0.f;
    const float step = 2.f / 127.f;
    for (int k = tid; k < NPIX; k += 256) {
        float e = expf(p[k] - m);
        float px = -1.f + (float)(k & 127) * step;
        float py = -1.f + (float)(k >> 7) * step;
        se += e; sx += e * px; sy += e * py;
    }
    for (int o = 16; o; o >>= 1) {
        se += __shfl_xor_sync(~0u, se, o);
        sx += __shfl_xor_sync(~0u, sx, o);
        sy += __shfl_xor_sync(~0u, sy, o);
    }
    if ((tid & 31) == 0) { r2[0][tid >> 5] = se; r2[1][tid >> 5] = sx; r2[2][tid >> 5] = sy; }
    __syncthreads();
    if (tid == 0) {
        float a = 0.f, bx = 0.f, by = 0.f;
        for (int w = 0; w < 8; w++) { a += r2[0][w]; bx += r2[1][w]; by += r2[2][w]; }
        feat[bt * 64 + cam * 32 + 2 * ch + 0] = bx / a;
        feat[bt * 64 + cam * 32 + 2 * ch + 1] = by / a;
    }
}

// ---------------------------------------------------------------------------
// Persistent LSTM: one launch, all 60 cells + 10 output heads.
// NBLK blocks co-resident; CG-style software grid barrier between cells.
// ---------------------------------------------------------------------------
__device__ __forceinline__ float sigm(float x) { return 1.f / (1.f + expf(-x)); }

__device__ __forceinline__ void grid_bar(int epoch) {
    __syncthreads();
    if (threadIdx.x == 0) {
        __threadfence();
        unsigned target = (unsigned)(epoch + 1) * NBLK;
        unsigned t = atomicAdd(&g_bar_in, 1u);
        if (t + 1u == target) {
            atomicExch(&g_bar_out, (unsigned)(epoch + 1));
        } else {
            while (atomicAdd(&g_bar_out, 0u) < (unsigned)(epoch + 1)) { __nanosleep(64); }
        }
        __threadfence();
    }
    __syncthreads();
}

__global__ void __launch_bounds__(256, 4) lstm_seq_kernel(
    const float* __restrict__ states, const float* __restrict__ feat,
    const float* __restrict__ wih0, const float* __restrict__ whh0,
    const float* __restrict__ bih0, const float* __restrict__ bhh0,
    const float* __restrict__ wih_r, const float* __restrict__ whh_r,
    const float* __restrict__ bih_r, const float* __restrict__ bhh_r,
    const float* __restrict__ out_w, const float* __restrict__ out_b,
    float* __restrict__ h, float* __restrict__ c, float* __restrict__ outp)
{
    __shared__ float xs[BB][576];
    __shared__ float hs[BB][HID];
    __shared__ float part[8][BB];
    __shared__ float gs[16];
    __shared__ float ored[8];

    const int j = blockIdx.x;
    const int tid = threadIdx.x;
    const int warp = tid >> 5;
    const int lane = tid & 31;
    int epoch = 0;

    for (int t = 0; t < TT; t++) {
        for (int l = 0; l < LL; l++) {
            const int alen = (l == 0) ? SS : HID;
            const int inlen = alen + 64;
            const float* wih = (l == 0) ? wih0 : wih_r + (size_t)(l - 1) * 4 * HID * 576;
            const float* whh = (l == 0) ? whh0 : whh_r + (size_t)(l - 1) * 4 * HID * HID;
            const float* bih = (l == 0) ? bih0 : bih_r + (size_t)(l - 1) * 4 * HID;
            const float* bhh = (l == 0) ? bhh0 : bhh_r + (size_t)(l - 1) * 4 * HID;
            float* hl = h + (size_t)l * BB * HID;
            float* cl = c + (size_t)l * BB * HID;
            const float* hin = h + (size_t)(l - 1) * BB * HID;   // valid for l>0

            // stage xs = [x_a, im] and hs = h[l] (previous t)
            for (int idx = tid; idx < BB * inlen; idx += 256) {
                int b = idx / inlen;
                int k = idx - b * inlen;
                float v;
                if (k < alen)
                    v = (l == 0) ? states[(b * TT + t) * SS + k] : hin[b * HID + k];
                else
                    v = feat[(b * TT + t) * 64 + (k - alen)];
                xs[b][k] = v;
            }
            for (int idx = tid; idx < BB * HID; idx += 256)
                hs[idx >> 9][idx & 511] = hl[idx];
            __syncthreads();

            const int g = warp >> 1;
            const int half = warp & 1;
            const int row = g * HID + j;
            const int k0 = half * 32 + lane;

            float s0 = 0.f, s1 = 0.f, s2 = 0.f, s3 = 0.f;
            const float* wr = wih + (size_t)row * inlen;
#pragma unroll 4
            for (int k = k0; k < inlen; k += 64) {
                float w = wr[k];
                s0 += w * xs[0][k]; s1 += w * xs[1][k];
                s2 += w * xs[2][k]; s3 += w * xs[3][k];
            }
            const float* hr = whh + (size_t)row * HID;
#pragma unroll 4
            for (int k = k0; k < HID; k += 64) {
                float w = hr[k];
                s0 += w * hs[0][k]; s1 += w * hs[1][k];
                s2 += w * hs[2][k]; s3 += w * hs[3][k];
            }
            for (int o = 16; o; o >>= 1) {
                s0 += __shfl_xor_sync(~0u, s0, o);
                s1 += __shfl_xor_sync(~0u, s1, o);
                s2 += __shfl_xor_sync(~0u, s2, o);
                s3 += __shfl_xor_sync(~0u, s3, o);
            }
            if (lane == 0) {
                part[warp][0] = s0; part[warp][1] = s1;
                part[warp][2] = s2; part[warp][3] = s3;
            }
            __syncthreads();

            if (tid < 16) {
                int gg = tid >> 2, b = tid & 3;
                float s = part[gg * 2][b] + part[gg * 2 + 1][b]
                        + bih[gg * HID + j] + bhh[gg * HID + j];
                gs[b * 4 + gg] = s;
            }
            __syncthreads();

            if (tid < BB) {
                const int b = tid;
                float gi = gs[b * 4 + 0];
                float gf = gs[b * 4 + 1];
                float gg = gs[b * 4 + 2];
                float go = gs[b * 4 + 3];
                float cold = cl[b * HID + j];
                float cn = sigm(gf) * cold + sigm(gi) * tanhf(gg);
                float hn = sigm(go) * tanhf(cn);
                cl[b * HID + j] = cn;
                hl[b * HID + j] = hn;
            }
            grid_bar(epoch++);
        }

        // output head for timestep t: blocks 0..23
        if (j < BB * AA) {
            const int b = j / AA;
            const int a = j % AA;
            const float* w = out_w + a * (HID + 64);
            const float* h5 = h + (size_t)(LL - 1) * BB * HID + b * HID;
            float s = 0.f;
            for (int k = tid; k < HID; k += 256) s += w[k] * h5[k];
            for (int k = tid; k < 64; k += 256) s += w[HID + k] * feat[(b * TT + t) * 64 + k];
            for (int o = 16; o; o >>= 1) s += __shfl_xor_sync(~0u, s, o);
            if (lane == 0) ored[warp] = s;
            __syncthreads();
            if (tid == 0) {
                float r = out_b[a];
                for (int ww = 0; ww < 8; ww++) r += ored[ww];
                outp[b * (TT * AA) + t * AA + a] = r;
            }
            __syncthreads();
        }
    }
}

__global__ void zero_state_kernel()
{
    int i = blockIdx.x * blockDim.x + threadIdx.x;
    if (i < LL * BB * HID) { g_h[i] = 0.f; g_c[i] = 0.f; }
    if (i == 0) { g_bar_in = 0u; g_bar_out = 0u; }
}

// ---------------------------------------------------------------------------
// Launch
// ---------------------------------------------------------------------------
extern "C" void kernel_launch(void* const* d_in, const int* in_sizes, int n_in,
                              void* d_out, int out_size)
{
    (void)in_sizes; (void)n_in; (void)out_size;

    const float* img_m  = (const float*)d_in[0];
    const float* img_s  = (const float*)d_in[1];
    const float* states = (const float*)d_in[2];
    const float* wih0 = (const float*)d_in[19];
    const float* whh0 = (const float*)d_in[20];
    const float* bih0 = (const float*)d_in[21];
    const float* bhh0 = (const float*)d_in[22];
    const float* wih_r = (const float*)d_in[23];
    const float* whh_r = (const float*)d_in[24];
    const float* bih_r = (const float*)d_in[25];
    const float* bhh_r = (const float*)d_in[26];
    const float* out_w = (const float*)d_in[27];
    const float* out_b = (const float*)d_in[28];
    float* outp = (float*)d_out;

    unsigned* actA; cudaGetSymbolAddress((void**)&actA, g_actA);
    unsigned* actB; cudaGetSymbolAddress((void**)&actB, g_actB);
    float* conv16;  cudaGetSymbolAddress((void**)&conv16, g_conv16);
    unsigned* wbuf; cudaGetSymbolAddress((void**)&wbuf, g_wb);
    float* feat;    cudaGetSymbolAddress((void**)&feat, g_feat);
    float* hbuf;    cudaGetSymbolAddress((void**)&hbuf, g_h);
    float* cbuf;    cudaGetSymbolAddress((void**)&cbuf, g_c);

    const int smemL1 = (3 * 144 + 3 * PCH) * 4;
    const int smemBF = 2 * (WS_U32 + PATCH_U32) * 4;
    cudaFuncSetAttribute(conv3x3_l1_kernel, cudaFuncAttributeMaxDynamicSharedMemorySize, smemL1);
    cudaFuncSetAttribute(conv3x3_bf16_kernel<32, true>,   cudaFuncAttributeMaxDynamicSharedMemorySize, smemBF);
    cudaFuncSetAttribute(conv3x3_bf16_kernel<64, true>,   cudaFuncAttributeMaxDynamicSharedMemorySize, smemBF);
    cudaFuncSetAttribute(conv3x3_bf16_kernel<128, false>, cudaFuncAttributeMaxDynamicSharedMemorySize, smemBF);

    zero_state_kernel<<<48, 256>>>();

    const float* mw[4] = { (const float*)d_in[3], (const float*)d_in[5],
                           (const float*)d_in[7], (const float*)d_in[9] };
    const float* mb[4] = { (const float*)d_in[4], (const float*)d_in[6],
                           (const float*)d_in[8], (const float*)d_in[10] };
    const float* sw[4] = { (const float*)d_in[11], (const float*)d_in[13],
                           (const float*)d_in[15], (const float*)d_in[17] };
    const float* sb[4] = { (const float*)d_in[12], (const float*)d_in[14],
                           (const float*)d_in[16], (const float*)d_in[18] };

    prep_all_kernel<<<(2 * WCAM + 255) / 256, 256>>>(
        mw[1], mw[2], mw[3], sw[1], sw[2], sw[3], wbuf);

    conv3x3_l1_kernel<<<dim3(4, 4, NIMG * 2), 256, smemL1>>>(
        img_m, img_s, mw[0], sw[0], mb[0], sb[0], actA, 2);
    conv3x3_bf16_kernel<32, true><<<dim3(4, 4, NIMG * 4), 256, smemBF>>>(
        actA, 16, wbuf + WOFF_L2, wbuf + WCAM + WOFF_L2, mb[1], sb[1],
        actB, nullptr, 32, 4);
    conv3x3_bf16_kernel<64, true><<<dim3(4, 4, NIMG * 8), 256, smemBF>>>(
        actB, 32, wbuf + WOFF_L3, wbuf + WCAM + WOFF_L3, mb[2], sb[2],
        actA, nullptr, 64, 8);
    conv3x3_bf16_kernel<128, false><<<dim3(4, 4, NIMG * 1), 256, smemBF>>>(
        actA, 64, wbuf + WOFF_L4, wbuf + WCAM + WOFF_L4, mb[3], sb[3],
        nullptr, conv16, 16, 1);

    sspmax_kernel<<<NIMG * 16, 256>>>(conv16, feat);

    lstm_seq_kernel<<<NBLK, 256>>>(
        states, feat,
        wih0, whh0, bih0, bhh0,
        wih_r, whh_r, bih_r, bhh_r,
        out_w, out_b,
        hbuf, cbuf, outp);
}

// round 14
// speedup vs baseline: 2.5331x; 1.2219x over previous
#include <cuda_runtime.h>
#include <cuda_bf16.h>
#include <math.h>
#include <stdint.h>

// Problem constants
#define BB 4
#define TT 10
#define SS 6
#define AA 6
#define HID 512
#define LL 6
#define IMGD 128
#define NPIX 16384
#define NIMG_CAM 40
#define NIMG 80

// padded activation planes: 130 rows x 132 cols (u32 = bf16x2 pair)
#define PLROW 132
#define PLROWS 130
#define PLSTR (PLROW * PLROWS)      // 17160 u32 per plane

// patch layouts
#define PROW 36
#define PCH  (34 * PROW)            // 1224
#define PATCH_U32 (8 * PCH)         // 9792
#define WS_U32    1152

// fp32 L1 patch (unpadded input)
#define PCH_F (34 * PROW)

// per-camera bf16 weight block offsets (u32 pairs)
#define WOFF_L2 0
#define WSZ_L2  9216
#define WOFF_L3 9216
#define WSZ_L3  36864
#define WOFF_L4 46080
#define WSZ_L4  9216
#define WCAM    55296

#define NBLK 512            // persistent LSTM grid
#define NPLANES (NIMG * 64 + NIMG * 32)   // padded planes to border-zero

// ---------------------------------------------------------------------------
// Scratch
// ---------------------------------------------------------------------------
__device__ __align__(16) unsigned g_actA[(size_t)NIMG * 64 * PLSTR];
__device__ __align__(16) unsigned g_actB[(size_t)NIMG * 32 * PLSTR];
__device__ __align__(16) float    g_conv16[(size_t)NIMG * 16 * NPIX];
__device__ __align__(16) unsigned g_wb[2 * WCAM];
__device__ float g_feat[NIMG_CAM * 64];
__device__ float g_h[LL * BB * HID];
__device__ float g_c[LL * BB * HID];
__device__ unsigned g_bar_in;
__device__ unsigned g_bar_out;

// ---------------------------------------------------------------------------
// helpers
// ---------------------------------------------------------------------------
__device__ __forceinline__ unsigned long long pack2(float a, float b) {
    unsigned long long r;
    asm("mov.b64 %0, {%1, %2};" : "=l"(r) : "r"(__float_as_uint(a)), "r"(__float_as_uint(b)));
    return r;
}
__device__ __forceinline__ void unpack2(unsigned long long v, float& a, float& b) {
    unsigned int lo, hi;
    asm("mov.b64 {%0, %1}, %2;" : "=r"(lo), "=r"(hi) : "l"(v));
    a = __uint_as_float(lo); b = __uint_as_float(hi);
}
__device__ __forceinline__ void fma2(unsigned long long& d, unsigned long long a, unsigned long long b) {
    asm("fma.rn.f32x2 %0, %1, %2, %0;" : "+l"(d) : "l"(a), "l"(b));
}
__device__ __forceinline__ unsigned pack_bf2(float lo, float hi) {
    __nv_bfloat162 v = __floats2bfloat162_rn(lo, hi);
    return *(unsigned*)&v;
}

__device__ __forceinline__ void cp_async4(uint32_t smem_addr, const void* gptr, int sz) {
    asm volatile("cp.async.ca.shared.global [%0], [%1], 4, %2;\n"
                 :: "r"(smem_addr), "l"(gptr), "r"(sz));
}
__device__ __forceinline__ void cp_async16(uint32_t smem_addr, const void* gptr) {
    asm volatile("cp.async.cg.shared.global [%0], [%1], 16;\n"
                 :: "r"(smem_addr), "l"(gptr));
}
__device__ __forceinline__ void cp_commit() { asm volatile("cp.async.commit_group;"); }
template<int N>
__device__ __forceinline__ void cp_wait() { asm volatile("cp.async.wait_group %0;" :: "n"(N)); }

__device__ __forceinline__ void mma_bf16(float* d, const unsigned* a, unsigned b0, unsigned b1) {
    asm volatile(
        "mma.sync.aligned.m16n8k16.row.col.f32.bf16.bf16.f32 "
        "{%0,%1,%2,%3}, {%4,%5,%6,%7}, {%8,%9}, {%0,%1,%2,%3};"
        : "+f"(d[0]), "+f"(d[1]), "+f"(d[2]), "+f"(d[3])
        : "r"(a[0]), "r"(a[1]), "r"(a[2]), "r"(a[3]), "r"(b0), "r"(b1));
}

// ---------------------------------------------------------------------------
// Init: zero h/c/barriers + zero borders of all padded planes
// ---------------------------------------------------------------------------
__global__ void init_kernel()
{
    int i = blockIdx.x * 256 + threadIdx.x;
    if (i < LL * BB * HID) { g_h[i] = 0.f; g_c[i] = 0.f; }
    if (i == 0) { g_bar_in = 0u; g_bar_out = 0u; }
    if (i < NPLANES * 520) {
        int plane = i / 520;
        int e = i - plane * 520;
        unsigned* base = (plane < NIMG * 64)
                       ? g_actA + (size_t)plane * PLSTR
                       : g_actB + (size_t)(plane - NIMG * 64) * PLSTR;
        int r, c;
        if (e < 264) { r = (e < 132) ? 0 : 129; c = (e < 132) ? e : e - 132; }
        else { int e2 = e - 264; r = 1 + (e2 >> 1); c = (e2 & 1) ? 129 : 0; }
        base[r * PLROW + c] = 0u;
    }
}

// ---------------------------------------------------------------------------
// Combined weight prep -> bf16x2 tiled
// ---------------------------------------------------------------------------
__device__ __forceinline__ void prep_one(const float* wt, unsigned* dst, int CIN, int local)
{
    int p = local;
    int cq = p & 7;  p >>= 3;
    int ko_l = p & 15; p >>= 4;
    int k = p % 9;   p /= 9;
    int nch = CIN >> 4;
    int chunk = p % nch;
    int grp = p / nch;
    int ci0 = chunk * 16 + cq * 2;
    int ko = grp * 16 + ko_l;
    float lo = wt[((size_t)ko * CIN + ci0) * 9 + k];
    float hi = wt[((size_t)ko * CIN + ci0 + 1) * 9 + k];
    dst[local] = pack_bf2(lo, hi);
}

__global__ void prep_all_kernel(const float* m2, const float* m3, const float* m4,
                                const float* s2, const float* s3, const float* s4,
                                unsigned* dst)
{
    int idx = blockIdx.x * 256 + threadIdx.x;
    if (idx >= 2 * WCAM) return;
    int i = idx;
    const float* wt; int CIN; int local; unsigned* out;
    if (i < WCAM) {
        out = dst;
        if (i < WOFF_L3)      { wt = m2; CIN = 32;  local = i; out += WOFF_L2; }
        else if (i < WOFF_L4) { wt = m3; CIN = 64;  local = i - WOFF_L3; out += WOFF_L3; }
        else                  { wt = m4; CIN = 128; local = i - WOFF_L4; out += WOFF_L4; }
    } else {
        i -= WCAM;
        out = dst + WCAM;
        if (i < WOFF_L3)      { wt = s2; CIN = 32;  local = i; out += WOFF_L2; }
        else if (i < WOFF_L4) { wt = s3; CIN = 64;  local = i - WOFF_L3; out += WOFF_L3; }
        else                  { wt = s4; CIN = 128; local = i - WOFF_L4; out += WOFF_L4; }
    }
    prep_one(wt, out, CIN, local);
}

// ---------------------------------------------------------------------------
// bf16 conv staging: padded planes -> 9x cp.async16 per halo row, no predicates
// ---------------------------------------------------------------------------
__device__ __forceinline__ void stage_chunk_bf16(
    const unsigned* __restrict__ ib, const unsigned* __restrict__ wb,
    int nchunk, int grp, int bx32, int by32, int ch,
    uint32_t ws_s, uint32_t patch_s, int tid)
{
    const unsigned* wsrc = wb + (size_t)(grp * nchunk + ch) * WS_U32;
    for (int idx = tid; idx < 288; idx += 256)
        cp_async16(ws_s + idx * 16, wsrc + idx * 4);

    const int c0q = ch * 8;
#pragma unroll
    for (int cq = 0; cq < 8; cq++) {
        const unsigned* plane = ib + (size_t)(c0q + cq) * PLSTR
                              + (size_t)by32 * PLROW + bx32;
        uint32_t pdst = patch_s + (uint32_t)(cq * PCH * 4);
        // 34 rows x 9 16B-segments = 306 tasks
        for (int t = tid; t < 306; t += 256) {
            int r = t / 9;
            int seg = t - r * 9;
            cp_async16(pdst + (uint32_t)((r * PROW + seg * 4) * 4),
                       plane + r * PLROW + seg * 4);
        }
    }
}

// ---------------------------------------------------------------------------
// bf16 tensor-core 3x3 conv + bias + relu (dual-camera, padded I/O)
// OBF: true -> padded bf16x2 planes; false -> flat fp32 planes
// ---------------------------------------------------------------------------
template<int CIN, bool OBF>
__global__ void __launch_bounds__(256, 2) conv3x3_bf16_kernel(
    const unsigned* __restrict__ in, int inp_pairs,
    const unsigned* __restrict__ wb0, const unsigned* __restrict__ wb1,
    const float* __restrict__ bias0, const float* __restrict__ bias1,
    unsigned* __restrict__ outu, float* __restrict__ outf,
    int out_pairs, int groups)
{
    constexpr int NCHUNK = CIN / 16;

    extern __shared__ __align__(16) float smem[];
    unsigned* ws_base = (unsigned*)smem;
    unsigned* patch_base = (unsigned*)smem + 2 * WS_U32;
    uint32_t sbase = (uint32_t)__cvta_generic_to_shared(smem);
    const uint32_t ws_off[2] = { sbase, sbase + (uint32_t)(WS_U32 * 4) };
    const uint32_t pa_off[2] = { sbase + (uint32_t)(2 * WS_U32 * 4),
                                 sbase + (uint32_t)((2 * WS_U32 + PATCH_U32) * 4) };

    const int img = blockIdx.z / groups;
    const int grp = blockIdx.z % groups;
    const unsigned* wb = (img < NIMG_CAM) ? wb0 : wb1;
    const float* bias  = (img < NIMG_CAM) ? bias0 : bias1;

    const int tid = threadIdx.x;
    const int w    = tid >> 5;
    const int lane = tid & 31;
    const int lg   = lane >> 2;
    const int tig  = lane & 3;
    const int wy   = w >> 1;
    const int x0   = (w & 1) * 16;
    const int bx32 = (int)blockIdx.x * 32;
    const int by32 = (int)blockIdx.y * 32;

    const unsigned* ib = in + (size_t)img * inp_pairs * PLSTR;

    float d[8][2][4];
#pragma unroll
    for (int sb = 0; sb < 8; sb++)
#pragma unroll
        for (int h = 0; h < 2; h++)
#pragma unroll
            for (int i = 0; i < 4; i++) d[sb][h][i] = 0.f;

    stage_chunk_bf16(ib, wb, NCHUNK, grp, bx32, by32, 0, ws_off[0], pa_off[0], tid);
    cp_commit();
    if (NCHUNK > 1) {
        stage_chunk_bf16(ib, wb, NCHUNK, grp, bx32, by32, 1, ws_off[1], pa_off[1], tid);
        cp_commit();
    }

    for (int ch = 0; ch < NCHUNK; ch++) {
        const int cur = ch & 1;
        if (ch + 1 < NCHUNK) cp_wait<1>(); else cp_wait<0>();
        __syncthreads();

        const unsigned* W = ws_base + cur * WS_U32;
        const unsigned* PA = patch_base + cur * PATCH_U32
                           + tig * PCH + (wy * 8) * PROW + x0 + lg;

#pragma unroll
        for (int kx = 0; kx < 3; kx++) {
            unsigned a[10][4];
#pragma unroll
            for (int r = 0; r < 10; r++) {
                const unsigned* ap = PA + r * PROW + kx;
                a[r][0] = ap[0];
                a[r][1] = ap[8];
                a[r][2] = ap[4 * PCH];
                a[r][3] = ap[4 * PCH + 8];
            }
#pragma unroll
            for (int ky = 0; ky < 3; ky++) {
                const int k = ky * 3 + kx;
                const unsigned* wk = W + k * 128;
                unsigned b00 = wk[lg * 8 + tig];
                unsigned b01 = wk[lg * 8 + tig + 4];
                unsigned b10 = wk[(8 + lg) * 8 + tig];
                unsigned b11 = wk[(8 + lg) * 8 + tig + 4];
#pragma unroll
                for (int sb = 0; sb < 8; sb++) {
                    mma_bf16(d[sb][0], a[sb + ky], b00, b01);
                    mma_bf16(d[sb][1], a[sb + ky], b10, b11);
                }
            }
        }

        if (ch + 2 < NCHUNK) {
            __syncthreads();
            stage_chunk_bf16(ib, wb, NCHUNK, grp, bx32, by32, ch + 2,
                             ws_off[cur], pa_off[cur], tid);
            cp_commit();
        }
    }

    const int gxa = bx32 + x0 + lg;
    const int gxb = gxa + 8;
    if (OBF) {
        unsigned* ob = outu + (size_t)img * out_pairs * PLSTR;
#pragma unroll
        for (int h = 0; h < 2; h++) {
            const int ko0 = h * 8 + 2 * tig;
            const float bi0 = bias[grp * 16 + ko0];
            const float bi1 = bias[grp * 16 + ko0 + 1];
            const int q = grp * 8 + h * 4 + tig;
            unsigned* oq = ob + (size_t)q * PLSTR;
#pragma unroll
            for (int sb = 0; sb < 8; sb++) {
                const int gy = by32 + wy * 8 + sb;
                oq[(gy + 1) * PLROW + gxa + 1] = pack_bf2(fmaxf(d[sb][h][0] + bi0, 0.f),
                                                          fmaxf(d[sb][h][1] + bi1, 0.f));
                oq[(gy + 1) * PLROW + gxb + 1] = pack_bf2(fmaxf(d[sb][h][2] + bi0, 0.f),
                                                          fmaxf(d[sb][h][3] + bi1, 0.f));
            }
        }
    } else {
        float* ob = outf + (size_t)img * (groups * 16) * NPIX + (size_t)grp * 16 * NPIX;
#pragma unroll
        for (int h = 0; h < 2; h++) {
            const int ko0 = h * 8 + 2 * tig;
            const float bi0 = bias[grp * 16 + ko0];
            const float bi1 = bias[grp * 16 + ko0 + 1];
            float* o0 = ob + (size_t)ko0 * NPIX;
            float* o1 = ob + (size_t)(ko0 + 1) * NPIX;
#pragma unroll
            for (int sb = 0; sb < 8; sb++) {
                const int gy = by32 + wy * 8 + sb;
                o0[gy * IMGD + gxa] = fmaxf(d[sb][h][0] + bi0, 0.f);
                o1[gy * IMGD + gxa] = fmaxf(d[sb][h][1] + bi1, 0.f);
                o0[gy * IMGD + gxb] = fmaxf(d[sb][h][2] + bi0, 0.f);
                o1[gy * IMGD + gxb] = fmaxf(d[sb][h][3] + bi1, 0.f);
            }
        }
    }
}

// ---------------------------------------------------------------------------
// Layer-1 fp32 conv (unpadded input, predicated staging) -> padded bf16 pairs
// ---------------------------------------------------------------------------
__device__ __forceinline__ void stage_l1(
    const float* __restrict__ ib, const float* __restrict__ wt,
    int g, int bx, int by, uint32_t ws_s, uint32_t patch_s, int tid)
{
    for (int idx = tid; idx < 3 * 144; idx += 256) {
        int ci = idx / 144;
        int rem = idx - ci * 144;
        int k = rem >> 4;
        int ko = rem & 15;
        const float* src = wt + ((size_t)(g * 16 + ko) * 3 + ci) * 9 + k;
        cp_async4(ws_s + idx * 4, src, 4);
    }
    const int lane32 = tid & 31;
    int py = tid >> 5;
    int ci = 0;
    const int gx = bx * 32 - 1 + lane32;
    const bool okx = ((unsigned)gx < 128u);
    for (int r = tid >> 5; r < 3 * 34; r += 8) {
        int gy = by * 32 + py - 1;
        bool oky = ((unsigned)gy < 128u);
        const float* srow = ib + (size_t)ci * NPIX + gy * IMGD;
        uint32_t drow = patch_s + (uint32_t)((ci * PCH_F + py * PROW) * 4);
        bool ok = oky && okx;
        cp_async4(drow + lane32 * 4, srow + (ok ? gx : 0), ok ? 4 : 0);
        if (lane32 < 2) {
            bool ok2 = oky && ((unsigned)(gx + 32) < 128u);
            cp_async4(drow + (32 + lane32) * 4, srow + (ok2 ? (gx + 32) : 0), ok2 ? 4 : 0);
        }
        py += 8;
        if (py >= 34) { py -= 34; ci++; }
    }
}

__global__ void __launch_bounds__(256, 2) conv3x3_l1_kernel(
    const float* __restrict__ in0, const float* __restrict__ in1,
    const float* __restrict__ wt0, const float* __restrict__ wt1,
    const float* __restrict__ bias0, const float* __restrict__ bias1,
    unsigned* __restrict__ outu, int groups)
{
    extern __shared__ __align__(16) float smem[];
    float* ws_base = smem;
    float* patch_base = smem + 3 * 144;
    uint32_t sbase = (uint32_t)__cvta_generic_to_shared(smem);
    const uint32_t ws_s = sbase;
    const uint32_t pa_s = sbase + (uint32_t)(3 * 144 * 4);

    const int img = blockIdx.z / groups;
    const int g   = blockIdx.z % groups;
    const float* wt   = (img < NIMG_CAM) ? wt0 : wt1;
    const float* bias = (img < NIMG_CAM) ? bias0 : bias1;
    const int limg = (img < NIMG_CAM) ? img : (img - NIMG_CAM);
    const float* ib = ((img < NIMG_CAM) ? in0 : in1) + (size_t)limg * 3 * NPIX;

    const int tid = threadIdx.x;
    const int tx  = tid & 15;
    const int ty  = tid >> 4;
    const int bx  = (int)blockIdx.x;
    const int by  = (int)blockIdx.y;
    const int ox0 = bx * 32 + 2 * tx;
    const int oy0 = by * 32 + 2 * ty;

    unsigned long long acc[4][8];
    const unsigned long long z2 = pack2(0.f, 0.f);
#pragma unroll
    for (int p_ = 0; p_ < 4; p_++)
#pragma unroll
        for (int i = 0; i < 8; i++) acc[p_][i] = z2;

    stage_l1(ib, wt, g, bx, by, ws_s, pa_s, tid);
    cp_commit();
    cp_wait<0>();
    __syncthreads();

#pragma unroll
    for (int ci = 0; ci < 3; ci++) {
        float p[4][4];
        const float* pb = patch_base + ci * PCH_F + (2 * ty) * PROW + 2 * tx;
#pragma unroll
        for (int r = 0; r < 4; r++) {
            float2 a = *(const float2*)(pb + r * PROW);
            float2 b = *(const float2*)(pb + r * PROW + 2);
            p[r][0] = a.x; p[r][1] = a.y; p[r][2] = b.x; p[r][3] = b.y;
        }
        const float* wk = ws_base + ci * 144;
#pragma unroll
        for (int k = 0; k < 9; k++) {
            const int ky = k / 3, kx = k - 3 * (k / 3);
            const ulonglong2* wp = (const ulonglong2*)(wk + k * 16);
            ulonglong2 w01 = wp[0];
            ulonglong2 w23 = wp[1];
            ulonglong2 w45 = wp[2];
            ulonglong2 w67 = wp[3];
#pragma unroll
            for (int p_ = 0; p_ < 4; p_++) {
                float v = p[(p_ >> 1) + ky][(p_ & 1) + kx];
                unsigned long long bb = pack2(v, v);
                fma2(acc[p_][0], w01.x, bb);
                fma2(acc[p_][1], w01.y, bb);
                fma2(acc[p_][2], w23.x, bb);
                fma2(acc[p_][3], w23.y, bb);
                fma2(acc[p_][4], w45.x, bb);
                fma2(acc[p_][5], w45.y, bb);
                fma2(acc[p_][6], w67.x, bb);
                fma2(acc[p_][7], w67.y, bb);
            }
        }
    }

    // epilogue -> padded planes (16 pairs per img)
    unsigned* ob = outu + (size_t)img * 16 * PLSTR;
#pragma unroll
    for (int i = 0; i < 8; i++) {
        float b0 = bias[g * 16 + 2 * i];
        float b1 = bias[g * 16 + 2 * i + 1];
        unsigned* oq = ob + (size_t)(g * 8 + i) * PLSTR;
#pragma unroll
        for (int pr = 0; pr < 2; pr++) {
            float a0l, a1l, a0r, a1r;
            unpack2(acc[pr * 2 + 0][i], a0l, a1l);
            unpack2(acc[pr * 2 + 1][i], a0r, a1r);
            int row = oy0 + pr;
            oq[(row + 1) * PLROW + ox0 + 1] = pack_bf2(fmaxf(a0l + b0, 0.f), fmaxf(a1l + b1, 0.f));
            oq[(row + 1) * PLROW + ox0 + 2] = pack_bf2(fmaxf(a0r + b0, 0.f), fmaxf(a1r + b1, 0.f));
        }
    }
}

// ---------------------------------------------------------------------------
// Spatial softmax
// ---------------------------------------------------------------------------
__global__ void __launch_bounds__(256) sspmax_kernel(
    const float* __restrict__ conv16, float* __restrict__ feat)
{
    __shared__ float red[8];
    __shared__ float r2[3][8];

    const int id = blockIdx.x;
    const int img = id >> 4;
    const int ch = id & 15;
    const int cam = (img >= NIMG_CAM) ? 1 : 0;
    const int bt = img - cam * NIMG_CAM;
    const float* p = conv16 + ((size_t)img * 16 + ch) * NPIX;
    const int tid = threadIdx.x;

    float m = -1e30f;
    for (int k = tid; k < NPIX; k += 256) m = fmaxf(m, p[k]);
    for (int o = 16; o; o >>= 1) m = fmaxf(m, __shfl_xor_sync(~0u, m, o));
    if ((tid & 31) == 0) red[tid >> 5] = m;
    __syncthreads();
    if (tid < 8) {
        float v = red[tid];
        for (int o = 4; o; o >>= 1) v = fmaxf(v, __shfl_xor_sync(0xffu, v, o));
        if (tid == 0) red[0] = v;
    }
    __syncthreads();
    m = red[0];

    float se = 0.f, sx = 0.f, sy = 0.f;
    const float step = 2.f / 127.f;
    for (int k = tid; k < NPIX; k += 256) {
        float e = expf(p[k] - m);
        float px = -1.f + (float)(k & 127) * step;
        float py = -1.f + (float)(k >> 7) * step;
        se += e; sx += e * px; sy += e * py;
    }
    for (int o = 16; o; o >>= 1) {
        se += __shfl_xor_sync(~0u, se, o);
        sx += __shfl_xor_sync(~0u, sx, o);
        sy += __shfl_xor_sync(~0u, sy, o);
    }
    if ((tid & 31) == 0) { r2[0][tid >> 5] = se; r2[1][tid >> 5] = sx; r2[2][tid >> 5] = sy; }
    __syncthreads();
    if (tid == 0) {
        float a = 0.f, bx = 0.f, by = 0.f;
        for (int w = 0; w < 8; w++) { a += r2[0][w]; bx += r2[1][w]; by += r2[2][w]; }
        feat[bt * 64 + cam * 32 + 2 * ch + 0] = bx / a;
        feat[bt * 64 + cam * 32 + 2 * ch + 1] = by / a;
    }
}

// ---------------------------------------------------------------------------
// Persistent LSTM (unchanged from R13)
// ---------------------------------------------------------------------------
__device__ __forceinline__ float sigm(float x) { return 1.f / (1.f + expf(-x)); }

__device__ __forceinline__ void grid_bar(int epoch) {
    __syncthreads();
    if (threadIdx.x == 0) {
        __threadfence();
        unsigned target = (unsigned)(epoch + 1) * NBLK;
        unsigned t = atomicAdd(&g_bar_in, 1u);
        if (t + 1u == target) {
            atomicExch(&g_bar_out, (unsigned)(epoch + 1));
        } else {
            while (atomicAdd(&g_bar_out, 0u) < (unsigned)(epoch + 1)) { __nanosleep(64); }
        }
        __threadfence();
    }
    __syncthreads();
}

__global__ void __launch_bounds__(256, 4) lstm_seq_kernel(
    const float* __restrict__ states, const float* __restrict__ feat,
    const float* __restrict__ wih0, const float* __restrict__ whh0,
    const float* __restrict__ bih0, const float* __restrict__ bhh0,
    const float* __restrict__ wih_r, const float* __restrict__ whh_r,
    const float* __restrict__ bih_r, const float* __restrict__ bhh_r,
    const float* __restrict__ out_w, const float* __restrict__ out_b,
    float* __restrict__ h, float* __restrict__ c, float* __restrict__ outp)
{
    __shared__ float xs[BB][576];
    __shared__ float hs[BB][HID];
    __shared__ float part[8][BB];
    __shared__ float gs[16];
    __shared__ float ored[8];

    const int j = blockIdx.x;
    const int tid = threadIdx.x;
    const int warp = tid >> 5;
    const int lane = tid & 31;
    int epoch = 0;

    for (int t = 0; t < TT; t++) {
        for (int l = 0; l < LL; l++) {
            const int alen = (l == 0) ? SS : HID;
            const int inlen = alen + 64;
            const float* wih = (l == 0) ? wih0 : wih_r + (size_t)(l - 1) * 4 * HID * 576;
            const float* whh = (l == 0) ? whh0 : whh_r + (size_t)(l - 1) * 4 * HID * HID;
            const float* bih = (l == 0) ? bih0 : bih_r + (size_t)(l - 1) * 4 * HID;
            const float* bhh = (l == 0) ? bhh0 : bhh_r + (size_t)(l - 1) * 4 * HID;
            float* hl = h + (size_t)l * BB * HID;
            float* cl = c + (size_t)l * BB * HID;
            const float* hin = h + (size_t)(l - 1) * BB * HID;

            for (int idx = tid; idx < BB * inlen; idx += 256) {
                int b = idx / inlen;
                int k = idx - b * inlen;
                float v;
                if (k < alen)
                    v = (l == 0) ? states[(b * TT + t) * SS + k] : hin[b * HID + k];
                else
                    v = feat[(b * TT + t) * 64 + (k - alen)];
                xs[b][k] = v;
            }
            for (int idx = tid; idx < BB * HID; idx += 256)
                hs[idx >> 9][idx & 511] = hl[idx];
            __syncthreads();

            const int g = warp >> 1;
            const int half = warp & 1;
            const int row = g * HID + j;
            const int k0 = half * 32 + lane;

            float s0 = 0.f, s1 = 0.f, s2 = 0.f, s3 = 0.f;
            const float* wr = wih + (size_t)row * inlen;
#pragma unroll 4
            for (int k = k0; k < inlen; k += 64) {
                float w = wr[k];
                s0 += w * xs[0][k]; s1 += w * xs[1][k];
                s2 += w * xs[2][k]; s3 += w * xs[3][k];
            }
            const float* hr = whh + (size_t)row * HID;
#pragma unroll 4
            for (int k = k0; k < HID; k += 64) {
                float w = hr[k];
                s0 += w * hs[0][k]; s1 += w * hs[1][k];
                s2 += w * hs[2][k]; s3 += w * hs[3][k];
            }
            for (int o = 16; o; o >>= 1) {
                s0 += __shfl_xor_sync(~0u, s0, o);
                s1 += __shfl_xor_sync(~0u, s1, o);
                s2 += __shfl_xor_sync(~0u, s2, o);
                s3 += __shfl_xor_sync(~0u, s3, o);
            }
            if (lane == 0) {
                part[warp][0] = s0; part[warp][1] = s1;
                part[warp][2] = s2; part[warp][3] = s3;
            }
            __syncthreads();

            if (tid < 16) {
                int gg = tid >> 2, b = tid & 3;
                float s = part[gg * 2][b] + part[gg * 2 + 1][b]
                        + bih[gg * HID + j] + bhh[gg * HID + j];
                gs[b * 4 + gg] = s;
            }
            __syncthreads();

            if (tid < BB) {
                const int b = tid;
                float gi = gs[b * 4 + 0];
                float gf = gs[b * 4 + 1];
                float gg = gs[b * 4 + 2];
                float go = gs[b * 4 + 3];
                float cold = cl[b * HID + j];
                float cn = sigm(gf) * cold + sigm(gi) * tanhf(gg);
                float hn = sigm(go) * tanhf(cn);
                cl[b * HID + j] = cn;
                hl[b * HID + j] = hn;
            }
            grid_bar(epoch++);
        }

        if (j < BB * AA) {
            const int b = j / AA;
            const int a = j % AA;
            const float* w = out_w + a * (HID + 64);
            const float* h5 = h + (size_t)(LL - 1) * BB * HID + b * HID;
            float s = 0.f;
            for (int k = tid; k < HID; k += 256) s += w[k] * h5[k];
            for (int k = tid; k < 64; k += 256) s += w[HID + k] * feat[(b * TT + t) * 64 + k];
            for (int o = 16; o; o >>= 1) s += __shfl_xor_sync(~0u, s, o);
            if (lane == 0) ored[warp] = s;
            __syncthreads();
            if (tid == 0) {
                float r = out_b[a];
                for (int ww = 0; ww < 8; ww++) r += ored[ww];
                outp[b * (TT * AA) + t * AA + a] = r;
            }
            __syncthreads();
        }
    }
}

// ---------------------------------------------------------------------------
// Launch
// ---------------------------------------------------------------------------
extern "C" void kernel_launch(void* const* d_in, const int* in_sizes, int n_in,
                              void* d_out, int out_size)
{
    (void)in_sizes; (void)n_in; (void)out_size;

    const float* img_m  = (const float*)d_in[0];
    const float* img_s  = (const float*)d_in[1];
    const float* states = (const float*)d_in[2];
    const float* wih0 = (const float*)d_in[19];
    const float* whh0 = (const float*)d_in[20];
    const float* bih0 = (const float*)d_in[21];
    const float* bhh0 = (const float*)d_in[22];
    const float* wih_r = (const float*)d_in[23];
    const float* whh_r = (const float*)d_in[24];
    const float* bih_r = (const float*)d_in[25];
    const float* bhh_r = (const float*)d_in[26];
    const float* out_w = (const float*)d_in[27];
    const float* out_b = (const float*)d_in[28];
    float* outp = (float*)d_out;

    unsigned* actA; cudaGetSymbolAddress((void**)&actA, g_actA);
    unsigned* actB; cudaGetSymbolAddress((void**)&actB, g_actB);
    float* conv16;  cudaGetSymbolAddress((void**)&conv16, g_conv16);
    unsigned* wbuf; cudaGetSymbolAddress((void**)&wbuf, g_wb);
    float* feat;    cudaGetSymbolAddress((void**)&feat, g_feat);
    float* hbuf;    cudaGetSymbolAddress((void**)&hbuf, g_h);
    float* cbuf;    cudaGetSymbolAddress((void**)&cbuf, g_c);

    const int smemL1 = (3 * 144 + 3 * PCH_F) * 4;
    const int smemBF = 2 * (WS_U32 + PATCH_U32) * 4;
    cudaFuncSetAttribute(conv3x3_l1_kernel, cudaFuncAttributeMaxDynamicSharedMemorySize, smemL1);
    cudaFuncSetAttribute(conv3x3_bf16_kernel<32, true>,   cudaFuncAttributeMaxDynamicSharedMemorySize, smemBF);
    cudaFuncSetAttribute(conv3x3_bf16_kernel<64, true>,   cudaFuncAttributeMaxDynamicSharedMemorySize, smemBF);
    cudaFuncSetAttribute(conv3x3_bf16_kernel<128, false>, cudaFuncAttributeMaxDynamicSharedMemorySize, smemBF);

    init_kernel<<<(NPLANES * 520 + 255) / 256, 256>>>();

    const float* mw[4] = { (const float*)d_in[3], (const float*)d_in[5],
                           (const float*)d_in[7], (const float*)d_in[9] };
    const float* mb[4] = { (const float*)d_in[4], (const float*)d_in[6],
                           (const float*)d_in[8], (const float*)d_in[10] };
    const float* sw[4] = { (const float*)d_in[11], (const float*)d_in[13],
                           (const float*)d_in[15], (const float*)d_in[17] };
    const float* sb[4] = { (const float*)d_in[12], (const float*)d_in[14],
                           (const float*)d_in[16], (const float*)d_in[18] };

    prep_all_kernel<<<(2 * WCAM + 255) / 256, 256>>>(
        mw[1], mw[2], mw[3], sw[1], sw[2], sw[3], wbuf);

    conv3x3_l1_kernel<<<dim3(4, 4, NIMG * 2), 256, smemL1>>>(
        img_m, img_s, mw[0], sw[0], mb[0], sb[0], actA, 2);
    conv3x3_bf16_kernel<32, true><<<dim3(4, 4, NIMG * 4), 256, smemBF>>>(
        actA, 16, wbuf + WOFF_L2, wbuf + WCAM + WOFF_L2, mb[1], sb[1],
        actB, nullptr, 32, 4);
    conv3x3_bf16_kernel<64, true><<<dim3(4, 4, NIMG * 8), 256, smemBF>>>(
        actB, 32, wbuf + WOFF_L3, wbuf + WCAM + WOFF_L3, mb[2], sb[2],
        actA, nullptr, 64, 8);
    conv3x3_bf16_kernel<128, false><<<dim3(4, 4, NIMG * 1), 256, smemBF>>>(
        actA, 64, wbuf + WOFF_L4, wbuf + WCAM + WOFF_L4, mb[3], sb[3],
        nullptr, conv16, 16, 1);

    sspmax_kernel<<<NIMG * 16, 256>>>(conv16, feat);

    lstm_seq_kernel<<<NBLK, 256>>>(
        states, feat,
        wih0, whh0, bih0, bhh0,
        wih_r, whh_r, bih_r, bhh_r,
        out_w, out_b,
        hbuf, cbuf, outp);
}

// round 15
// speedup vs baseline: 2.7845x; 1.0992x over previous
#include <cuda_runtime.h>
#include <cuda_bf16.h>
#include <math.h>
#include <stdint.h>

// Problem constants
#define BB 4
#define TT 10
#define SS 6
#define AA 6
#define HID 512
#define LL 6
#define IMGD 128
#define NPIX 16384
#define NIMG_CAM 40
#define NIMG 80

// padded activation planes: 130 rows x 132 cols (u32 = bf16x2 pair)
#define PLROW 132
#define PLROWS 130
#define PLSTR (PLROW * PLROWS)

// patch layouts
#define PROW 36
#define PCH  (34 * PROW)
#define PATCH_U32 (8 * PCH)
#define WS_U32    1152
#define PCH_F (34 * PROW)

// per-camera bf16 weight block offsets (u32 pairs)
#define WOFF_L2 0
#define WSZ_L2  9216
#define WOFF_L3 9216
#define WSZ_L3  36864
#define WOFF_L4 46080
#define WSZ_L4  9216
#define WCAM    55296

#define NBLK 512
#define NWAVE 16                         // wavefronts: cells w=0..14, heads t=w-6
#define NPLANES (NIMG * 64 + NIMG * 32)

// ---------------------------------------------------------------------------
// Scratch
// ---------------------------------------------------------------------------
__device__ __align__(16) unsigned g_actA[(size_t)NIMG * 64 * PLSTR];
__device__ __align__(16) unsigned g_actB[(size_t)NIMG * 32 * PLSTR];
__device__ __align__(16) float    g_conv16[(size_t)NIMG * 16 * NPIX];
__device__ __align__(16) unsigned g_wb[2 * WCAM];
__device__ float g_feat[NIMG_CAM * 64];
__device__ float g_h[2 * LL * BB * HID];      // parity double buffer
__device__ float g_c[LL * BB * HID];
__device__ float g_h5[TT * BB * HID];         // h[5] history per timestep
__device__ unsigned g_bar_in;
__device__ unsigned g_bar_out;

// ---------------------------------------------------------------------------
// helpers
// ---------------------------------------------------------------------------
__device__ __forceinline__ unsigned long long pack2(float a, float b) {
    unsigned long long r;
    asm("mov.b64 %0, {%1, %2};" : "=l"(r) : "r"(__float_as_uint(a)), "r"(__float_as_uint(b)));
    return r;
}
__device__ __forceinline__ void unpack2(unsigned long long v, float& a, float& b) {
    unsigned int lo, hi;
    asm("mov.b64 {%0, %1}, %2;" : "=r"(lo), "=r"(hi) : "l"(v));
    a = __uint_as_float(lo); b = __uint_as_float(hi);
}
__device__ __forceinline__ void fma2(unsigned long long& d, unsigned long long a, unsigned long long b) {
    asm("fma.rn.f32x2 %0, %1, %2, %0;" : "+l"(d) : "l"(a), "l"(b));
}
__device__ __forceinline__ unsigned pack_bf2(float lo, float hi) {
    __nv_bfloat162 v = __floats2bfloat162_rn(lo, hi);
    return *(unsigned*)&v;
}

__device__ __forceinline__ void cp_async4(uint32_t smem_addr, const void* gptr, int sz) {
    asm volatile("cp.async.ca.shared.global [%0], [%1], 4, %2;\n"
                 :: "r"(smem_addr), "l"(gptr), "r"(sz));
}
__device__ __forceinline__ void cp_async16(uint32_t smem_addr, const void* gptr) {
    asm volatile("cp.async.cg.shared.global [%0], [%1], 16;\n"
                 :: "r"(smem_addr), "l"(gptr));
}
__device__ __forceinline__ void cp_commit() { asm volatile("cp.async.commit_group;"); }
template<int N>
__device__ __forceinline__ void cp_wait() { asm volatile("cp.async.wait_group %0;" :: "n"(N)); }

__device__ __forceinline__ void mma_bf16(float* d, const unsigned* a, unsigned b0, unsigned b1) {
    asm volatile(
        "mma.sync.aligned.m16n8k16.row.col.f32.bf16.bf16.f32 "
        "{%0,%1,%2,%3}, {%4,%5,%6,%7}, {%8,%9}, {%0,%1,%2,%3};"
        : "+f"(d[0]), "+f"(d[1]), "+f"(d[2]), "+f"(d[3])
        : "r"(a[0]), "r"(a[1]), "r"(a[2]), "r"(a[3]), "r"(b0), "r"(b1));
}

// ---------------------------------------------------------------------------
// Init: zero h (both parities) / c / h5 / barriers + plane borders
// ---------------------------------------------------------------------------
__global__ void init_kernel()
{
    int i = blockIdx.x * 256 + threadIdx.x;
    if (i < 2 * LL * BB * HID) g_h[i] = 0.f;
    if (i < LL * BB * HID) g_c[i] = 0.f;
    if (i < TT * BB * HID) g_h5[i] = 0.f;
    if (i == 0) { g_bar_in = 0u; g_bar_out = 0u; }
    if (i < NPLANES * 520) {
        int plane = i / 520;
        int e = i - plane * 520;
        unsigned* base = (plane < NIMG * 64)
                       ? g_actA + (size_t)plane * PLSTR
                       : g_actB + (size_t)(plane - NIMG * 64) * PLSTR;
        int r, c;
        if (e < 264) { r = (e < 132) ? 0 : 129; c = (e < 132) ? e : e - 132; }
        else { int e2 = e - 264; r = 1 + (e2 >> 1); c = (e2 & 1) ? 129 : 0; }
        base[r * PLROW + c] = 0u;
    }
}

// ---------------------------------------------------------------------------
// Combined weight prep -> bf16x2 tiled
// ---------------------------------------------------------------------------
__device__ __forceinline__ void prep_one(const float* wt, unsigned* dst, int CIN, int local)
{
    int p = local;
    int cq = p & 7;  p >>= 3;
    int ko_l = p & 15; p >>= 4;
    int k = p % 9;   p /= 9;
    int nch = CIN >> 4;
    int chunk = p % nch;
    int grp = p / nch;
    int ci0 = chunk * 16 + cq * 2;
    int ko = grp * 16 + ko_l;
    float lo = wt[((size_t)ko * CIN + ci0) * 9 + k];
    float hi = wt[((size_t)ko * CIN + ci0 + 1) * 9 + k];
    dst[local] = pack_bf2(lo, hi);
}

__global__ void prep_all_kernel(const float* m2, const float* m3, const float* m4,
                                const float* s2, const float* s3, const float* s4,
                                unsigned* dst)
{
    int idx = blockIdx.x * 256 + threadIdx.x;
    if (idx >= 2 * WCAM) return;
    int i = idx;
    const float* wt; int CIN; int local; unsigned* out;
    if (i < WCAM) {
        out = dst;
        if (i < WOFF_L3)      { wt = m2; CIN = 32;  local = i; out += WOFF_L2; }
        else if (i < WOFF_L4) { wt = m3; CIN = 64;  local = i - WOFF_L3; out += WOFF_L3; }
        else                  { wt = m4; CIN = 128; local = i - WOFF_L4; out += WOFF_L4; }
    } else {
        i -= WCAM;
        out = dst + WCAM;
        if (i < WOFF_L3)      { wt = s2; CIN = 32;  local = i; out += WOFF_L2; }
        else if (i < WOFF_L4) { wt = s3; CIN = 64;  local = i - WOFF_L3; out += WOFF_L3; }
        else                  { wt = s4; CIN = 128; local = i - WOFF_L4; out += WOFF_L4; }
    }
    prep_one(wt, out, CIN, local);
}

// ---------------------------------------------------------------------------
// bf16 conv staging: padded planes, all cp.async16, no predicates
// ---------------------------------------------------------------------------
__device__ __forceinline__ void stage_chunk_bf16(
    const unsigned* __restrict__ ib, const unsigned* __restrict__ wb,
    int nchunk, int grp, int bx32, int by32, int ch,
    uint32_t ws_s, uint32_t patch_s, int tid)
{
    const unsigned* wsrc = wb + (size_t)(grp * nchunk + ch) * WS_U32;
    for (int idx = tid; idx < 288; idx += 256)
        cp_async16(ws_s + idx * 16, wsrc + idx * 4);

    const int c0q = ch * 8;
#pragma unroll
    for (int cq = 0; cq < 8; cq++) {
        const unsigned* plane = ib + (size_t)(c0q + cq) * PLSTR
                              + (size_t)by32 * PLROW + bx32;
        uint32_t pdst = patch_s + (uint32_t)(cq * PCH * 4);
        for (int t = tid; t < 306; t += 256) {
            int r = t / 9;
            int seg = t - r * 9;
            cp_async16(pdst + (uint32_t)((r * PROW + seg * 4) * 4),
                       plane + r * PLROW + seg * 4);
        }
    }
}

// ---------------------------------------------------------------------------
// bf16 tensor-core 3x3 conv + bias + relu (dual-camera, padded I/O)
// ---------------------------------------------------------------------------
template<int CIN, bool OBF>
__global__ void __launch_bounds__(256, 2) conv3x3_bf16_kernel(
    const unsigned* __restrict__ in, int inp_pairs,
    const unsigned* __restrict__ wb0, const unsigned* __restrict__ wb1,
    const float* __restrict__ bias0, const float* __restrict__ bias1,
    unsigned* __restrict__ outu, float* __restrict__ outf,
    int out_pairs, int groups)
{
    constexpr int NCHUNK = CIN / 16;

    extern __shared__ __align__(16) float smem[];
    unsigned* ws_base = (unsigned*)smem;
    unsigned* patch_base = (unsigned*)smem + 2 * WS_U32;
    uint32_t sbase = (uint32_t)__cvta_generic_to_shared(smem);
    const uint32_t ws_off[2] = { sbase, sbase + (uint32_t)(WS_U32 * 4) };
    const uint32_t pa_off[2] = { sbase + (uint32_t)(2 * WS_U32 * 4),
                                 sbase + (uint32_t)((2 * WS_U32 + PATCH_U32) * 4) };

    const int img = blockIdx.z / groups;
    const int grp = blockIdx.z % groups;
    const unsigned* wb = (img < NIMG_CAM) ? wb0 : wb1;
    const float* bias  = (img < NIMG_CAM) ? bias0 : bias1;

    const int tid = threadIdx.x;
    const int w    = tid >> 5;
    const int lane = tid & 31;
    const int lg   = lane >> 2;
    const int tig  = lane & 3;
    const int wy   = w >> 1;
    const int x0   = (w & 1) * 16;
    const int bx32 = (int)blockIdx.x * 32;
    const int by32 = (int)blockIdx.y * 32;

    const unsigned* ib = in + (size_t)img * inp_pairs * PLSTR;

    float d[8][2][4];
#pragma unroll
    for (int sb = 0; sb < 8; sb++)
#pragma unroll
        for (int h = 0; h < 2; h++)
#pragma unroll
            for (int i = 0; i < 4; i++) d[sb][h][i] = 0.f;

    stage_chunk_bf16(ib, wb, NCHUNK, grp, bx32, by32, 0, ws_off[0], pa_off[0], tid);
    cp_commit();
    if (NCHUNK > 1) {
        stage_chunk_bf16(ib, wb, NCHUNK, grp, bx32, by32, 1, ws_off[1], pa_off[1], tid);
        cp_commit();
    }

    for (int ch = 0; ch < NCHUNK; ch++) {
        const int cur = ch & 1;
        if (ch + 1 < NCHUNK) cp_wait<1>(); else cp_wait<0>();
        __syncthreads();

        const unsigned* W = ws_base + cur * WS_U32;
        const unsigned* PA = patch_base + cur * PATCH_U32
                           + tig * PCH + (wy * 8) * PROW + x0 + lg;

#pragma unroll
        for (int kx = 0; kx < 3; kx++) {
            unsigned a[10][4];
#pragma unroll
            for (int r = 0; r < 10; r++) {
                const unsigned* ap = PA + r * PROW + kx;
                a[r][0] = ap[0];
                a[r][1] = ap[8];
                a[r][2] = ap[4 * PCH];
                a[r][3] = ap[4 * PCH + 8];
            }
#pragma unroll
            for (int ky = 0; ky < 3; ky++) {
                const int k = ky * 3 + kx;
                const unsigned* wk = W + k * 128;
                unsigned b00 = wk[lg * 8 + tig];
                unsigned b01 = wk[lg * 8 + tig + 4];
                unsigned b10 = wk[(8 + lg) * 8 + tig];
                unsigned b11 = wk[(8 + lg) * 8 + tig + 4];
#pragma unroll
                for (int sb = 0; sb < 8; sb++) {
                    mma_bf16(d[sb][0], a[sb + ky], b00, b01);
                    mma_bf16(d[sb][1], a[sb + ky], b10, b11);
                }
            }
        }

        if (ch + 2 < NCHUNK) {
            __syncthreads();
            stage_chunk_bf16(ib, wb, NCHUNK, grp, bx32, by32, ch + 2,
                             ws_off[cur], pa_off[cur], tid);
            cp_commit();
        }
    }

    const int gxa = bx32 + x0 + lg;
    const int gxb = gxa + 8;
    if (OBF) {
        unsigned* ob = outu + (size_t)img * out_pairs * PLSTR;
#pragma unroll
        for (int h = 0; h < 2; h++) {
            const int ko0 = h * 8 + 2 * tig;
            const float bi0 = bias[grp * 16 + ko0];
            const float bi1 = bias[grp * 16 + ko0 + 1];
            const int q = grp * 8 + h * 4 + tig;
            unsigned* oq = ob + (size_t)q * PLSTR;
#pragma unroll
            for (int sb = 0; sb < 8; sb++) {
                const int gy = by32 + wy * 8 + sb;
                oq[(gy + 1) * PLROW + gxa + 1] = pack_bf2(fmaxf(d[sb][h][0] + bi0, 0.f),
                                                          fmaxf(d[sb][h][1] + bi1, 0.f));
                oq[(gy + 1) * PLROW + gxb + 1] = pack_bf2(fmaxf(d[sb][h][2] + bi0, 0.f),
                                                          fmaxf(d[sb][h][3] + bi1, 0.f));
            }
        }
    } else {
        float* ob = outf + (size_t)img * (groups * 16) * NPIX + (size_t)grp * 16 * NPIX;
#pragma unroll
        for (int h = 0; h < 2; h++) {
            const int ko0 = h * 8 + 2 * tig;
            const float bi0 = bias[grp * 16 + ko0];
            const float bi1 = bias[grp * 16 + ko0 + 1];
            float* o0 = ob + (size_t)ko0 * NPIX;
            float* o1 = ob + (size_t)(ko0 + 1) * NPIX;
#pragma unroll
            for (int sb = 0; sb < 8; sb++) {
                const int gy = by32 + wy * 8 + sb;
                o0[gy * IMGD + gxa] = fmaxf(d[sb][h][0] + bi0, 0.f);
                o1[gy * IMGD + gxa] = fmaxf(d[sb][h][1] + bi1, 0.f);
                o0[gy * IMGD + gxb] = fmaxf(d[sb][h][2] + bi0, 0.f);
                o1[gy * IMGD + gxb] = fmaxf(d[sb][h][3] + bi1, 0.f);
            }
        }
    }
}

// ---------------------------------------------------------------------------
// Layer-1 fp32 conv (unpadded input) -> padded bf16 pairs
// ---------------------------------------------------------------------------
__device__ __forceinline__ void stage_l1(
    const float* __restrict__ ib, const float* __restrict__ wt,
    int g, int bx, int by, uint32_t ws_s, uint32_t patch_s, int tid)
{
    for (int idx = tid; idx < 3 * 144; idx += 256) {
        int ci = idx / 144;
        int rem = idx - ci * 144;
        int k = rem >> 4;
        int ko = rem & 15;
        const float* src = wt + ((size_t)(g * 16 + ko) * 3 + ci) * 9 + k;
        cp_async4(ws_s + idx * 4, src, 4);
    }
    const int lane32 = tid & 31;
    int py = tid >> 5;
    int ci = 0;
    const int gx = bx * 32 - 1 + lane32;
    const bool okx = ((unsigned)gx < 128u);
    for (int r = tid >> 5; r < 3 * 34; r += 8) {
        int gy = by * 32 + py - 1;
        bool oky = ((unsigned)gy < 128u);
        const float* srow = ib + (size_t)ci * NPIX + gy * IMGD;
        uint32_t drow = patch_s + (uint32_t)((ci * PCH_F + py * PROW) * 4);
        bool ok = oky && okx;
        cp_async4(drow + lane32 * 4, srow + (ok ? gx : 0), ok ? 4 : 0);
        if (lane32 < 2) {
            bool ok2 = oky && ((unsigned)(gx + 32) < 128u);
            cp_async4(drow + (32 + lane32) * 4, srow + (ok2 ? (gx + 32) : 0), ok2 ? 4 : 0);
        }
        py += 8;
        if (py >= 34) { py -= 34; ci++; }
    }
}

__global__ void __launch_bounds__(256, 2) conv3x3_l1_kernel(
    const float* __restrict__ in0, const float* __restrict__ in1,
    const float* __restrict__ wt0, const float* __restrict__ wt1,
    const float* __restrict__ bias0, const float* __restrict__ bias1,
    unsigned* __restrict__ outu, int groups)
{
    extern __shared__ __align__(16) float smem[];
    float* ws_base = smem;
    float* patch_base = smem + 3 * 144;
    uint32_t sbase = (uint32_t)__cvta_generic_to_shared(smem);
    const uint32_t ws_s = sbase;
    const uint32_t pa_s = sbase + (uint32_t)(3 * 144 * 4);

    const int img = blockIdx.z / groups;
    const int g   = blockIdx.z % groups;
    const float* wt   = (img < NIMG_CAM) ? wt0 : wt1;
    const float* bias = (img < NIMG_CAM) ? bias0 : bias1;
    const int limg = (img < NIMG_CAM) ? img : (img - NIMG_CAM);
    const float* ib = ((img < NIMG_CAM) ? in0 : in1) + (size_t)limg * 3 * NPIX;

    const int tid = threadIdx.x;
    const int tx  = tid & 15;
    const int ty  = tid >> 4;
    const int bx  = (int)blockIdx.x;
    const int by  = (int)blockIdx.y;
    const int ox0 = bx * 32 + 2 * tx;
    const int oy0 = by * 32 + 2 * ty;

    unsigned long long acc[4][8];
    const unsigned long long z2 = pack2(0.f, 0.f);
#pragma unroll
    for (int p_ = 0; p_ < 4; p_++)
#pragma unroll
        for (int i = 0; i < 8; i++) acc[p_][i] = z2;

    stage_l1(ib, wt, g, bx, by, ws_s, pa_s, tid);
    cp_commit();
    cp_wait<0>();
    __syncthreads();

#pragma unroll
    for (int ci = 0; ci < 3; ci++) {
        float p[4][4];
        const float* pb = patch_base + ci * PCH_F + (2 * ty) * PROW + 2 * tx;
#pragma unroll
        for (int r = 0; r < 4; r++) {
            float2 a = *(const float2*)(pb + r * PROW);
            float2 b = *(const float2*)(pb + r * PROW + 2);
            p[r][0] = a.x; p[r][1] = a.y; p[r][2] = b.x; p[r][3] = b.y;
        }
        const float* wk = ws_base + ci * 144;
#pragma unroll
        for (int k = 0; k < 9; k++) {
            const int ky = k / 3, kx = k - 3 * (k / 3);
            const ulonglong2* wp = (const ulonglong2*)(wk + k * 16);
            ulonglong2 w01 = wp[0];
            ulonglong2 w23 = wp[1];
            ulonglong2 w45 = wp[2];
            ulonglong2 w67 = wp[3];
#pragma unroll
            for (int p_ = 0; p_ < 4; p_++) {
                float v = p[(p_ >> 1) + ky][(p_ & 1) + kx];
                unsigned long long bb = pack2(v, v);
                fma2(acc[p_][0], w01.x, bb);
                fma2(acc[p_][1], w01.y, bb);
                fma2(acc[p_][2], w23.x, bb);
                fma2(acc[p_][3], w23.y, bb);
                fma2(acc[p_][4], w45.x, bb);
                fma2(acc[p_][5], w45.y, bb);
                fma2(acc[p_][6], w67.x, bb);
                fma2(acc[p_][7], w67.y, bb);
            }
        }
    }

    unsigned* ob = outu + (size_t)img * 16 * PLSTR;
#pragma unroll
    for (int i = 0; i < 8; i++) {
        float b0 = bias[g * 16 + 2 * i];
        float b1 = bias[g * 16 + 2 * i + 1];
        unsigned* oq = ob + (size_t)(g * 8 + i) * PLSTR;
#pragma unroll
        for (int pr = 0; pr < 2; pr++) {
            float a0l, a1l, a0r, a1r;
            unpack2(acc[pr * 2 + 0][i], a0l, a1l);
            unpack2(acc[pr * 2 + 1][i], a0r, a1r);
            int row = oy0 + pr;
            oq[(row + 1) * PLROW + ox0 + 1] = pack_bf2(fmaxf(a0l + b0, 0.f), fmaxf(a1l + b1, 0.f));
            oq[(row + 1) * PLROW + ox0 + 2] = pack_bf2(fmaxf(a0r + b0, 0.f), fmaxf(a1r + b1, 0.f));
        }
    }
}

// ---------------------------------------------------------------------------
// Spatial softmax
// ---------------------------------------------------------------------------
__global__ void __launch_bounds__(256) sspmax_kernel(
    const float* __restrict__ conv16, float* __restrict__ feat)
{
    __shared__ float red[8];
    __shared__ float r2[3][8];

    const int id = blockIdx.x;
    const int img = id >> 4;
    const int ch = id & 15;
    const int cam = (img >= NIMG_CAM) ? 1 : 0;
    const int bt = img - cam * NIMG_CAM;
    const float* p = conv16 + ((size_t)img * 16 + ch) * NPIX;
    const int tid = threadIdx.x;

    float m = -1e30f;
    for (int k = tid; k < NPIX; k += 256) m = fmaxf(m, p[k]);
    for (int o = 16; o; o >>= 1) m = fmaxf(m, __shfl_xor_sync(~0u, m, o));
    if ((tid & 31) == 0) red[tid >> 5] = m;
    __syncthreads();
    if (tid < 8) {
        float v = red[tid];
        for (int o = 4; o; o >>= 1) v = fmaxf(v, __shfl_xor_sync(0xffu, v, o));
        if (tid == 0) red[0] = v;
    }
    __syncthreads();
    m = red[0];

    float se = 0.f, sx = 0.f, sy = 0.f;
    const float step = 2.f / 127.f;
    for (int k = tid; k < NPIX; k += 256) {
        float e = expf(p[k] - m);
        float px = -1.f + (float)(k & 127) * step;
        float py = -1.f + (float)(k >> 7) * step;
        se += e; sx += e * px; sy += e * py;
    }
    for (int o = 16; o; o >>= 1) {
        se += __shfl_xor_sync(~0u, se, o);
        sx += __shfl_xor_sync(~0u, sx, o);
        sy += __shfl_xor_sync(~0u, sy, o);
    }
    if ((tid & 31) == 0) { r2[0][tid >> 5] = se; r2[1][tid >> 5] = sx; r2[2][tid >> 5] = sy; }
    __syncthreads();
    if (tid == 0) {
        float a = 0.f, bx = 0.f, by = 0.f;
        for (int w = 0; w < 8; w++) { a += r2[0][w]; bx += r2[1][w]; by += r2[2][w]; }
        feat[bt * 64 + cam * 32 + 2 * ch + 0] = bx / a;
        feat[bt * 64 + cam * 32 + 2 * ch + 1] = by / a;
    }
}

// ---------------------------------------------------------------------------
// Wavefront persistent LSTM: cells (t,l) with t+l == w run concurrently.
// h double-buffered by wavefront parity; c in-place (one writer per l per w);
// h[5] snapshotted to g_h5[t]; output head for t runs at w = t+6.
// 16 grid barriers total (vs 60).
// ---------------------------------------------------------------------------
__device__ __forceinline__ float sigm(float x) { return 1.f / (1.f + expf(-x)); }

__device__ __forceinline__ void grid_bar(int epoch) {
    __syncthreads();
    if (threadIdx.x == 0) {
        __threadfence();
        unsigned target = (unsigned)(epoch + 1) * NBLK;
        unsigned t = atomicAdd(&g_bar_in, 1u);
        if (t + 1u == target) {
            atomicExch(&g_bar_out, (unsigned)(epoch + 1));
        } else {
            while (atomicAdd(&g_bar_out, 0u) < (unsigned)(epoch + 1)) { __nanosleep(64); }
        }
        __threadfence();
    }
    __syncthreads();
}

__global__ void __launch_bounds__(256, 4) lstm_wave_kernel(
    const float* __restrict__ states, const float* __restrict__ feat,
    const float* __restrict__ wih0, const float* __restrict__ whh0,
    const float* __restrict__ bih0, const float* __restrict__ bhh0,
    const float* __restrict__ wih_r, const float* __restrict__ whh_r,
    const float* __restrict__ bih_r, const float* __restrict__ bhh_r,
    const float* __restrict__ out_w, const float* __restrict__ out_b,
    float* __restrict__ hbuf, float* __restrict__ c,
    float* __restrict__ h5hist, float* __restrict__ outp)
{
    __shared__ float xs[BB][576];
    __shared__ float hs[BB][HID];
    __shared__ float part[8][BB];
    __shared__ float gs[16];
    __shared__ float ored[8];

    const int j = blockIdx.x;
    const int tid = threadIdx.x;
    const int warp = tid >> 5;
    const int lane = tid & 31;
    const int HB = LL * BB * HID;

    for (int wv = 0; wv < NWAVE; wv++) {
        const float* hprev = hbuf + ((wv + 1) & 1) * HB;   // parity wv-1
        float* hcur = hbuf + (wv & 1) * HB;                // parity wv

        // output head for t = wv - 6 (reads h5 snapshot, fully parallel)
        if (j < BB * AA && wv >= 6 && wv - 6 < TT) {
            const int t = wv - 6;
            const int b = j / AA;
            const int a = j % AA;
            const float* w = out_w + a * (HID + 64);
            const float* h5 = h5hist + (size_t)(t * BB + b) * HID;
            float s = 0.f;
            for (int k = tid; k < HID; k += 256) s += w[k] * h5[k];
            for (int k = tid; k < 64; k += 256) s += w[HID + k] * feat[(b * TT + t) * 64 + k];
            for (int o = 16; o; o >>= 1) s += __shfl_xor_sync(~0u, s, o);
            if (lane == 0) ored[warp] = s;
            __syncthreads();
            if (tid == 0) {
                float r = out_b[a];
                for (int ww = 0; ww < 8; ww++) r += ored[ww];
                outp[b * (TT * AA) + t * AA + a] = r;
            }
            __syncthreads();
        }

        // cells on this wavefront
        const int lmin = (wv > TT - 1) ? (wv - (TT - 1)) : 0;
        const int lmax = (wv < LL - 1) ? wv : (LL - 1);
        for (int l = lmin; l <= lmax; l++) {
            const int t = wv - l;
            const int alen = (l == 0) ? SS : HID;
            const int inlen = alen + 64;
            const float* wih = (l == 0) ? wih0 : wih_r + (size_t)(l - 1) * 4 * HID * 576;
            const float* whh = (l == 0) ? whh0 : whh_r + (size_t)(l - 1) * 4 * HID * HID;
            const float* bih = (l == 0) ? bih0 : bih_r + (size_t)(l - 1) * 4 * HID;
            const float* bhh = (l == 0) ? bhh0 : bhh_r + (size_t)(l - 1) * 4 * HID;
            float* cl = c + (size_t)l * BB * HID;
            const float* hrec = hprev + (size_t)l * BB * HID;        // h[l] @ t-1
            const float* hin  = hprev + (size_t)(l - 1) * BB * HID;  // h[l-1] @ t (l>0)

            for (int idx = tid; idx < BB * inlen; idx += 256) {
                int b = idx / inlen;
                int k = idx - b * inlen;
                float v;
                if (k < alen)
                    v = (l == 0) ? states[(b * TT + t) * SS + k] : hin[b * HID + k];
                else
                    v = feat[(b * TT + t) * 64 + (k - alen)];
                xs[b][k] = v;
            }
            for (int idx = tid; idx < BB * HID; idx += 256)
                hs[idx >> 9][idx & 511] = hrec[idx];
            __syncthreads();

            const int g = warp >> 1;
            const int half = warp & 1;
            const int row = g * HID + j;
            const int k0 = half * 32 + lane;

            float s0 = 0.f, s1 = 0.f, s2 = 0.f, s3 = 0.f;
            const float* wr = wih + (size_t)row * inlen;
#pragma unroll 4
            for (int k = k0; k < inlen; k += 64) {
                float w = wr[k];
                s0 += w * xs[0][k]; s1 += w * xs[1][k];
                s2 += w * xs[2][k]; s3 += w * xs[3][k];
            }
            const float* hr = whh + (size_t)row * HID;
#pragma unroll 4
            for (int k = k0; k < HID; k += 64) {
                float w = hr[k];
                s0 += w * hs[0][k]; s1 += w * hs[1][k];
                s2 += w * hs[2][k]; s3 += w * hs[3][k];
            }
            for (int o = 16; o; o >>= 1) {
                s0 += __shfl_xor_sync(~0u, s0, o);
                s1 += __shfl_xor_sync(~0u, s1, o);
                s2 += __shfl_xor_sync(~0u, s2, o);
                s3 += __shfl_xor_sync(~0u, s3, o);
            }
            if (lane == 0) {
                part[warp][0] = s0; part[warp][1] = s1;
                part[warp][2] = s2; part[warp][3] = s3;
            }
            __syncthreads();

            if (tid < 16) {
                int gg = tid >> 2, b = tid & 3;
                float s = part[gg * 2][b] + part[gg * 2 + 1][b]
                        + bih[gg * HID + j] + bhh[gg * HID + j];
                gs[b * 4 + gg] = s;
            }
            __syncthreads();

            if (tid < BB) {
                const int b = tid;
                float gi = gs[b * 4 + 0];
                float gf = gs[b * 4 + 1];
                float gg = gs[b * 4 + 2];
                float go = gs[b * 4 + 3];
                float cold = cl[b * HID + j];
                float cn = sigm(gf) * cold + sigm(gi) * tanhf(gg);
                float hn = sigm(go) * tanhf(cn);
                cl[b * HID + j] = cn;
                hcur[(size_t)l * BB * HID + b * HID + j] = hn;
                if (l == LL - 1)
                    h5hist[(size_t)(t * BB + b) * HID + j] = hn;
            }
            __syncthreads();
        }

        grid_bar(wv);
    }
}

// ---------------------------------------------------------------------------
// Launch
// ---------------------------------------------------------------------------
extern "C" void kernel_launch(void* const* d_in, const int* in_sizes, int n_in,
                              void* d_out, int out_size)
{
    (void)in_sizes; (void)n_in; (void)out_size;

    const float* img_m  = (const float*)d_in[0];
    const float* img_s  = (const float*)d_in[1];
    const float* states = (const float*)d_in[2];
    const float* wih0 = (const float*)d_in[19];
    const float* whh0 = (const float*)d_in[20];
    const float* bih0 = (const float*)d_in[21];
    const float* bhh0 = (const float*)d_in[22];
    const float* wih_r = (const float*)d_in[23];
    const float* whh_r = (const float*)d_in[24];
    const float* bih_r = (const float*)d_in[25];
    const float* bhh_r = (const float*)d_in[26];
    const float* out_w = (const float*)d_in[27];
    const float* out_b = (const float*)d_in[28];
    float* outp = (float*)d_out;

    unsigned* actA; cudaGetSymbolAddress((void**)&actA, g_actA);
    unsigned* actB; cudaGetSymbolAddress((void**)&actB, g_actB);
    float* conv16;  cudaGetSymbolAddress((void**)&conv16, g_conv16);
    unsigned* wbuf; cudaGetSymbolAddress((void**)&wbuf, g_wb);
    float* feat;    cudaGetSymbolAddress((void**)&feat, g_feat);
    float* hbuf;    cudaGetSymbolAddress((void**)&hbuf, g_h);
    float* cbuf;    cudaGetSymbolAddress((void**)&cbuf, g_c);
    float* h5buf;   cudaGetSymbolAddress((void**)&h5buf, g_h5);

    const int smemL1 = (3 * 144 + 3 * PCH_F) * 4;
    const int smemBF = 2 * (WS_U32 + PATCH_U32) * 4;
    cudaFuncSetAttribute(conv3x3_l1_kernel, cudaFuncAttributeMaxDynamicSharedMemorySize, smemL1);
    cudaFuncSetAttribute(conv3x3_bf16_kernel<32, true>,   cudaFuncAttributeMaxDynamicSharedMemorySize, smemBF);
    cudaFuncSetAttribute(conv3x3_bf16_kernel<64, true>,   cudaFuncAttributeMaxDynamicSharedMemorySize, smemBF);
    cudaFuncSetAttribute(conv3x3_bf16_kernel<128, false>, cudaFuncAttributeMaxDynamicSharedMemorySize, smemBF);

    init_kernel<<<(NPLANES * 520 + 255) / 256, 256>>>();

    const float* mw[4] = { (const float*)d_in[3], (const float*)d_in[5],
                           (const float*)d_in[7], (const float*)d_in[9] };
    const float* mb[4] = { (const float*)d_in[4], (const float*)d_in[6],
                           (const float*)d_in[8], (const float*)d_in[10] };
    const float* sw[4] = { (const float*)d_in[11], (const float*)d_in[13],
                           (const float*)d_in[15], (const float*)d_in[17] };
    const float* sb[4] = { (const float*)d_in[12], (const float*)d_in[14],
                           (const float*)d_in[16], (const float*)d_in[18] };

    prep_all_kernel<<<(2 * WCAM + 255) / 256, 256>>>(
        mw[1], mw[2], mw[3], sw[1], sw[2], sw[3], wbuf);

    conv3x3_l1_kernel<<<dim3(4, 4, NIMG * 2), 256, smemL1>>>(
        img_m, img_s, mw[0], sw[0], mb[0], sb[0], actA, 2);
    conv3x3_bf16_kernel<32, true><<<dim3(4, 4, NIMG * 4), 256, smemBF>>>(
        actA, 16, wbuf + WOFF_L2, wbuf + WCAM + WOFF_L2, mb[1], sb[1],
        actB, nullptr, 32, 4);
    conv3x3_bf16_kernel<64, true><<<dim3(4, 4, NIMG * 8), 256, smemBF>>>(
        actB, 32, wbuf + WOFF_L3, wbuf + WCAM + WOFF_L3, mb[2], sb[2],
        actA, nullptr, 64, 8);
    conv3x3_bf16_kernel<128, false><<<dim3(4, 4, NIMG * 1), 256, smemBF>>>(
        actA, 64, wbuf + WOFF_L4, wbuf + WCAM + WOFF_L4, mb[3], sb[3],
        nullptr, conv16, 16, 1);

    sspmax_kernel<<<NIMG * 16, 256>>>(conv16, feat);

    lstm_wave_kernel<<<NBLK, 256>>>(
        states, feat,
        wih0, whh0, bih0, bhh0,
        wih_r, whh_r, bih_r, bhh_r,
        out_w, out_b,
        hbuf, cbuf, h5buf, outp);
}

// round 16
// speedup vs baseline: 2.9368x; 1.0547x over previous
#include <cuda_runtime.h>
#include <cuda_bf16.h>
#include <math.h>
#include <stdint.h>

// Problem constants
#define BB 4
#define TT 10
#define SS 6
#define AA 6
#define HID 512
#define LL 6
#define IMGD 128
#define NPIX 16384
#define NIMG_CAM 40
#define NIMG 80

// padded activation planes: 130 rows x 132 cols (u32 = bf16x2 pair)
#define PLROW 132
#define PLROWS 130
#define PLSTR (PLROW * PLROWS)

// bf16 conv patch (32x16 tile): halo 18 rows x 34 cols, padded row 36
#define PROW 36
#define PCHH (18 * PROW)             // 648 u32 per cq (648 % 32 == 8)
#define PATCH_U32 (8 * PCHH)         // 5184
#define WS_U32    1152

// fp32 L1 patch (32x32 tile)
#define PCH_F (34 * PROW)

// per-camera bf16 weight block offsets (u32 pairs)
#define WOFF_L2 0
#define WSZ_L2  9216
#define WOFF_L3 9216
#define WSZ_L3  36864
#define WOFF_L4 46080
#define WSZ_L4  9216
#define WCAM    55296

#define NBLK 512
#define NWAVE 16
#define NPLANES (NIMG * 64 + NIMG * 32)

// ---------------------------------------------------------------------------
// Scratch
// ---------------------------------------------------------------------------
__device__ __align__(16) unsigned g_actA[(size_t)NIMG * 64 * PLSTR];
__device__ __align__(16) unsigned g_actB[(size_t)NIMG * 32 * PLSTR];
__device__ __align__(16) float    g_conv16[(size_t)NIMG * 16 * NPIX];
__device__ __align__(16) unsigned g_wb[2 * WCAM];
__device__ float g_feat[NIMG_CAM * 64];
__device__ float g_h[2 * LL * BB * HID];
__device__ float g_c[LL * BB * HID];
__device__ float g_h5[TT * BB * HID];
__device__ unsigned g_bar_in;
__device__ unsigned g_bar_out;

// ---------------------------------------------------------------------------
// helpers
// ---------------------------------------------------------------------------
__device__ __forceinline__ unsigned long long pack2(float a, float b) {
    unsigned long long r;
    asm("mov.b64 %0, {%1, %2};" : "=l"(r) : "r"(__float_as_uint(a)), "r"(__float_as_uint(b)));
    return r;
}
__device__ __forceinline__ void unpack2(unsigned long long v, float& a, float& b) {
    unsigned int lo, hi;
    asm("mov.b64 {%0, %1}, %2;" : "=r"(lo), "=r"(hi) : "l"(v));
    a = __uint_as_float(lo); b = __uint_as_float(hi);
}
__device__ __forceinline__ void fma2(unsigned long long& d, unsigned long long a, unsigned long long b) {
    asm("fma.rn.f32x2 %0, %1, %2, %0;" : "+l"(d) : "l"(a), "l"(b));
}
__device__ __forceinline__ unsigned pack_bf2(float lo, float hi) {
    __nv_bfloat162 v = __floats2bfloat162_rn(lo, hi);
    return *(unsigned*)&v;
}

__device__ __forceinline__ void cp_async4(uint32_t smem_addr, const void* gptr, int sz) {
    asm volatile("cp.async.ca.shared.global [%0], [%1], 4, %2;\n"
                 :: "r"(smem_addr), "l"(gptr), "r"(sz));
}
__device__ __forceinline__ void cp_async16(uint32_t smem_addr, const void* gptr) {
    asm volatile("cp.async.cg.shared.global [%0], [%1], 16;\n"
                 :: "r"(smem_addr), "l"(gptr));
}
__device__ __forceinline__ void cp_commit() { asm volatile("cp.async.commit_group;"); }
template<int N>
__device__ __forceinline__ void cp_wait() { asm volatile("cp.async.wait_group %0;" :: "n"(N)); }

__device__ __forceinline__ void mma_bf16(float* d, const unsigned* a, unsigned b0, unsigned b1) {
    asm volatile(
        "mma.sync.aligned.m16n8k16.row.col.f32.bf16.bf16.f32 "
        "{%0,%1,%2,%3}, {%4,%5,%6,%7}, {%8,%9}, {%0,%1,%2,%3};"
        : "+f"(d[0]), "+f"(d[1]), "+f"(d[2]), "+f"(d[3])
        : "r"(a[0]), "r"(a[1]), "r"(a[2]), "r"(a[3]), "r"(b0), "r"(b1));
}

// ---------------------------------------------------------------------------
// Init: zero h (both parities) / c / h5 / barriers + plane borders
// ---------------------------------------------------------------------------
__global__ void init_kernel()
{
    int i = blockIdx.x * 256 + threadIdx.x;
    if (i < 2 * LL * BB * HID) g_h[i] = 0.f;
    if (i < LL * BB * HID) g_c[i] = 0.f;
    if (i < TT * BB * HID) g_h5[i] = 0.f;
    if (i == 0) { g_bar_in = 0u; g_bar_out = 0u; }
    if (i < NPLANES * 520) {
        int plane = i / 520;
        int e = i - plane * 520;
        unsigned* base = (plane < NIMG * 64)
                       ? g_actA + (size_t)plane * PLSTR
                       : g_actB + (size_t)(plane - NIMG * 64) * PLSTR;
        int r, c;
        if (e < 264) { r = (e < 132) ? 0 : 129; c = (e < 132) ? e : e - 132; }
        else { int e2 = e - 264; r = 1 + (e2 >> 1); c = (e2 & 1) ? 129 : 0; }
        base[r * PLROW + c] = 0u;
    }
}

// ---------------------------------------------------------------------------
// Combined weight prep -> bf16x2 tiled
// ---------------------------------------------------------------------------
__device__ __forceinline__ void prep_one(const float* wt, unsigned* dst, int CIN, int local)
{
    int p = local;
    int cq = p & 7;  p >>= 3;
    int ko_l = p & 15; p >>= 4;
    int k = p % 9;   p /= 9;
    int nch = CIN >> 4;
    int chunk = p % nch;
    int grp = p / nch;
    int ci0 = chunk * 16 + cq * 2;
    int ko = grp * 16 + ko_l;
    float lo = wt[((size_t)ko * CIN + ci0) * 9 + k];
    float hi = wt[((size_t)ko * CIN + ci0 + 1) * 9 + k];
    dst[local] = pack_bf2(lo, hi);
}

__global__ void prep_all_kernel(const float* m2, const float* m3, const float* m4,
                                const float* s2, const float* s3, const float* s4,
                                unsigned* dst)
{
    int idx = blockIdx.x * 256 + threadIdx.x;
    if (idx >= 2 * WCAM) return;
    int i = idx;
    const float* wt; int CIN; int local; unsigned* out;
    if (i < WCAM) {
        out = dst;
        if (i < WOFF_L3)      { wt = m2; CIN = 32;  local = i; out += WOFF_L2; }
        else if (i < WOFF_L4) { wt = m3; CIN = 64;  local = i - WOFF_L3; out += WOFF_L3; }
        else                  { wt = m4; CIN = 128; local = i - WOFF_L4; out += WOFF_L4; }
    } else {
        i -= WCAM;
        out = dst + WCAM;
        if (i < WOFF_L3)      { wt = s2; CIN = 32;  local = i; out += WOFF_L2; }
        else if (i < WOFF_L4) { wt = s3; CIN = 64;  local = i - WOFF_L3; out += WOFF_L3; }
        else                  { wt = s4; CIN = 128; local = i - WOFF_L4; out += WOFF_L4; }
    }
    prep_one(wt, out, CIN, local);
}

// ---------------------------------------------------------------------------
// bf16 conv staging (32x16 tile): 18 halo rows x 9 16B-segments per cq
// ---------------------------------------------------------------------------
__device__ __forceinline__ void stage_chunk_bf16(
    const unsigned* __restrict__ ib, const unsigned* __restrict__ wb,
    int nchunk, int grp, int bx32, int by16, int ch,
    uint32_t ws_s, uint32_t patch_s, int tid)
{
    const unsigned* wsrc = wb + (size_t)(grp * nchunk + ch) * WS_U32;
    for (int idx = tid; idx < 288; idx += 256)
        cp_async16(ws_s + idx * 16, wsrc + idx * 4);

    const int c0q = ch * 8;
#pragma unroll
    for (int cq = 0; cq < 8; cq++) {
        const unsigned* plane = ib + (size_t)(c0q + cq) * PLSTR
                              + (size_t)by16 * PLROW + bx32;
        uint32_t pdst = patch_s + (uint32_t)(cq * PCHH * 4);
        // 18 rows x 9 segments = 162 tasks
        for (int t = tid; t < 162; t += 256) {
            int r = t / 9;
            int seg = t - r * 9;
            cp_async16(pdst + (uint32_t)((r * PROW + seg * 4) * 4),
                       plane + r * PLROW + seg * 4);
        }
    }
}

// ---------------------------------------------------------------------------
// bf16 tensor-core 3x3 conv + bias + relu (dual-camera, padded I/O)
// Block: 32x16 pixel tile x 16 ko, 256 threads, 3 CTAs/SM.
// Warp: 4-row band x 16 x-pixels x 16 ko.
// ---------------------------------------------------------------------------
template<int CIN, bool OBF>
__global__ void __launch_bounds__(256, 3) conv3x3_bf16_kernel(
    const unsigned* __restrict__ in, int inp_pairs,
    const unsigned* __restrict__ wb0, const unsigned* __restrict__ wb1,
    const float* __restrict__ bias0, const float* __restrict__ bias1,
    unsigned* __restrict__ outu, float* __restrict__ outf,
    int out_pairs, int groups)
{
    constexpr int NCHUNK = CIN / 16;

    extern __shared__ __align__(16) float smem[];
    unsigned* ws_base = (unsigned*)smem;
    unsigned* patch_base = (unsigned*)smem + 2 * WS_U32;
    uint32_t sbase = (uint32_t)__cvta_generic_to_shared(smem);
    const uint32_t ws_off[2] = { sbase, sbase + (uint32_t)(WS_U32 * 4) };
    const uint32_t pa_off[2] = { sbase + (uint32_t)(2 * WS_U32 * 4),
                                 sbase + (uint32_t)((2 * WS_U32 + PATCH_U32) * 4) };

    const int img = blockIdx.z / groups;
    const int grp = blockIdx.z % groups;
    const unsigned* wb = (img < NIMG_CAM) ? wb0 : wb1;
    const float* bias  = (img < NIMG_CAM) ? bias0 : bias1;

    const int tid = threadIdx.x;
    const int w    = tid >> 5;
    const int lane = tid & 31;
    const int lg   = lane >> 2;
    const int tig  = lane & 3;
    const int wy   = w >> 1;            // 4-row band 0..3
    const int x0   = (w & 1) * 16;
    const int bx32 = (int)blockIdx.x * 32;
    const int by16 = (int)blockIdx.y * 16;

    const unsigned* ib = in + (size_t)img * inp_pairs * PLSTR;

    float d[4][2][4];
#pragma unroll
    for (int sb = 0; sb < 4; sb++)
#pragma unroll
        for (int h = 0; h < 2; h++)
#pragma unroll
            for (int i = 0; i < 4; i++) d[sb][h][i] = 0.f;

    stage_chunk_bf16(ib, wb, NCHUNK, grp, bx32, by16, 0, ws_off[0], pa_off[0], tid);
    cp_commit();
    if (NCHUNK > 1) {
        stage_chunk_bf16(ib, wb, NCHUNK, grp, bx32, by16, 1, ws_off[1], pa_off[1], tid);
        cp_commit();
    }

    for (int ch = 0; ch < NCHUNK; ch++) {
        const int cur = ch & 1;
        if (ch + 1 < NCHUNK) cp_wait<1>(); else cp_wait<0>();
        __syncthreads();

        const unsigned* W = ws_base + cur * WS_U32;
        const unsigned* PA = patch_base + cur * PATCH_U32
                           + tig * PCHH + (wy * 4) * PROW + x0 + lg;

#pragma unroll
        for (int kx = 0; kx < 3; kx++) {
            unsigned a[6][4];
#pragma unroll
            for (int r = 0; r < 6; r++) {
                const unsigned* ap = PA + r * PROW + kx;
                a[r][0] = ap[0];
                a[r][1] = ap[8];
                a[r][2] = ap[4 * PCHH];
                a[r][3] = ap[4 * PCHH + 8];
            }
#pragma unroll
            for (int ky = 0; ky < 3; ky++) {
                const int k = ky * 3 + kx;
                const unsigned* wk = W + k * 128;
                unsigned b00 = wk[lg * 8 + tig];
                unsigned b01 = wk[lg * 8 + tig + 4];
                unsigned b10 = wk[(8 + lg) * 8 + tig];
                unsigned b11 = wk[(8 + lg) * 8 + tig + 4];
#pragma unroll
                for (int sb = 0; sb < 4; sb++) {
                    mma_bf16(d[sb][0], a[sb + ky], b00, b01);
                    mma_bf16(d[sb][1], a[sb + ky], b10, b11);
                }
            }
        }

        if (ch + 2 < NCHUNK) {
            __syncthreads();
            stage_chunk_bf16(ib, wb, NCHUNK, grp, bx32, by16, ch + 2,
                             ws_off[cur], pa_off[cur], tid);
            cp_commit();
        }
    }

    const int gxa = bx32 + x0 + lg;
    const int gxb = gxa + 8;
    if (OBF) {
        unsigned* ob = outu + (size_t)img * out_pairs * PLSTR;
#pragma unroll
        for (int h = 0; h < 2; h++) {
            const int ko0 = h * 8 + 2 * tig;
            const float bi0 = bias[grp * 16 + ko0];
            const float bi1 = bias[grp * 16 + ko0 + 1];
            const int q = grp * 8 + h * 4 + tig;
            unsigned* oq = ob + (size_t)q * PLSTR;
#pragma unroll
            for (int sb = 0; sb < 4; sb++) {
                const int gy = by16 + wy * 4 + sb;
                oq[(gy + 1) * PLROW + gxa + 1] = pack_bf2(fmaxf(d[sb][h][0] + bi0, 0.f),
                                                          fmaxf(d[sb][h][1] + bi1, 0.f));
                oq[(gy + 1) * PLROW + gxb + 1] = pack_bf2(fmaxf(d[sb][h][2] + bi0, 0.f),
                                                          fmaxf(d[sb][h][3] + bi1, 0.f));
            }
        }
    } else {
        float* ob = outf + (size_t)img * (groups * 16) * NPIX + (size_t)grp * 16 * NPIX;
#pragma unroll
        for (int h = 0; h < 2; h++) {
            const int ko0 = h * 8 + 2 * tig;
            const float bi0 = bias[grp * 16 + ko0];
            const float bi1 = bias[grp * 16 + ko0 + 1];
            float* o0 = ob + (size_t)ko0 * NPIX;
            float* o1 = ob + (size_t)(ko0 + 1) * NPIX;
#pragma unroll
            for (int sb = 0; sb < 4; sb++) {
                const int gy = by16 + wy * 4 + sb;
                o0[gy * IMGD + gxa] = fmaxf(d[sb][h][0] + bi0, 0.f);
                o1[gy * IMGD + gxa] = fmaxf(d[sb][h][1] + bi1, 0.f);
                o0[gy * IMGD + gxb] = fmaxf(d[sb][h][2] + bi0, 0.f);
                o1[gy * IMGD + gxb] = fmaxf(d[sb][h][3] + bi1, 0.f);
            }
        }
    }
}

// ---------------------------------------------------------------------------
// Layer-1 fp32 conv (unpadded input) -> padded bf16 pairs (32x32 tile)
// ---------------------------------------------------------------------------
__device__ __forceinline__ void stage_l1(
    const float* __restrict__ ib, const float* __restrict__ wt,
    int g, int bx, int by, uint32_t ws_s, uint32_t patch_s, int tid)
{
    for (int idx = tid; idx < 3 * 144; idx += 256) {
        int ci = idx / 144;
        int rem = idx - ci * 144;
        int k = rem >> 4;
        int ko = rem & 15;
        const float* src = wt + ((size_t)(g * 16 + ko) * 3 + ci) * 9 + k;
        cp_async4(ws_s + idx * 4, src, 4);
    }
    const int lane32 = tid & 31;
    int py = tid >> 5;
    int ci = 0;
    const int gx = bx * 32 - 1 + lane32;
    const bool okx = ((unsigned)gx < 128u);
    for (int r = tid >> 5; r < 3 * 34; r += 8) {
        int gy = by * 32 + py - 1;
        bool oky = ((unsigned)gy < 128u);
        const float* srow = ib + (size_t)ci * NPIX + gy * IMGD;
        uint32_t drow = patch_s + (uint32_t)((ci * PCH_F + py * PROW) * 4);
        bool ok = oky && okx;
        cp_async4(drow + lane32 * 4, srow + (ok ? gx : 0), ok ? 4 : 0);
        if (lane32 < 2) {
            bool ok2 = oky && ((unsigned)(gx + 32) < 128u);
            cp_async4(drow + (32 + lane32) * 4, srow + (ok2 ? (gx + 32) : 0), ok2 ? 4 : 0);
        }
        py += 8;
        if (py >= 34) { py -= 34; ci++; }
    }
}

__global__ void __launch_bounds__(256, 2) conv3x3_l1_kernel(
    const float* __restrict__ in0, const float* __restrict__ in1,
    const float* __restrict__ wt0, const float* __restrict__ wt1,
    const float* __restrict__ bias0, const float* __restrict__ bias1,
    unsigned* __restrict__ outu, int groups)
{
    extern __shared__ __align__(16) float smem[];
    float* ws_base = smem;
    float* patch_base = smem + 3 * 144;
    uint32_t sbase = (uint32_t)__cvta_generic_to_shared(smem);
    const uint32_t ws_s = sbase;
    const uint32_t pa_s = sbase + (uint32_t)(3 * 144 * 4);

    const int img = blockIdx.z / groups;
    const int g   = blockIdx.z % groups;
    const float* wt   = (img < NIMG_CAM) ? wt0 : wt1;
    const float* bias = (img < NIMG_CAM) ? bias0 : bias1;
    const int limg = (img < NIMG_CAM) ? img : (img - NIMG_CAM);
    const float* ib = ((img < NIMG_CAM) ? in0 : in1) + (size_t)limg * 3 * NPIX;

    const int tid = threadIdx.x;
    const int tx  = tid & 15;
    const int ty  = tid >> 4;
    const int bx  = (int)blockIdx.x;
    const int by  = (int)blockIdx.y;
    const int ox0 = bx * 32 + 2 * tx;
    const int oy0 = by * 32 + 2 * ty;

    unsigned long long acc[4][8];
    const unsigned long long z2 = pack2(0.f, 0.f);
#pragma unroll
    for (int p_ = 0; p_ < 4; p_++)
#pragma unroll
        for (int i = 0; i < 8; i++) acc[p_][i] = z2;

    stage_l1(ib, wt, g, bx, by, ws_s, pa_s, tid);
    cp_commit();
    cp_wait<0>();
    __syncthreads();

#pragma unroll
    for (int ci = 0; ci < 3; ci++) {
        float p[4][4];
        const float* pb = patch_base + ci * PCH_F + (2 * ty) * PROW + 2 * tx;
#pragma unroll
        for (int r = 0; r < 4; r++) {
            float2 a = *(const float2*)(pb + r * PROW);
            float2 b = *(const float2*)(pb + r * PROW + 2);
            p[r][0] = a.x; p[r][1] = a.y; p[r][2] = b.x; p[r][3] = b.y;
        }
        const float* wk = ws_base + ci * 144;
#pragma unroll
        for (int k = 0; k < 9; k++) {
            const int ky = k / 3, kx = k - 3 * (k / 3);
            const ulonglong2* wp = (const ulonglong2*)(wk + k * 16);
            ulonglong2 w01 = wp[0];
            ulonglong2 w23 = wp[1];
            ulonglong2 w45 = wp[2];
            ulonglong2 w67 = wp[3];
#pragma unroll
            for (int p_ = 0; p_ < 4; p_++) {
                float v = p[(p_ >> 1) + ky][(p_ & 1) + kx];
                unsigned long long bb = pack2(v, v);
                fma2(acc[p_][0], w01.x, bb);
                fma2(acc[p_][1], w01.y, bb);
                fma2(acc[p_][2], w23.x, bb);
                fma2(acc[p_][3], w23.y, bb);
                fma2(acc[p_][4], w45.x, bb);
                fma2(acc[p_][5], w45.y, bb);
                fma2(acc[p_][6], w67.x, bb);
                fma2(acc[p_][7], w67.y, bb);
            }
        }
    }

    unsigned* ob = outu + (size_t)img * 16 * PLSTR;
#pragma unroll
    for (int i = 0; i < 8; i++) {
        float b0 = bias[g * 16 + 2 * i];
        float b1 = bias[g * 16 + 2 * i + 1];
        unsigned* oq = ob + (size_t)(g * 8 + i) * PLSTR;
#pragma unroll
        for (int pr = 0; pr < 2; pr++) {
            float a0l, a1l, a0r, a1r;
            unpack2(acc[pr * 2 + 0][i], a0l, a1l);
            unpack2(acc[pr * 2 + 1][i], a0r, a1r);
            int row = oy0 + pr;
            oq[(row + 1) * PLROW + ox0 + 1] = pack_bf2(fmaxf(a0l + b0, 0.f), fmaxf(a1l + b1, 0.f));
            oq[(row + 1) * PLROW + ox0 + 2] = pack_bf2(fmaxf(a0r + b0, 0.f), fmaxf(a1r + b1, 0.f));
        }
    }
}

// ---------------------------------------------------------------------------
// Spatial softmax
// ---------------------------------------------------------------------------
__global__ void __launch_bounds__(256) sspmax_kernel(
    const float* __restrict__ conv16, float* __restrict__ feat)
{
    __shared__ float red[8];
    __shared__ float r2[3][8];

    const int id = blockIdx.x;
    const int img = id >> 4;
    const int ch = id & 15;
    const int cam = (img >= NIMG_CAM) ? 1 : 0;
    const int bt = img - cam * NIMG_CAM;
    const float* p = conv16 + ((size_t)img * 16 + ch) * NPIX;
    const int tid = threadIdx.x;

    float m = -1e30f;
    for (int k = tid; k < NPIX; k += 256) m = fmaxf(m, p[k]);
    for (int o = 16; o; o >>= 1) m = fmaxf(m, __shfl_xor_sync(~0u, m, o));
    if ((tid & 31) == 0) red[tid >> 5] = m;
    __syncthreads();
    if (tid < 8) {
        float v = red[tid];
        for (int o = 4; o; o >>= 1) v = fmaxf(v, __shfl_xor_sync(0xffu, v, o));
        if (tid == 0) red[0] = v;
    }
    __syncthreads();
    m = red[0];

    float se = 0.f, sx = 0.f, sy = 0.f;
    const float step = 2.f / 127.f;
    for (int k = tid; k < NPIX; k += 256) {
        float e = expf(p[k] - m);
        float px = -1.f + (float)(k & 127) * step;
        float py = -1.f + (float)(k >> 7) * step;
        se += e; sx += e * px; sy += e * py;
    }
    for (int o = 16; o; o >>= 1) {
        se += __shfl_xor_sync(~0u, se, o);
        sx += __shfl_xor_sync(~0u, sx, o);
        sy += __shfl_xor_sync(~0u, sy, o);
    }
    if ((tid & 31) == 0) { r2[0][tid >> 5] = se; r2[1][tid >> 5] = sx; r2[2][tid >> 5] = sy; }
    __syncthreads();
    if (tid == 0) {
        float a = 0.f, bx = 0.f, by = 0.f;
        for (int w = 0; w < 8; w++) { a += r2[0][w]; bx += r2[1][w]; by += r2[2][w]; }
        feat[bt * 64 + cam * 32 + 2 * ch + 0] = bx / a;
        feat[bt * 64 + cam * 32 + 2 * ch + 1] = by / a;
    }
}

// ---------------------------------------------------------------------------
// Wavefront persistent LSTM (unchanged from R15)
// ---------------------------------------------------------------------------
__device__ __forceinline__ float sigm(float x) { return 1.f / (1.f + expf(-x)); }

__device__ __forceinline__ void grid_bar(int epoch) {
    __syncthreads();
    if (threadIdx.x == 0) {
        __threadfence();
        unsigned target = (unsigned)(epoch + 1) * NBLK;
        unsigned t = atomicAdd(&g_bar_in, 1u);
        if (t + 1u == target) {
            atomicExch(&g_bar_out, (unsigned)(epoch + 1));
        } else {
            while (atomicAdd(&g_bar_out, 0u) < (unsigned)(epoch + 1)) { __nanosleep(64); }
        }
        __threadfence();
    }
    __syncthreads();
}

__global__ void __launch_bounds__(256, 4) lstm_wave_kernel(
    const float* __restrict__ states, const float* __restrict__ feat,
    const float* __restrict__ wih0, const float* __restrict__ whh0,
    const float* __restrict__ bih0, const float* __restrict__ bhh0,
    const float* __restrict__ wih_r, const float* __restrict__ whh_r,
    const float* __restrict__ bih_r, const float* __restrict__ bhh_r,
    const float* __restrict__ out_w, const float* __restrict__ out_b,
    float* __restrict__ hbuf, float* __restrict__ c,
    float* __restrict__ h5hist, float* __restrict__ outp)
{
    __shared__ float xs[BB][576];
    __shared__ float hs[BB][HID];
    __shared__ float part[8][BB];
    __shared__ float gs[16];
    __shared__ float ored[8];

    const int j = blockIdx.x;
    const int tid = threadIdx.x;
    const int warp = tid >> 5;
    const int lane = tid & 31;
    const int HB = LL * BB * HID;

    for (int wv = 0; wv < NWAVE; wv++) {
        const float* hprev = hbuf + ((wv + 1) & 1) * HB;
        float* hcur = hbuf + (wv & 1) * HB;

        if (j < BB * AA && wv >= 6 && wv - 6 < TT) {
            const int t = wv - 6;
            const int b = j / AA;
            const int a = j % AA;
            const float* w = out_w + a * (HID + 64);
            const float* h5 = h5hist + (size_t)(t * BB + b) * HID;
            float s = 0.f;
            for (int k = tid; k < HID; k += 256) s += w[k] * h5[k];
            for (int k = tid; k < 64; k += 256) s += w[HID + k] * feat[(b * TT + t) * 64 + k];
            for (int o = 16; o; o >>= 1) s += __shfl_xor_sync(~0u, s, o);
            if (lane == 0) ored[warp] = s;
            __syncthreads();
            if (tid == 0) {
                float r = out_b[a];
                for (int ww = 0; ww < 8; ww++) r += ored[ww];
                outp[b * (TT * AA) + t * AA + a] = r;
            }
            __syncthreads();
        }

        const int lmin = (wv > TT - 1) ? (wv - (TT - 1)) : 0;
        const int lmax = (wv < LL - 1) ? wv : (LL - 1);
        for (int l = lmin; l <= lmax; l++) {
            const int t = wv - l;
            const int alen = (l == 0) ? SS : HID;
            const int inlen = alen + 64;
            const float* wih = (l == 0) ? wih0 : wih_r + (size_t)(l - 1) * 4 * HID * 576;
            const float* whh = (l == 0) ? whh0 : whh_r + (size_t)(l - 1) * 4 * HID * HID;
            const float* bih = (l == 0) ? bih0 : bih_r + (size_t)(l - 1) * 4 * HID;
            const float* bhh = (l == 0) ? bhh0 : bhh_r + (size_t)(l - 1) * 4 * HID;
            float* cl = c + (size_t)l * BB * HID;
            const float* hrec = hprev + (size_t)l * BB * HID;
            const float* hin  = hprev + (size_t)(l - 1) * BB * HID;

            for (int idx = tid; idx < BB * inlen; idx += 256) {
                int b = idx / inlen;
                int k = idx - b * inlen;
                float v;
                if (k < alen)
                    v = (l == 0) ? states[(b * TT + t) * SS + k] : hin[b * HID + k];
                else
                    v = feat[(b * TT + t) * 64 + (k - alen)];
                xs[b][k] = v;
            }
            for (int idx = tid; idx < BB * HID; idx += 256)
                hs[idx >> 9][idx & 511] = hrec[idx];
            __syncthreads();

            const int g = warp >> 1;
            const int half = warp & 1;
            const int row = g * HID + j;
            const int k0 = half * 32 + lane;

            float s0 = 0.f, s1 = 0.f, s2 = 0.f, s3 = 0.f;
            const float* wr = wih + (size_t)row * inlen;
#pragma unroll 4
            for (int k = k0; k < inlen; k += 64) {
                float w = wr[k];
                s0 += w * xs[0][k]; s1 += w * xs[1][k];
                s2 += w * xs[2][k]; s3 += w * xs[3][k];
            }
            const float* hr = whh + (size_t)row * HID;
#pragma unroll 4
            for (int k = k0; k < HID; k += 64) {
                float w = hr[k];
                s0 += w * hs[0][k]; s1 += w * hs[1][k];
                s2 += w * hs[2][k]; s3 += w * hs[3][k];
            }
            for (int o = 16; o; o >>= 1) {
                s0 += __shfl_xor_sync(~0u, s0, o);
                s1 += __shfl_xor_sync(~0u, s1, o);
                s2 += __shfl_xor_sync(~0u, s2, o);
                s3 += __shfl_xor_sync(~0u, s3, o);
            }
            if (lane == 0) {
                part[warp][0] = s0; part[warp][1] = s1;
                part[warp][2] = s2; part[warp][3] = s3;
            }
            __syncthreads();

            if (tid < 16) {
                int gg = tid >> 2, b = tid & 3;
                float s = part[gg * 2][b] + part[gg * 2 + 1][b]
                        + bih[gg * HID + j] + bhh[gg * HID + j];
                gs[b * 4 + gg] = s;
            }
            __syncthreads();

            if (tid < BB) {
                const int b = tid;
                float gi = gs[b * 4 + 0];
                float gf = gs[b * 4 + 1];
                float gg = gs[b * 4 + 2];
                float go = gs[b * 4 + 3];
                float cold = cl[b * HID + j];
                float cn = sigm(gf) * cold + sigm(gi) * tanhf(gg);
                float hn = sigm(go) * tanhf(cn);
                cl[b * HID + j] = cn;
                hcur[(size_t)l * BB * HID + b * HID + j] = hn;
                if (l == LL - 1)
                    h5hist[(size_t)(t * BB + b) * HID + j] = hn;
            }
            __syncthreads();
        }

        grid_bar(wv);
    }
}

// ---------------------------------------------------------------------------
// Launch
// ---------------------------------------------------------------------------
extern "C" void kernel_launch(void* const* d_in, const int* in_sizes, int n_in,
                              void* d_out, int out_size)
{
    (void)in_sizes; (void)n_in; (void)out_size;

    const float* img_m  = (const float*)d_in[0];
    const float* img_s  = (const float*)d_in[1];
    const float* states = (const float*)d_in[2];
    const float* wih0 = (const float*)d_in[19];
    const float* whh0 = (const float*)d_in[20];
    const float* bih0 = (const float*)d_in[21];
    const float* bhh0 = (const float*)d_in[22];
    const float* wih_r = (const float*)d_in[23];
    const float* whh_r = (const float*)d_in[24];
    const float* bih_r = (const float*)d_in[25];
    const float* bhh_r = (const float*)d_in[26];
    const float* out_w = (const float*)d_in[27];
    const float* out_b = (const float*)d_in[28];
    float* outp = (float*)d_out;

    unsigned* actA; cudaGetSymbolAddress((void**)&actA, g_actA);
    unsigned* actB; cudaGetSymbolAddress((void**)&actB, g_actB);
    float* conv16;  cudaGetSymbolAddress((void**)&conv16, g_conv16);
    unsigned* wbuf; cudaGetSymbolAddress((void**)&wbuf, g_wb);
    float* feat;    cudaGetSymbolAddress((void**)&feat, g_feat);
    float* hbuf;    cudaGetSymbolAddress((void**)&hbuf, g_h);
    float* cbuf;    cudaGetSymbolAddress((void**)&cbuf, g_c);
    float* h5buf;   cudaGetSymbolAddress((void**)&h5buf, g_h5);

    const int smemL1 = (3 * 144 + 3 * PCH_F) * 4;
    const int smemBF = 2 * (WS_U32 + PATCH_U32) * 4;       // 50688
    cudaFuncSetAttribute(conv3x3_l1_kernel, cudaFuncAttributeMaxDynamicSharedMemorySize, smemL1);
    cudaFuncSetAttribute(conv3x3_bf16_kernel<32, true>,   cudaFuncAttributeMaxDynamicSharedMemorySize, smemBF);
    cudaFuncSetAttribute(conv3x3_bf16_kernel<64, true>,   cudaFuncAttributeMaxDynamicSharedMemorySize, smemBF);
    cudaFuncSetAttribute(conv3x3_bf16_kernel<128, false>, cudaFuncAttributeMaxDynamicSharedMemorySize, smemBF);

    init_kernel<<<(NPLANES * 520 + 255) / 256, 256>>>();

    const float* mw[4] = { (const float*)d_in[3], (const float*)d_in[5],
                           (const float*)d_in[7], (const float*)d_in[9] };
    const float* mb[4] = { (const float*)d_in[4], (const float*)d_in[6],
                           (const float*)d_in[8], (const float*)d_in[10] };
    const float* sw[4] = { (const float*)d_in[11], (const float*)d_in[13],
                           (const float*)d_in[15], (const float*)d_in[17] };
    const float* sb[4] = { (const float*)d_in[12], (const float*)d_in[14],
                           (const float*)d_in[16], (const float*)d_in[18] };

    prep_all_kernel<<<(2 * WCAM + 255) / 256, 256>>>(
        mw[1], mw[2], mw[3], sw[1], sw[2], sw[3], wbuf);

    conv3x3_l1_kernel<<<dim3(4, 4, NIMG * 2), 256, smemL1>>>(
        img_m, img_s, mw[0], sw[0], mb[0], sb[0], actA, 2);
    conv3x3_bf16_kernel<32, true><<<dim3(4, 8, NIMG * 4), 256, smemBF>>>(
        actA, 16, wbuf + WOFF_L2, wbuf + WCAM + WOFF_L2, mb[1], sb[1],
        actB, nullptr, 32, 4);
    conv3x3_bf16_kernel<64, true><<<dim3(4, 8, NIMG * 8), 256, smemBF>>>(
        actB, 32, wbuf + WOFF_L3, wbuf + WCAM + WOFF_L3, mb[2], sb[2],
        actA, nullptr, 64, 8);
    conv3x3_bf16_kernel<128, false><<<dim3(4, 8, NIMG * 1), 256, smemBF>>>(
        actA, 64, wbuf + WOFF_L4, wbuf + WCAM + WOFF_L4, mb[3], sb[3],
        nullptr, conv16, 16, 1);

    sspmax_kernel<<<NIMG * 16, 256>>>(conv16, feat);

    lstm_wave_kernel<<<NBLK, 256>>>(
        states, feat,
        wih0, whh0, bih0, bhh0,
        wih_r, whh_r, bih_r, bhh_r,
        out_w, out_b,
        hbuf, cbuf, h5buf, outp);
}

// round 17
// speedup vs baseline: 3.0488x; 1.0382x over previous
#include <cuda_runtime.h>
#include <cuda_bf16.h>
#include <math.h>
#include <stdint.h>

// Problem constants
#define BB 4
#define TT 10
#define SS 6
#define AA 6
#define HID 512
#define LL 6
#define IMGD 128
#define NPIX 16384
#define NIMG_CAM 40
#define NIMG 80

// padded activation planes: 130 rows x 132 cols (u32 = bf16x2 pair)
#define PLROW 132
#define PLROWS 130
#define PLSTR (PLROW * PLROWS)

// bf16 conv patch (32x16 tile): halo 18 rows x 34 cols, padded row 36
#define PROW 36
#define PCHH (18 * PROW)             // 648 u32 per cq (648 % 32 == 8)
#define PATCH_U32 (8 * PCHH)         // 5184
#define WS_U32    1152

// fp32 L1 patch (32x32 tile)
#define PCH_F (34 * PROW)

// per-camera bf16 weight block offsets (u32 pairs)
#define WOFF_L2 0
#define WSZ_L2  9216
#define WOFF_L3 9216
#define WSZ_L3  36864
#define WOFF_L4 46080
#define WSZ_L4  9216
#define WCAM    55296

#define NBLK 512
#define NWAVE 16
#define NPLANES (NIMG * 64 + NIMG * 32)

// ---------------------------------------------------------------------------
// Scratch
// ---------------------------------------------------------------------------
__device__ __align__(16) unsigned g_actA[(size_t)NIMG * 64 * PLSTR];
__device__ __align__(16) unsigned g_actB[(size_t)NIMG * 32 * PLSTR];
__device__ __align__(16) float    g_conv16[(size_t)NIMG * 16 * NPIX];
__device__ __align__(16) unsigned g_wb[2 * WCAM];
__device__ float g_feat[NIMG_CAM * 64];
__device__ float g_h[2 * LL * BB * HID];
__device__ float g_c[LL * BB * HID];
__device__ float g_h5[TT * BB * HID];
__device__ unsigned g_bar_in;
__device__ unsigned g_bar_out;

// ---------------------------------------------------------------------------
// helpers
// ---------------------------------------------------------------------------
__device__ __forceinline__ unsigned long long pack2(float a, float b) {
    unsigned long long r;
    asm("mov.b64 %0, {%1, %2};" : "=l"(r) : "r"(__float_as_uint(a)), "r"(__float_as_uint(b)));
    return r;
}
__device__ __forceinline__ void unpack2(unsigned long long v, float& a, float& b) {
    unsigned int lo, hi;
    asm("mov.b64 {%0, %1}, %2;" : "=r"(lo), "=r"(hi) : "l"(v));
    a = __uint_as_float(lo); b = __uint_as_float(hi);
}
__device__ __forceinline__ void fma2(unsigned long long& d, unsigned long long a, unsigned long long b) {
    asm("fma.rn.f32x2 %0, %1, %2, %0;" : "+l"(d) : "l"(a), "l"(b));
}
__device__ __forceinline__ unsigned pack_bf2(float lo, float hi) {
    __nv_bfloat162 v = __floats2bfloat162_rn(lo, hi);
    return *(unsigned*)&v;
}

__device__ __forceinline__ void cp_async4(uint32_t smem_addr, const void* gptr, int sz) {
    asm volatile("cp.async.ca.shared.global [%0], [%1], 4, %2;\n"
                 :: "r"(smem_addr), "l"(gptr), "r"(sz));
}
__device__ __forceinline__ void cp_async16(uint32_t smem_addr, const void* gptr) {
    asm volatile("cp.async.cg.shared.global [%0], [%1], 16;\n"
                 :: "r"(smem_addr), "l"(gptr));
}
__device__ __forceinline__ void cp_commit() { asm volatile("cp.async.commit_group;"); }
template<int N>
__device__ __forceinline__ void cp_wait() { asm volatile("cp.async.wait_group %0;" :: "n"(N)); }

__device__ __forceinline__ void mma_bf16(float* d, const unsigned* a, unsigned b0, unsigned b1) {
    asm volatile(
        "mma.sync.aligned.m16n8k16.row.col.f32.bf16.bf16.f32 "
        "{%0,%1,%2,%3}, {%4,%5,%6,%7}, {%8,%9}, {%0,%1,%2,%3};"
        : "+f"(d[0]), "+f"(d[1]), "+f"(d[2]), "+f"(d[3])
        : "r"(a[0]), "r"(a[1]), "r"(a[2]), "r"(a[3]), "r"(b0), "r"(b1));
}

// ---------------------------------------------------------------------------
// Init: zero h (both parities) / c / h5 / barriers + plane borders
// ---------------------------------------------------------------------------
__global__ void init_kernel()
{
    int i = blockIdx.x * 256 + threadIdx.x;
    if (i < 2 * LL * BB * HID) g_h[i] = 0.f;
    if (i < LL * BB * HID) g_c[i] = 0.f;
    if (i < TT * BB * HID) g_h5[i] = 0.f;
    if (i == 0) { g_bar_in = 0u; g_bar_out = 0u; }
    if (i < NPLANES * 520) {
        int plane = i / 520;
        int e = i - plane * 520;
        unsigned* base = (plane < NIMG * 64)
                       ? g_actA + (size_t)plane * PLSTR
                       : g_actB + (size_t)(plane - NIMG * 64) * PLSTR;
        int r, c;
        if (e < 264) { r = (e < 132) ? 0 : 129; c = (e < 132) ? e : e - 132; }
        else { int e2 = e - 264; r = 1 + (e2 >> 1); c = (e2 & 1) ? 129 : 0; }
        base[r * PLROW + c] = 0u;
    }
}

// ---------------------------------------------------------------------------
// Combined weight prep -> bf16x2 tiled, B-pairs (cq, cq+4) adjacent:
// layout [k][ko][(cq&3)*2 + (cq>>2)]
// ---------------------------------------------------------------------------
__device__ __forceinline__ void prep_one(const float* wt, unsigned* dst, int CIN, int local)
{
    int p = local;
    int cq = p & 7;  p >>= 3;
    int ko_l = p & 15; p >>= 4;
    int k = p % 9;   p /= 9;
    int nch = CIN >> 4;
    int chunk = p % nch;
    int grp = p / nch;
    int ci0 = chunk * 16 + cq * 2;
    int ko = grp * 16 + ko_l;
    float lo = wt[((size_t)ko * CIN + ci0) * 9 + k];
    float hi = wt[((size_t)ko * CIN + ci0 + 1) * 9 + k];
    int perm = (cq & 3) * 2 + (cq >> 2);
    dst[(local & ~7) | perm] = pack_bf2(lo, hi);
}

__global__ void prep_all_kernel(const float* m2, const float* m3, const float* m4,
                                const float* s2, const float* s3, const float* s4,
                                unsigned* dst)
{
    int idx = blockIdx.x * 256 + threadIdx.x;
    if (idx >= 2 * WCAM) return;
    int i = idx;
    const float* wt; int CIN; int local; unsigned* out;
    if (i < WCAM) {
        out = dst;
        if (i < WOFF_L3)      { wt = m2; CIN = 32;  local = i; out += WOFF_L2; }
        else if (i < WOFF_L4) { wt = m3; CIN = 64;  local = i - WOFF_L3; out += WOFF_L3; }
        else                  { wt = m4; CIN = 128; local = i - WOFF_L4; out += WOFF_L4; }
    } else {
        i -= WCAM;
        out = dst + WCAM;
        if (i < WOFF_L3)      { wt = s2; CIN = 32;  local = i; out += WOFF_L2; }
        else if (i < WOFF_L4) { wt = s3; CIN = 64;  local = i - WOFF_L3; out += WOFF_L3; }
        else                  { wt = s4; CIN = 128; local = i - WOFF_L4; out += WOFF_L4; }
    }
    prep_one(wt, out, CIN, local);
}

// ---------------------------------------------------------------------------
// bf16 conv staging (32x16 tile): 18 halo rows x 9 16B-segments per cq
// ---------------------------------------------------------------------------
__device__ __forceinline__ void stage_chunk_bf16(
    const unsigned* __restrict__ ib, const unsigned* __restrict__ wb,
    int nchunk, int grp, int bx32, int by16, int ch,
    uint32_t ws_s, uint32_t patch_s, int tid)
{
    const unsigned* wsrc = wb + (size_t)(grp * nchunk + ch) * WS_U32;
    for (int idx = tid; idx < 288; idx += 256)
        cp_async16(ws_s + idx * 16, wsrc + idx * 4);

    const int c0q = ch * 8;
#pragma unroll
    for (int cq = 0; cq < 8; cq++) {
        const unsigned* plane = ib + (size_t)(c0q + cq) * PLSTR
                              + (size_t)by16 * PLROW + bx32;
        uint32_t pdst = patch_s + (uint32_t)(cq * PCHH * 4);
        for (int t = tid; t < 162; t += 256) {
            int r = t / 9;
            int seg = t - r * 9;
            cp_async16(pdst + (uint32_t)((r * PROW + seg * 4) * 4),
                       plane + r * PLROW + seg * 4);
        }
    }
}

// ---------------------------------------------------------------------------
// bf16 tensor-core 3x3 conv + bias + relu (dual-camera, padded I/O)
// Block: 32x16 pixel tile x 16 ko, 256 threads, 3 CTAs/SM.
// B-operand fetched as LDS.64 pairs via permuted weight layout.
// ---------------------------------------------------------------------------
template<int CIN, bool OBF>
__global__ void __launch_bounds__(256, 3) conv3x3_bf16_kernel(
    const unsigned* __restrict__ in, int inp_pairs,
    const unsigned* __restrict__ wb0, const unsigned* __restrict__ wb1,
    const float* __restrict__ bias0, const float* __restrict__ bias1,
    unsigned* __restrict__ outu, float* __restrict__ outf,
    int out_pairs, int groups)
{
    constexpr int NCHUNK = CIN / 16;

    extern __shared__ __align__(16) float smem[];
    unsigned* ws_base = (unsigned*)smem;
    unsigned* patch_base = (unsigned*)smem + 2 * WS_U32;
    uint32_t sbase = (uint32_t)__cvta_generic_to_shared(smem);
    const uint32_t ws_off[2] = { sbase, sbase + (uint32_t)(WS_U32 * 4) };
    const uint32_t pa_off[2] = { sbase + (uint32_t)(2 * WS_U32 * 4),
                                 sbase + (uint32_t)((2 * WS_U32 + PATCH_U32) * 4) };

    const int img = blockIdx.z / groups;
    const int grp = blockIdx.z % groups;
    const unsigned* wb = (img < NIMG_CAM) ? wb0 : wb1;
    const float* bias  = (img < NIMG_CAM) ? bias0 : bias1;

    const int tid = threadIdx.x;
    const int w    = tid >> 5;
    const int lane = tid & 31;
    const int lg   = lane >> 2;
    const int tig  = lane & 3;
    const int wy   = w >> 1;            // 4-row band 0..3
    const int x0   = (w & 1) * 16;
    const int bx32 = (int)blockIdx.x * 32;
    const int by16 = (int)blockIdx.y * 16;

    const unsigned* ib = in + (size_t)img * inp_pairs * PLSTR;

    float d[4][2][4];
#pragma unroll
    for (int sb = 0; sb < 4; sb++)
#pragma unroll
        for (int h = 0; h < 2; h++)
#pragma unroll
            for (int i = 0; i < 4; i++) d[sb][h][i] = 0.f;

    stage_chunk_bf16(ib, wb, NCHUNK, grp, bx32, by16, 0, ws_off[0], pa_off[0], tid);
    cp_commit();
    if (NCHUNK > 1) {
        stage_chunk_bf16(ib, wb, NCHUNK, grp, bx32, by16, 1, ws_off[1], pa_off[1], tid);
        cp_commit();
    }

    for (int ch = 0; ch < NCHUNK; ch++) {
        const int cur = ch & 1;
        if (ch + 1 < NCHUNK) cp_wait<1>(); else cp_wait<0>();
        __syncthreads();

        const unsigned* W = ws_base + cur * WS_U32;
        const unsigned* PA = patch_base + cur * PATCH_U32
                           + tig * PCHH + (wy * 4) * PROW + x0 + lg;

#pragma unroll
        for (int kx = 0; kx < 3; kx++) {
            unsigned a[6][4];
#pragma unroll
            for (int r = 0; r < 6; r++) {
                const unsigned* ap = PA + r * PROW + kx;
                a[r][0] = ap[0];
                a[r][1] = ap[8];
                a[r][2] = ap[4 * PCHH];
                a[r][3] = ap[4 * PCHH + 8];
            }
#pragma unroll
            for (int ky = 0; ky < 3; ky++) {
                const int k = ky * 3 + kx;
                const unsigned long long* wk64 =
                    (const unsigned long long*)(W + k * 128);
                unsigned long long B0 = wk64[lg * 4 + tig];        // ko=lg  : (cq tig, tig+4)
                unsigned long long B1 = wk64[(8 + lg) * 4 + tig];  // ko=lg+8
                unsigned b00 = (unsigned)B0, b01 = (unsigned)(B0 >> 32);
                unsigned b10 = (unsigned)B1, b11 = (unsigned)(B1 >> 32);
#pragma unroll
                for (int sb = 0; sb < 4; sb++) {
                    mma_bf16(d[sb][0], a[sb + ky], b00, b01);
                    mma_bf16(d[sb][1], a[sb + ky], b10, b11);
                }
            }
        }

        if (ch + 2 < NCHUNK) {
            __syncthreads();
            stage_chunk_bf16(ib, wb, NCHUNK, grp, bx32, by16, ch + 2,
                             ws_off[cur], pa_off[cur], tid);
            cp_commit();
        }
    }

    const int gxa = bx32 + x0 + lg;
    const int gxb = gxa + 8;
    if (OBF) {
        unsigned* ob = outu + (size_t)img * out_pairs * PLSTR;
#pragma unroll
        for (int h = 0; h < 2; h++) {
            const int ko0 = h * 8 + 2 * tig;
            const float bi0 = bias[grp * 16 + ko0];
            const float bi1 = bias[grp * 16 + ko0 + 1];
            const int q = grp * 8 + h * 4 + tig;
            unsigned* oq = ob + (size_t)q * PLSTR;
#pragma unroll
            for (int sb = 0; sb < 4; sb++) {
                const int gy = by16 + wy * 4 + sb;
                oq[(gy + 1) * PLROW + gxa + 1] = pack_bf2(fmaxf(d[sb][h][0] + bi0, 0.f),
                                                          fmaxf(d[sb][h][1] + bi1, 0.f));
                oq[(gy + 1) * PLROW + gxb + 1] = pack_bf2(fmaxf(d[sb][h][2] + bi0, 0.f),
                                                          fmaxf(d[sb][h][3] + bi1, 0.f));
            }
        }
    } else {
        float* ob = outf + (size_t)img * (groups * 16) * NPIX + (size_t)grp * 16 * NPIX;
#pragma unroll
        for (int h = 0; h < 2; h++) {
            const int ko0 = h * 8 + 2 * tig;
            const float bi0 = bias[grp * 16 + ko0];
            const float bi1 = bias[grp * 16 + ko0 + 1];
            float* o0 = ob + (size_t)ko0 * NPIX;
            float* o1 = ob + (size_t)(ko0 + 1) * NPIX;
#pragma unroll
            for (int sb = 0; sb < 4; sb++) {
                const int gy = by16 + wy * 4 + sb;
                o0[gy * IMGD + gxa] = fmaxf(d[sb][h][0] + bi0, 0.f);
                o1[gy * IMGD + gxa] = fmaxf(d[sb][h][1] + bi1, 0.f);
                o0[gy * IMGD + gxb] = fmaxf(d[sb][h][2] + bi0, 0.f);
                o1[gy * IMGD + gxb] = fmaxf(d[sb][h][3] + bi1, 0.f);
            }
        }
    }
}

// ---------------------------------------------------------------------------
// Layer-1 fp32 conv (unpadded input) -> padded bf16 pairs (32x32 tile)
// ---------------------------------------------------------------------------
__device__ __forceinline__ void stage_l1(
    const float* __restrict__ ib, const float* __restrict__ wt,
    int g, int bx, int by, uint32_t ws_s, uint32_t patch_s, int tid)
{
    for (int idx = tid; idx < 3 * 144; idx += 256) {
        int ci = idx / 144;
        int rem = idx - ci * 144;
        int k = rem >> 4;
        int ko = rem & 15;
        const float* src = wt + ((size_t)(g * 16 + ko) * 3 + ci) * 9 + k;
        cp_async4(ws_s + idx * 4, src, 4);
    }
    const int lane32 = tid & 31;
    int py = tid >> 5;
    int ci = 0;
    const int gx = bx * 32 - 1 + lane32;
    const bool okx = ((unsigned)gx < 128u);
    for (int r = tid >> 5; r < 3 * 34; r += 8) {
        int gy = by * 32 + py - 1;
        bool oky = ((unsigned)gy < 128u);
        const float* srow = ib + (size_t)ci * NPIX + gy * IMGD;
        uint32_t drow = patch_s + (uint32_t)((ci * PCH_F + py * PROW) * 4);
        bool ok = oky && okx;
        cp_async4(drow + lane32 * 4, srow + (ok ? gx : 0), ok ? 4 : 0);
        if (lane32 < 2) {
            bool ok2 = oky && ((unsigned)(gx + 32) < 128u);
            cp_async4(drow + (32 + lane32) * 4, srow + (ok2 ? (gx + 32) : 0), ok2 ? 4 : 0);
        }
        py += 8;
        if (py >= 34) { py -= 34; ci++; }
    }
}

__global__ void __launch_bounds__(256, 2) conv3x3_l1_kernel(
    const float* __restrict__ in0, const float* __restrict__ in1,
    const float* __restrict__ wt0, const float* __restrict__ wt1,
    const float* __restrict__ bias0, const float* __restrict__ bias1,
    unsigned* __restrict__ outu, int groups)
{
    extern __shared__ __align__(16) float smem[];
    float* ws_base = smem;
    float* patch_base = smem + 3 * 144;
    uint32_t sbase = (uint32_t)__cvta_generic_to_shared(smem);
    const uint32_t ws_s = sbase;
    const uint32_t pa_s = sbase + (uint32_t)(3 * 144 * 4);

    const int img = blockIdx.z / groups;
    const int g   = blockIdx.z % groups;
    const float* wt   = (img < NIMG_CAM) ? wt0 : wt1;
    const float* bias = (img < NIMG_CAM) ? bias0 : bias1;
    const int limg = (img < NIMG_CAM) ? img : (img - NIMG_CAM);
    const float* ib = ((img < NIMG_CAM) ? in0 : in1) + (size_t)limg * 3 * NPIX;

    const int tid = threadIdx.x;
    const int tx  = tid & 15;
    const int ty  = tid >> 4;
    const int bx  = (int)blockIdx.x;
    const int by  = (int)blockIdx.y;
    const int ox0 = bx * 32 + 2 * tx;
    const int oy0 = by * 32 + 2 * ty;

    unsigned long long acc[4][8];
    const unsigned long long z2 = pack2(0.f, 0.f);
#pragma unroll
    for (int p_ = 0; p_ < 4; p_++)
#pragma unroll
        for (int i = 0; i < 8; i++) acc[p_][i] = z2;

    stage_l1(ib, wt, g, bx, by, ws_s, pa_s, tid);
    cp_commit();
    cp_wait<0>();
    __syncthreads();

#pragma unroll
    for (int ci = 0; ci < 3; ci++) {
        float p[4][4];
        const float* pb = patch_base + ci * PCH_F + (2 * ty) * PROW + 2 * tx;
#pragma unroll
        for (int r = 0; r < 4; r++) {
            float2 a = *(const float2*)(pb + r * PROW);
            float2 b = *(const float2*)(pb + r * PROW + 2);
            p[r][0] = a.x; p[r][1] = a.y; p[r][2] = b.x; p[r][3] = b.y;
        }
        const float* wk = ws_base + ci * 144;
#pragma unroll
        for (int k = 0; k < 9; k++) {
            const int ky = k / 3, kx = k - 3 * (k / 3);
            const ulonglong2* wp = (const ulonglong2*)(wk + k * 16);
            ulonglong2 w01 = wp[0];
            ulonglong2 w23 = wp[1];
            ulonglong2 w45 = wp[2];
            ulonglong2 w67 = wp[3];
#pragma unroll
            for (int p_ = 0; p_ < 4; p_++) {
                float v = p[(p_ >> 1) + ky][(p_ & 1) + kx];
                unsigned long long bb = pack2(v, v);
                fma2(acc[p_][0], w01.x, bb);
                fma2(acc[p_][1], w01.y, bb);
                fma2(acc[p_][2], w23.x, bb);
                fma2(acc[p_][3], w23.y, bb);
                fma2(acc[p_][4], w45.x, bb);
                fma2(acc[p_][5], w45.y, bb);
                fma2(acc[p_][6], w67.x, bb);
                fma2(acc[p_][7], w67.y, bb);
            }
        }
    }

    unsigned* ob = outu + (size_t)img * 16 * PLSTR;
#pragma unroll
    for (int i = 0; i < 8; i++) {
        float b0 = bias[g * 16 + 2 * i];
        float b1 = bias[g * 16 + 2 * i + 1];
        unsigned* oq = ob + (size_t)(g * 8 + i) * PLSTR;
#pragma unroll
        for (int pr = 0; pr < 2; pr++) {
            float a0l, a1l, a0r, a1r;
            unpack2(acc[pr * 2 + 0][i], a0l, a1l);
            unpack2(acc[pr * 2 + 1][i], a0r, a1r);
            int row = oy0 + pr;
            oq[(row + 1) * PLROW + ox0 + 1] = pack_bf2(fmaxf(a0l + b0, 0.f), fmaxf(a1l + b1, 0.f));
            oq[(row + 1) * PLROW + ox0 + 2] = pack_bf2(fmaxf(a0r + b0, 0.f), fmaxf(a1r + b1, 0.f));
        }
    }
}

// ---------------------------------------------------------------------------
// Spatial softmax
// ---------------------------------------------------------------------------
__global__ void __launch_bounds__(256) sspmax_kernel(
    const float* __restrict__ conv16, float* __restrict__ feat)
{
    __shared__ float red[8];
    __shared__ float r2[3][8];

    const int id = blockIdx.x;
    const int img = id >> 4;
    const int ch = id & 15;
    const int cam = (img >= NIMG_CAM) ? 1 : 0;
    const int bt = img - cam * NIMG_CAM;
    const float* p = conv16 + ((size_t)img * 16 + ch) * NPIX;
    const int tid = threadIdx.x;

    float m = -1e30f;
    for (int k = tid; k < NPIX; k += 256) m = fmaxf(m, p[k]);
    for (int o = 16; o; o >>= 1) m = fmaxf(m, __shfl_xor_sync(~0u, m, o));
    if ((tid & 31) == 0) red[tid >> 5] = m;
    __syncthreads();
    if (tid < 8) {
        float v = red[tid];
        for (int o = 4; o; o >>= 1) v = fmaxf(v, __shfl_xor_sync(0xffu, v, o));
        if (tid == 0) red[0] = v;
    }
    __syncthreads();
    m = red[0];

    float se = 0.f, sx = 0.f, sy = 0.f;
    const float step = 2.f / 127.f;
    for (int k = tid; k < NPIX; k += 256) {
        float e = expf(p[k] - m);
        float px = -1.f + (float)(k & 127) * step;
        float py = -1.f + (float)(k >> 7) * step;
        se += e; sx += e * px; sy += e * py;
    }
    for (int o = 16; o; o >>= 1) {
        se += __shfl_xor_sync(~0u, se, o);
        sx += __shfl_xor_sync(~0u, sx, o);
        sy += __shfl_xor_sync(~0u, sy, o);
    }
    if ((tid & 31) == 0) { r2[0][tid >> 5] = se; r2[1][tid >> 5] = sx; r2[2][tid >> 5] = sy; }
    __syncthreads();
    if (tid == 0) {
        float a = 0.f, bx = 0.f, by = 0.f;
        for (int w = 0; w < 8; w++) { a += r2[0][w]; bx += r2[1][w]; by += r2[2][w]; }
        feat[bt * 64 + cam * 32 + 2 * ch + 0] = bx / a;
        feat[bt * 64 + cam * 32 + 2 * ch + 1] = by / a;
    }
}

// ---------------------------------------------------------------------------
// Wavefront persistent LSTM (unchanged)
// ---------------------------------------------------------------------------
__device__ __forceinline__ float sigm(float x) { return 1.f / (1.f + expf(-x)); }

__device__ __forceinline__ void grid_bar(int epoch) {
    __syncthreads();
    if (threadIdx.x == 0) {
        __threadfence();
        unsigned target = (unsigned)(epoch + 1) * NBLK;
        unsigned t = atomicAdd(&g_bar_in, 1u);
        if (t + 1u == target) {
            atomicExch(&g_bar_out, (unsigned)(epoch + 1));
        } else {
            while (atomicAdd(&g_bar_out, 0u) < (unsigned)(epoch + 1)) { __nanosleep(64); }
        }
        __threadfence();
    }
    __syncthreads();
}

__global__ void __launch_bounds__(256, 4) lstm_wave_kernel(
    const float* __restrict__ states, const float* __restrict__ feat,
    const float* __restrict__ wih0, const float* __restrict__ whh0,
    const float* __restrict__ bih0, const float* __restrict__ bhh0,
    const float* __restrict__ wih_r, const float* __restrict__ whh_r,
    const float* __restrict__ bih_r, const float* __restrict__ bhh_r,
    const float* __restrict__ out_w, const float* __restrict__ out_b,
    float* __restrict__ hbuf, float* __restrict__ c,
    float* __restrict__ h5hist, float* __restrict__ outp)
{
    __shared__ float xs[BB][576];
    __shared__ float hs[BB][HID];
    __shared__ float part[8][BB];
    __shared__ float gs[16];
    __shared__ float ored[8];

    const int j = blockIdx.x;
    const int tid = threadIdx.x;
    const int warp = tid >> 5;
    const int lane = tid & 31;
    const int HB = LL * BB * HID;

    for (int wv = 0; wv < NWAVE; wv++) {
        const float* hprev = hbuf + ((wv + 1) & 1) * HB;
        float* hcur = hbuf + (wv & 1) * HB;

        if (j < BB * AA && wv >= 6 && wv - 6 < TT) {
            const int t = wv - 6;
            const int b = j / AA;
            const int a = j % AA;
            const float* w = out_w + a * (HID + 64);
            const float* h5 = h5hist + (size_t)(t * BB + b) * HID;
            float s = 0.f;
            for (int k = tid; k < HID; k += 256) s += w[k] * h5[k];
            for (int k = tid; k < 64; k += 256) s += w[HID + k] * feat[(b * TT + t) * 64 + k];
            for (int o = 16; o; o >>= 1) s += __shfl_xor_sync(~0u, s, o);
            if (lane == 0) ored[warp] = s;
            __syncthreads();
            if (tid == 0) {
                float r = out_b[a];
                for (int ww = 0; ww < 8; ww++) r += ored[ww];
                outp[b * (TT * AA) + t * AA + a] = r;
            }
            __syncthreads();
        }

        const int lmin = (wv > TT - 1) ? (wv - (TT - 1)) : 0;
        const int lmax = (wv < LL - 1) ? wv : (LL - 1);
        for (int l = lmin; l <= lmax; l++) {
            const int t = wv - l;
            const int alen = (l == 0) ? SS : HID;
            const int inlen = alen + 64;
            const float* wih = (l == 0) ? wih0 : wih_r + (size_t)(l - 1) * 4 * HID * 576;
            const float* whh = (l == 0) ? whh0 : whh_r + (size_t)(l - 1) * 4 * HID * HID;
            const float* bih = (l == 0) ? bih0 : bih_r + (size_t)(l - 1) * 4 * HID;
            const float* bhh = (l == 0) ? bhh0 : bhh_r + (size_t)(l - 1) * 4 * HID;
            float* cl = c + (size_t)l * BB * HID;
            const float* hrec = hprev + (size_t)l * BB * HID;
            const float* hin  = hprev + (size_t)(l - 1) * BB * HID;

            for (int idx = tid; idx < BB * inlen; idx += 256) {
                int b = idx / inlen;
                int k = idx - b * inlen;
                float v;
                if (k < alen)
                    v = (l == 0) ? states[(b * TT + t) * SS + k] : hin[b * HID + k];
                else
                    v = feat[(b * TT + t) * 64 + (k - alen)];
                xs[b][k] = v;
            }
            for (int idx = tid; idx < BB * HID; idx += 256)
                hs[idx >> 9][idx & 511] = hrec[idx];
            __syncthreads();

            const int g = warp >> 1;
            const int half = warp & 1;
            const int row = g * HID + j;
            const int k0 = half * 32 + lane;

            float s0 = 0.f, s1 = 0.f, s2 = 0.f, s3 = 0.f;
            const float* wr = wih + (size_t)row * inlen;
#pragma unroll 4
            for (int k = k0; k < inlen; k += 64) {
                float w = wr[k];
                s0 += w * xs[0][k]; s1 += w * xs[1][k];
                s2 += w * xs[2][k]; s3 += w * xs[3][k];
            }
            const float* hr = whh + (size_t)row * HID;
#pragma unroll 4
            for (int k = k0; k < HID; k += 64) {
                float w = hr[k];
                s0 += w * hs[0][k]; s1 += w * hs[1][k];
                s2 += w * hs[2][k]; s3 += w * hs[3][k];
            }
            for (int o = 16; o; o >>= 1) {
                s0 += __shfl_xor_sync(~0u, s0, o);
                s1 += __shfl_xor_sync(~0u, s1, o);
                s2 += __shfl_xor_sync(~0u, s2, o);
                s3 += __shfl_xor_sync(~0u, s3, o);
            }
            if (lane == 0) {
                part[warp][0] = s0; part[warp][1] = s1;
                part[warp][2] = s2; part[warp][3] = s3;
            }
            __syncthreads();

            if (tid < 16) {
                int gg = tid >> 2, b = tid & 3;
                float s = part[gg * 2][b] + part[gg * 2 + 1][b]
                        + bih[gg * HID + j] + bhh[gg * HID + j];
                gs[b * 4 + gg] = s;
            }
            __syncthreads();

            if (tid < BB) {
                const int b = tid;
                float gi = gs[b * 4 + 0];
                float gf = gs[b * 4 + 1];
                float gg = gs[b * 4 + 2];
                float go = gs[b * 4 + 3];
                float cold = cl[b * HID + j];
                float cn = sigm(gf) * cold + sigm(gi) * tanhf(gg);
                float hn = sigm(go) * tanhf(cn);
                cl[b * HID + j] = cn;
                hcur[(size_t)l * BB * HID + b * HID + j] = hn;
                if (l == LL - 1)
                    h5hist[(size_t)(t * BB + b) * HID + j] = hn;
            }
            __syncthreads();
        }

        grid_bar(wv);
    }
}

// ---------------------------------------------------------------------------
// Launch
// ---------------------------------------------------------------------------
extern "C" void kernel_launch(void* const* d_in, const int* in_sizes, int n_in,
                              void* d_out, int out_size)
{
    (void)in_sizes; (void)n_in; (void)out_size;

    const float* img_m  = (const float*)d_in[0];
    const float* img_s  = (const float*)d_in[1];
    const float* states = (const float*)d_in[2];
    const float* wih0 = (const float*)d_in[19];
    const float* whh0 = (const float*)d_in[20];
    const float* bih0 = (const float*)d_in[21];
    const float* bhh0 = (const float*)d_in[22];
    const float* wih_r = (const float*)d_in[23];
    const float* whh_r = (const float*)d_in[24];
    const float* bih_r = (const float*)d_in[25];
    const float* bhh_r = (const float*)d_in[26];
    const float* out_w = (const float*)d_in[27];
    const float* out_b = (const float*)d_in[28];
    float* outp = (float*)d_out;

    unsigned* actA; cudaGetSymbolAddress((void**)&actA, g_actA);
    unsigned* actB; cudaGetSymbolAddress((void**)&actB, g_actB);
    float* conv16;  cudaGetSymbolAddress((void**)&conv16, g_conv16);
    unsigned* wbuf; cudaGetSymbolAddress((void**)&wbuf, g_wb);
    float* feat;    cudaGetSymbolAddress((void**)&feat, g_feat);
    float* hbuf;    cudaGetSymbolAddress((void**)&hbuf, g_h);
    float* cbuf;    cudaGetSymbolAddress((void**)&cbuf, g_c);
    float* h5buf;   cudaGetSymbolAddress((void**)&h5buf, g_h5);

    const int smemL1 = (3 * 144 + 3 * PCH_F) * 4;
    const int smemBF = 2 * (WS_U32 + PATCH_U32) * 4;       // 50688
    cudaFuncSetAttribute(conv3x3_l1_kernel, cudaFuncAttributeMaxDynamicSharedMemorySize, smemL1);
    cudaFuncSetAttribute(conv3x3_bf16_kernel<32, true>,   cudaFuncAttributeMaxDynamicSharedMemorySize, smemBF);
    cudaFuncSetAttribute(conv3x3_bf16_kernel<64, true>,   cudaFuncAttributeMaxDynamicSharedMemorySize, smemBF);
    cudaFuncSetAttribute(conv3x3_bf16_kernel<128, false>, cudaFuncAttributeMaxDynamicSharedMemorySize, smemBF);

    init_kernel<<<(NPLANES * 520 + 255) / 256, 256>>>();

    const float* mw[4] = { (const float*)d_in[3], (const float*)d_in[5],
                           (const float*)d_in[7], (const float*)d_in[9] };
    const float* mb[4] = { (const float*)d_in[4], (const float*)d_in[6],
                           (const float*)d_in[8], (const float*)d_in[10] };
    const float* sw[4] = { (const float*)d_in[11], (const float*)d_in[13],
                           (const float*)d_in[15], (const float*)d_in[17] };
    const float* sb[4] = { (const float*)d_in[12], (const float*)d_in[14],
                           (const float*)d_in[16], (const float*)d_in[18] };

    prep_all_kernel<<<(2 * WCAM + 255) / 256, 256>>>(
        mw[1], mw[2], mw[3], sw[1], sw[2], sw[3], wbuf);

    conv3x3_l1_kernel<<<dim3(4, 4, NIMG * 2), 256, smemL1>>>(
        img_m, img_s, mw[0], sw[0], mb[0], sb[0], actA, 2);
    conv3x3_bf16_kernel<32, true><<<dim3(4, 8, NIMG * 4), 256, smemBF>>>(
        actA, 16, wbuf + WOFF_L2, wbuf + WCAM + WOFF_L2, mb[1], sb[1],
        actB, nullptr, 32, 4);
    conv3x3_bf16_kernel<64, true><<<dim3(4, 8, NIMG * 8), 256, smemBF>>>(
        actB, 32, wbuf + WOFF_L3, wbuf + WCAM + WOFF_L3, mb[2], sb[2],
        actA, nullptr, 64, 8);
    conv3x3_bf16_kernel<128, false><<<dim3(4, 8, NIMG * 1), 256, smemBF>>>(
        actA, 64, wbuf + WOFF_L4, wbuf + WCAM + WOFF_L4, mb[3], sb[3],
        nullptr, conv16, 16, 1);

    sspmax_kernel<<<NIMG * 16, 256>>>(conv16, feat);

    lstm_wave_kernel<<<NBLK, 256>>>(
        states, feat,
        wih0, whh0, bih0, bhh0,
        wih_r, whh_r, bih_r, bhh_r,
        out_w, out_b,
        hbuf, cbuf, h5buf, outp);
}